// round 8
// baseline (speedup 1.0000x reference)
#include <cuda_runtime.h>
#include <cuda_bf16.h>
#include <math.h>
#include <stdint.h>

#define D     128
#define KP    20
#define VMAX  100000
#define EMAX  400000
#define EPS   1e-5f
#define NBMAX 1563   // (VMAX+63)/64

// ---------------- scratch (device globals; no allocations) ----------------
__device__ float g_npj  [VMAX * KP];
__device__ float g_logit[EMAX];
__device__ float g_aexp [EMAX];
__device__ float g_lmax [VMAX];
__device__ float g_asum [VMAX];
__device__ float g_hv   [VMAX * D];
__device__ float g_ctx  [VMAX * D];
__device__ float g_kf   [VMAX * D];
__device__ float g_gi   [VMAX * 3 * D];
__device__ float g_gh   [VMAX * 3 * D];
__device__ float g_gru  [VMAX * D];

// fragment-ordered bf16 hi/lo WEIGHT streams
__device__ uint32_t g_WpnS[1 * 4 * 4096];
__device__ uint32_t g_WihS[3 * 4 * 4096];
__device__ uint32_t g_WhhS[3 * 4 * 4096];
__device__ uint32_t g_WcS [1 * 8 * 4096];
__device__ uint32_t g_Wk2S[5 * 10240];

// COMPACT fragment-ordered bf16 hi/lo ACTIVATION streams
__device__ uint32_t g_Anode[(size_t)NBMAX * 4 * 2048];
__device__ uint32_t g_Actx [(size_t)NBMAX * 4 * 2048];
__device__ uint32_t g_Acat [(size_t)NBMAX * 8 * 2048];

// ---------------- helpers ----------------
__device__ __forceinline__ void split_pair(float a0, float a1,
                                           uint32_t& hi, uint32_t& lo) {
    uint32_t b0 = __float_as_uint(a0), b1 = __float_as_uint(a1);
    uint32_t hp;
    asm("prmt.b32 %0, %1, %2, 0x7632;" : "=r"(hp) : "r"(b0), "r"(b1));
    float l0 = a0 - __uint_as_float(b0 & 0xffff0000u);
    float l1 = a1 - __uint_as_float(b1 & 0xffff0000u);
    __nv_bfloat162 lp = __floats2bfloat162_rn(l0, l1);
    hi = hp; lo = *(uint32_t*)&lp;
}

#define MMA_BF16(c, A, B) asm volatile( \
    "mma.sync.aligned.m16n8k16.row.col.f32.bf16.bf16.f32 " \
    "{%0,%1,%2,%3}, {%4,%5,%6,%7}, {%8,%9}, {%0,%1,%2,%3};\n" \
    : "+f"(c[0]), "+f"(c[1]), "+f"(c[2]), "+f"(c[3]) \
    : "r"(A.x), "r"(A.y), "r"(A.z), "r"(A.w), "r"(B.x), "r"(B.y))

struct GemmSmem {
    uint32_t sa[2048];      // hi [0,1024) lo [1024,2048)
    uint32_t sb[4096];      // hi [0,2048) lo [2048,4096)
    float red[2][64][2];
};

// ---------------- device subroutines ----------------
__device__ __forceinline__ void dev_zero(float4* p, int n4, int b) {
    int i = b * 256 + threadIdx.x;
    if (i < n4) p[i] = make_float4(0.f, 0.f, 0.f, 0.f);
}

__device__ void dev_pack_w(const float* __restrict__ W, int K, int Ntot,
                           int transp, uint32_t* __restrict__ out, int b) {
    int idx = b * 256 + threadIdx.x;
    if (idx >= (K / 2) * Ntot) return;
    int kp = idx / Ntot, n = idx - kp * Ntot;
    int k0 = 2 * kp;
    float w0, w1;
    if (transp) { w0 = W[n * K + k0]; w1 = W[n * K + k0 + 1]; }
    else        { w0 = W[k0 * Ntot + n]; w1 = W[(k0 + 1) * Ntot + n]; }
    int c = kp >> 4, kpl = kp & 15;
    int ny = n >> 7, nl = n & 127;
    int bi = ((((nl >> 3) * 2 + (kpl >> 3)) * 32 + ((nl & 7) << 2) + (kpl & 3)) << 1)
             + ((kpl >> 2) & 1);
    size_t base = ((size_t)(ny * (K >> 5) + c)) << 12;
    uint32_t hi, lo;
    split_pair(w0, w1, hi, lo);
    out[base + bi] = hi;
    out[base + 2048 + bi] = lo;
}

__device__ void dev_pack_wk2(const float* __restrict__ W,
                             uint32_t* __restrict__ out, int b) {
    int idx = b * 256 + threadIdx.x;
    if (idx >= 200 * 128) return;
    int kp = idx >> 7, n = idx & 127;
    float w0 = W[(2 * kp) * 128 + n];
    float w1 = W[(2 * kp + 1) * 128 + n];
    int c = kp / 40, kpl = kp - c * 40;
    int bi = ((((n >> 3) * 5 + (kpl >> 3)) * 32 + ((n & 7) << 2) + (kpl & 3)) << 1)
             + ((kpl >> 2) & 1);
    uint32_t hi, lo;
    split_pair(w0, w1, hi, lo);
    out[c * 10240 + bi] = hi;
    out[c * 10240 + 5120 + bi] = lo;
}

__device__ void dev_pack_act(const float* __restrict__ X0, int K0,
                             const float* __restrict__ X1, int K1, int relu,
                             uint32_t* __restrict__ out, int V, int mb) {
    int t = threadIdx.x;
    int K = K0 + K1;
    int Kch = K >> 5;
    for (int it = 0; it < Kch * 4; it++) {
        int c = it >> 2;
        int idx = ((it & 3) << 8) + t;       // 0..1023 within chunk
        int mt = idx >> 8;
        int ks = (idx >> 7) & 1;
        int ln = (idx >> 2) & 31;
        int ri = idx & 3;
        int row = mb * 64 + mt * 16 + (ri & 1) * 8 + (ln >> 2);
        if (row >= V) row = V - 1;
        int k = c * 32 + ks * 16 + ((ri >> 1) << 3) + ((ln & 3) << 1);
        float2 a;
        if (k < K0) a = *(const float2*)&X0[(size_t)row * K0 + k];
        else        a = *(const float2*)&X1[(size_t)row * K1 + (k - K0)];
        if (relu) { a.x = fmaxf(a.x, 0.f); a.y = fmaxf(a.y, 0.f); }
        uint32_t hi, lo;
        split_pair(a.x, a.y, hi, lo);
        size_t base = ((size_t)(mb * Kch + c)) << 11;
        out[base + idx] = hi;
        out[base + 1024 + idx] = lo;
    }
}

__device__ void dev_npj(const float* __restrict__ x, const float* __restrict__ Wk1,
                        const float* __restrict__ bk1, const float* __restrict__ g,
                        const float* __restrict__ b, int V, int mb,
                        float (*xs)[D]) {
    int warp = threadIdx.x >> 5, lane = threadIdx.x & 31;
    int v = mb * 8 + warp;
    int vc = v < V ? v : V - 1;
    *(float4*)&xs[warp][lane << 2] = *(const float4*)&x[vc * D + (lane << 2)];
    __syncwarp();
    float y = 0.f;
    if (lane < KP) {
        #pragma unroll 8
        for (int k = 0; k < D; k++) y = fmaf(xs[warp][k], Wk1[k * KP + lane], y);
        y += bk1[lane];
    }
    float s = (lane < KP) ? y : 0.f;
    #pragma unroll
    for (int m = 16; m; m >>= 1) s += __shfl_xor_sync(0xffffffffu, s, m);
    float mu = s * (1.f / KP);
    float dv = (lane < KP) ? (y - mu) * (y - mu) : 0.f;
    #pragma unroll
    for (int m = 16; m; m >>= 1) dv += __shfl_xor_sync(0xffffffffu, dv, m);
    float rstd = rsqrtf(dv * (1.f / KP) + EPS);
    if (v < V && lane < KP)
        g_npj[v * KP + lane] = fmaxf((y - mu) * rstd * g[lane] + b[lane], 0.f);
}

__device__ void dev_logits(const float* __restrict__ x, const int* __restrict__ src,
                           const int* __restrict__ dst, const float* __restrict__ We,
                           const float* __restrict__ be, int E, int mb) {
    int e = mb * 8 + (threadIdx.x >> 5);
    if (e >= E) return;
    int lane = threadIdx.x & 31;
    int sn = src[e], dn = dst[e];
    float4 xd = *(const float4*)&x[dn * D + (lane << 2)];
    float4 w1 = *(const float4*)&We[lane << 2];
    float4 xv = *(const float4*)&x[sn * D + (lane << 2)];
    float4 w2 = *(const float4*)&We[D + (lane << 2)];
    float p = xd.x * w1.x + xd.y * w1.y + xd.z * w1.z + xd.w * w1.w
            + xv.x * w2.x + xv.y * w2.y + xv.z * w2.z + xv.w * w2.w;
    #pragma unroll
    for (int m = 16; m; m >>= 1) p += __shfl_xor_sync(0xffffffffu, p, m);
    if (lane == 0) {
        float lg = fmaxf(p + be[0], 0.f);
        g_logit[e] = lg;
        atomicMax((int*)&g_lmax[dn], __float_as_int(lg));  // valid: lg >= 0
    }
}

// ---- core mma GEMM (R7 body, parameterized block coords + shared ptr) ----
__device__ void dev_mma_gemm(GemmSmem& gs, int mb, int ny,
                             const uint32_t* __restrict__ As,
                             const uint32_t* __restrict__ Bs,
                             int Kchunks, int Ntot,
                             const float* __restrict__ bias,
                             const float* __restrict__ lng,
                             const float* __restrict__ lnb,
                             float* __restrict__ out, int V) {
    uint32_t* sa = gs.sa;
    uint32_t* sb = gs.sb;
    int t = threadIdx.x;
    int lane = t & 31, w = t >> 5;
    int wm = w & 3, wn = w >> 2;
    int row0 = mb * 64;
    int nb = ny * 128;

    float acc[8][4];
    #pragma unroll
    for (int j = 0; j < 8; j++) { acc[j][0]=acc[j][1]=acc[j][2]=acc[j][3]=0.f; }

    const uint4* ag = (const uint4*)(As + (size_t)mb * Kchunks * 2048);
    const uint4* bg = (const uint4*)(Bs + (size_t)ny * Kchunks * 4096);

    uint4 pa0, pa1, pb0, pb1, pb2, pb3;
    pa0 = ag[t]; pa1 = ag[t + 256];
    pb0 = bg[t]; pb1 = bg[t + 256]; pb2 = bg[t + 512]; pb3 = bg[t + 768];

    for (int c = 0; c < Kchunks; c++) {
        __syncthreads();
        ((uint4*)sa)[t]       = pa0; ((uint4*)sa)[t + 256] = pa1;
        ((uint4*)sb)[t]       = pb0; ((uint4*)sb)[t + 256] = pb1;
        ((uint4*)sb)[t + 512] = pb2; ((uint4*)sb)[t + 768] = pb3;
        __syncthreads();
        if (c + 1 < Kchunks) {
            const uint4* a4 = ag + (size_t)(c + 1) * 512;
            const uint4* b4 = bg + (size_t)(c + 1) * 1024;
            pa0 = a4[t]; pa1 = a4[t + 256];
            pb0 = b4[t]; pb1 = b4[t + 256]; pb2 = b4[t + 512]; pb3 = b4[t + 768];
        }
        #pragma unroll
        for (int ks = 0; ks < 2; ks++) {
            uint4 ah = ((const uint4*)sa)[(wm * 2 + ks) * 32 + lane];
            uint4 al = *(const uint4*)&sa[1024 + (((wm * 2 + ks) * 32 + lane) << 2)];
            #pragma unroll
            for (int j = 0; j < 8; j++) {
                int nt = wn * 8 + j;
                uint2 bh = ((const uint2*)sb)[(nt * 2 + ks) * 32 + lane];
                uint2 bl = *(const uint2*)&sb[2048 + (((nt * 2 + ks) * 32 + lane) << 1)];
                MMA_BF16(acc[j], ah, bh);
                MMA_BF16(acc[j], ah, bl);
                MMA_BF16(acc[j], al, bh);
            }
        }
    }

    int rl = row0 + wm * 16 + (lane >> 2);
    int rh = rl + 8;
    #pragma unroll
    for (int j = 0; j < 8; j++) {
        int gc = nb + wn * 64 + j * 8 + ((lane & 3) << 1);
        float b0 = bias[gc], b1 = bias[gc + 1];
        acc[j][0] += b0; acc[j][1] += b1; acc[j][2] += b0; acc[j][3] += b1;
    }
    if (lng == nullptr) {
        #pragma unroll
        for (int j = 0; j < 8; j++) {
            int gc = nb + wn * 64 + j * 8 + ((lane & 3) << 1);
            if (rl < V) *(float2*)&out[(size_t)rl * Ntot + gc] = make_float2(acc[j][0], acc[j][1]);
            if (rh < V) *(float2*)&out[(size_t)rh * Ntot + gc] = make_float2(acc[j][2], acc[j][3]);
        }
    } else {
        float s_lo=0.f, q_lo=0.f, s_hi=0.f, q_hi=0.f;
        #pragma unroll
        for (int j = 0; j < 8; j++) {
            s_lo += acc[j][0] + acc[j][1];
            q_lo += acc[j][0]*acc[j][0] + acc[j][1]*acc[j][1];
            s_hi += acc[j][2] + acc[j][3];
            q_hi += acc[j][2]*acc[j][2] + acc[j][3]*acc[j][3];
        }
        #pragma unroll
        for (int m = 1; m <= 2; m <<= 1) {
            s_lo += __shfl_xor_sync(0xffffffffu, s_lo, m);
            q_lo += __shfl_xor_sync(0xffffffffu, q_lo, m);
            s_hi += __shfl_xor_sync(0xffffffffu, s_hi, m);
            q_hi += __shfl_xor_sync(0xffffffffu, q_hi, m);
        }
        int rloc = wm * 16 + (lane >> 2);
        if ((lane & 3) == 0) {
            gs.red[wn][rloc][0] = s_lo;   gs.red[wn][rloc][1] = q_lo;
            gs.red[wn][rloc+8][0] = s_hi; gs.red[wn][rloc+8][1] = q_hi;
        }
        __syncthreads();
        float ts_lo = s_lo + gs.red[wn ^ 1][rloc][0];
        float tq_lo = q_lo + gs.red[wn ^ 1][rloc][1];
        float ts_hi = s_hi + gs.red[wn ^ 1][rloc + 8][0];
        float tq_hi = q_hi + gs.red[wn ^ 1][rloc + 8][1];
        float mu_lo = ts_lo * (1.f/128.f);
        float mu_hi = ts_hi * (1.f/128.f);
        float rs_lo = rsqrtf(tq_lo * (1.f/128.f) - mu_lo*mu_lo + EPS);
        float rs_hi = rsqrtf(tq_hi * (1.f/128.f) - mu_hi*mu_hi + EPS);
        #pragma unroll
        for (int j = 0; j < 8; j++) {
            int gc = wn * 64 + j * 8 + ((lane & 3) << 1);
            float g0 = lng[gc], g1 = lng[gc+1];
            float bb0 = lnb[gc], bb1 = lnb[gc+1];
            if (rl < V) {
                float o0 = fmaxf((acc[j][0]-mu_lo)*rs_lo*g0 + bb0, 0.f);
                float o1 = fmaxf((acc[j][1]-mu_lo)*rs_lo*g1 + bb1, 0.f);
                *(float2*)&out[(size_t)rl * 128 + gc] = make_float2(o0, o1);
            }
            if (rh < V) {
                float o2 = fmaxf((acc[j][2]-mu_hi)*rs_hi*g0 + bb0, 0.f);
                float o3 = fmaxf((acc[j][3]-mu_hi)*rs_hi*g1 + bb1, 0.f);
                *(float2*)&out[(size_t)rh * 128 + gc] = make_float2(o2, o3);
            }
        }
    }
}

// =================== K1: all independent prologue work ===================
__global__ __launch_bounds__(256)
void k1_kernel(const float* node, const int* src, const int* dst,
               const float* We, const float* be,
               const float* W_pn, const float* W_ih, const float* W_hh,
               const float* Wc, const float* Wk2,
               const float* Wk1, const float* bk1,
               const float* lnk1_g, const float* lnk1_b,
               uint32_t* WpnS, uint32_t* WihS, uint32_t* WhhS,
               uint32_t* WcS, uint32_t* Wk2S, uint32_t* An,
               float* ctx, float* kf, float* asum, float* lmax,
               int V, int E, int NBv, int nlog, int nnpj, int nzc, int nzs) {
    __shared__ float xs[8][D];
    int b = blockIdx.x;
    if (b < nlog) { dev_logits(node, src, dst, We, be, E, b); return; }
    b -= nlog;
    if (b < NBv) { dev_pack_act(node, 128, nullptr, 0, 0, An, V, b); return; }
    b -= NBv;
    if (b < nnpj) { dev_npj(node, Wk1, bk1, lnk1_g, lnk1_b, V, b, xs); return; }
    b -= nnpj;
    if (b < 32)  { dev_pack_w(W_pn, 128, 128, 0, WpnS, b); return; }
    b -= 32;
    if (b < 96)  { dev_pack_w(W_ih, 128, 384, 1, WihS, b); return; }
    b -= 96;
    if (b < 96)  { dev_pack_w(W_hh, 128, 384, 1, WhhS, b); return; }
    b -= 96;
    if (b < 64)  { dev_pack_w(Wc, 256, 128, 0, WcS, b); return; }
    b -= 64;
    if (b < 100) { dev_pack_wk2(Wk2, Wk2S, b); return; }
    b -= 100;
    if (b < nzc) { dev_zero((float4*)ctx, V * 32, b); return; }
    b -= nzc;
    if (b < nzc) { dev_zero((float4*)kf, V * 32, b); return; }
    b -= nzc;
    if (b < nzs) { dev_zero((float4*)asum, V / 4, b); return; }
    b -= nzs;
    dev_zero((float4*)lmax, V / 4, b);
}

// =================== K2: hv + gh GEMMs + expsum ===================
__global__ __launch_bounds__(256)
void k2_kernel(const uint32_t* An, const uint32_t* WpnS, const float* b_pn,
               float* hv, const uint32_t* WhhS, const float* b_hh, float* gh,
               const int* dst, int V, int E, int NBv) {
    __shared__ GemmSmem gs;
    int b = blockIdx.x;
    if (b < NBv) {
        dev_mma_gemm(gs, b, 0, An, WpnS, 4, 128, b_pn, nullptr, nullptr, hv, V);
        return;
    }
    b -= NBv;
    if (b < 3 * NBv) {
        dev_mma_gemm(gs, b % NBv, b / NBv, An, WhhS, 4, 384, b_hh,
                     nullptr, nullptr, gh, V);
        return;
    }
    b -= 3 * NBv;
    int e = b * 256 + threadIdx.x;
    if (e < E) {
        int dn = dst[e];
        float a = expf(g_logit[e] - g_lmax[dn]);
        g_aexp[e] = a;
        atomicAdd(&g_asum[dn], a);
    }
}

// =================== K3: kron GEMM + context scatter ===================
__global__ __launch_bounds__(256, 2)
void k3_kernel(const int* __restrict__ src, const int* __restrict__ dst,
               const uint32_t* __restrict__ Wk2S, const float* __restrict__ bk2,
               const float* __restrict__ lng, const float* __restrict__ lnb,
               int E, int NKRON) {
    extern __shared__ uint32_t dsm[];
    __shared__ int ssrc[128], sdst[128];
    __shared__ float red[2][128][2];

    int t = threadIdx.x;
    if (blockIdx.x >= NKRON) {
        // ---- context: 64 edges per block ----
        int mb = blockIdx.x - NKRON;
        int w = t >> 5, lane = t & 31;
        #pragma unroll
        for (int i = 0; i < 8; i++) {
            int e = mb * 64 + w * 8 + i;
            if (e < E) {
                int sn = src[e], dn = dst[e];
                float coef = g_aexp[e] / g_asum[dn];
                float4 h = *(const float4*)&g_hv[(size_t)sn * D + (lane << 2)];
                atomicAdd((float4*)&g_ctx[(size_t)dn * D + (lane << 2)],
                          make_float4(h.x*coef, h.y*coef, h.z*coef, h.w*coef));
            }
        }
        return;
    }
    // ---- kron (R7 body) ----
    uint32_t* sa = dsm;               // 10240: hi [0,5120) lo [5120,10240)
    uint32_t* sb = dsm + 10240;       // 10240
    float* Ss = (float*)(dsm + 20480);   // 128*20
    float* Ds = Ss + 2560;               // 128*20

    int lane = t & 31, w = t >> 5;
    int wm = w & 3, wn = w >> 2;
    int e0 = blockIdx.x * 128;

    if (t < 128) {
        int ee = e0 + t; if (ee >= E) ee = E - 1;
        ssrc[t] = src[ee];
        sdst[t] = dst[ee];
    }
    __syncthreads();
    for (int idx = t; idx < 640; idx += 256) {
        int e = idx / 5, q = idx - e * 5;
        ((float4*)Ss)[idx] = *(const float4*)&g_npj[ssrc[e] * KP + q * 4];
        ((float4*)Ds)[idx] = *(const float4*)&g_npj[sdst[e] * KP + q * 4];
    }

    float acc[2][8][4];
    #pragma unroll
    for (int r = 0; r < 2; r++)
        #pragma unroll
        for (int j = 0; j < 8; j++) { acc[r][j][0]=acc[r][j][1]=acc[r][j][2]=acc[r][j][3]=0.f; }

    int be = t >> 1, ih = t & 1;
    int amt = be >> 4;
    int ribase = (be >> 3) & 1;
    int alnb = (be & 7) << 2;

    for (int c = 0; c < 5; c++) {
        __syncthreads();
        {
            const float* ds = &Ds[be * 20];
            #pragma unroll
            for (int iv = 0; iv < 2; iv++) {
                int il = ih * 2 + iv;
                float sv = Ss[be * 20 + c * 4 + il];
                #pragma unroll
                for (int q = 0; q < 10; q++) {
                    float2 d = *(const float2*)&ds[2 * q];
                    float p0 = sv * d.x, p1 = sv * d.y;
                    int kp = il * 10 + q;
                    int ai = (((amt * 5 + (kp >> 3)) * 32 + alnb + (kp & 3)) << 2)
                             + ribase + (((kp >> 2) & 1) << 1);
                    uint32_t hi, lo;
                    split_pair(p0, p1, hi, lo);
                    sa[ai] = hi;
                    sa[5120 + ai] = lo;
                }
            }
        }
        {
            const uint4* bsrc = (const uint4*)(Wk2S + c * 10240);
            #pragma unroll
            for (int i = 0; i < 10; i++)
                ((uint4*)sb)[t + (i << 8)] = bsrc[t + (i << 8)];
        }
        __syncthreads();
        #pragma unroll
        for (int ks = 0; ks < 5; ks++) {
            uint4 ah0 = ((const uint4*)sa)[((wm * 2 + 0) * 5 + ks) * 32 + lane];
            uint4 al0 = ((const uint4*)sa)[1280 + ((wm * 2 + 0) * 5 + ks) * 32 + lane];
            uint4 ah1 = ((const uint4*)sa)[((wm * 2 + 1) * 5 + ks) * 32 + lane];
            uint4 al1 = ((const uint4*)sa)[1280 + ((wm * 2 + 1) * 5 + ks) * 32 + lane];
            #pragma unroll
            for (int j = 0; j < 8; j++) {
                int nt = wn * 8 + j;
                uint2 bh = ((const uint2*)sb)[(nt * 5 + ks) * 32 + lane];
                uint2 bl = ((const uint2*)sb)[2560 + (nt * 5 + ks) * 32 + lane];
                MMA_BF16(acc[0][j], ah0, bh);
                MMA_BF16(acc[0][j], ah0, bl);
                MMA_BF16(acc[0][j], al0, bh);
                MMA_BF16(acc[1][j], ah1, bh);
                MMA_BF16(acc[1][j], ah1, bl);
                MMA_BF16(acc[1][j], al1, bh);
            }
        }
    }

    #pragma unroll
    for (int r = 0; r < 2; r++)
        #pragma unroll
        for (int j = 0; j < 8; j++) {
            int gc = wn * 64 + j * 8 + ((lane & 3) << 1);
            float b0 = bk2[gc], b1 = bk2[gc + 1];
            acc[r][j][0] += b0; acc[r][j][1] += b1;
            acc[r][j][2] += b0; acc[r][j][3] += b1;
        }
    float sum[2][2], sq[2][2];
    #pragma unroll
    for (int r = 0; r < 2; r++) {
        float s_lo=0.f, q_lo=0.f, s_hi=0.f, q_hi=0.f;
        #pragma unroll
        for (int j = 0; j < 8; j++) {
            s_lo += acc[r][j][0] + acc[r][j][1];
            q_lo += acc[r][j][0]*acc[r][j][0] + acc[r][j][1]*acc[r][j][1];
            s_hi += acc[r][j][2] + acc[r][j][3];
            q_hi += acc[r][j][2]*acc[r][j][2] + acc[r][j][3]*acc[r][j][3];
        }
        #pragma unroll
        for (int m = 1; m <= 2; m <<= 1) {
            s_lo += __shfl_xor_sync(0xffffffffu, s_lo, m);
            q_lo += __shfl_xor_sync(0xffffffffu, q_lo, m);
            s_hi += __shfl_xor_sync(0xffffffffu, s_hi, m);
            q_hi += __shfl_xor_sync(0xffffffffu, q_hi, m);
        }
        sum[r][0] = s_lo; sq[r][0] = q_lo;
        sum[r][1] = s_hi; sq[r][1] = q_hi;
        if ((lane & 3) == 0) {
            int rloc = wm * 32 + r * 16 + (lane >> 2);
            red[wn][rloc][0] = s_lo;     red[wn][rloc][1] = q_lo;
            red[wn][rloc + 8][0] = s_hi; red[wn][rloc + 8][1] = q_hi;
        }
    }
    __syncthreads();
    #pragma unroll
    for (int r = 0; r < 2; r++) {
        #pragma unroll
        for (int h = 0; h < 2; h++) {
            int rloc = wm * 32 + r * 16 + h * 8 + (lane >> 2);
            float ts = sum[r][h] + red[wn ^ 1][rloc][0];
            float tq = sq[r][h] + red[wn ^ 1][rloc][1];
            float mu = ts * (1.f / 128.f);
            float rs = rsqrtf(tq * (1.f / 128.f) - mu * mu + EPS);
            int ge = e0 + rloc;
            if (ge < E) {
                int dn = sdst[rloc];
                #pragma unroll
                for (int j = 0; j < 8; j++) {
                    int gc = wn * 64 + j * 8 + ((lane & 3) << 1);
                    float g0 = lng[gc], g1 = lng[gc + 1];
                    float bb0 = lnb[gc], bb1 = lnb[gc + 1];
                    float* p = &g_kf[(size_t)dn * 128 + gc];
                    atomicAdd(p,     fmaxf((acc[r][j][2*h  ]-mu)*rs*g0 + bb0, 0.f));
                    atomicAdd(p + 1, fmaxf((acc[r][j][2*h+1]-mu)*rs*g1 + bb1, 0.f));
                }
            }
        }
    }
}

// =================== generic wrappers ===================
__global__ __launch_bounds__(256)
void mma_k(const uint32_t* As, const uint32_t* Bs, int Kchunks, int Ntot,
           const float* bias, const float* lng, const float* lnb,
           float* out, int V, int NBv) {
    __shared__ GemmSmem gs;
    dev_mma_gemm(gs, blockIdx.x % NBv, blockIdx.x / NBv,
                 As, Bs, Kchunks, Ntot, bias, lng, lnb, out, V);
}

__global__ __launch_bounds__(256)
void pack_k(const float* X0, int K0, const float* X1, int K1, int relu,
            uint32_t* out, int V) {
    dev_pack_act(X0, K0, X1, K1, relu, out, V, blockIdx.x);
}

__global__ __launch_bounds__(256)
void gates_k(const float* __restrict__ x, const float* __restrict__ lng,
             const float* __restrict__ lnb, int V) {
    int v = blockIdx.x * 8 + (threadIdx.x >> 5);
    if (v >= V) return;
    int lane = threadIdx.x & 31;
    const float* gi = &g_gi[(size_t)v * 384];
    const float* gh = &g_gh[(size_t)v * 384];
    float4 gir = *(const float4*)&gi[lane << 2];
    float4 giz = *(const float4*)&gi[128 + (lane << 2)];
    float4 gin = *(const float4*)&gi[256 + (lane << 2)];
    float4 ghr = *(const float4*)&gh[lane << 2];
    float4 ghz = *(const float4*)&gh[128 + (lane << 2)];
    float4 ghn = *(const float4*)&gh[256 + (lane << 2)];
    float4 xv  = *(const float4*)&x[(size_t)v * D + (lane << 2)];
    float h[4];
    #pragma unroll
    for (int i = 0; i < 4; i++) {
        float r = 1.f / (1.f + expf(-((&gir.x)[i] + (&ghr.x)[i])));
        float z = 1.f / (1.f + expf(-((&giz.x)[i] + (&ghz.x)[i])));
        float n = tanhf((&gin.x)[i] + r * (&ghn.x)[i]);
        h[i] = fmaxf((1.f - z) * n + z * (&xv.x)[i], 0.f);
    }
    float s = h[0] + h[1] + h[2] + h[3];
    #pragma unroll
    for (int m = 16; m; m >>= 1) s += __shfl_xor_sync(0xffffffffu, s, m);
    float mu = s * (1.f / 128.f), q = 0.f;
    #pragma unroll
    for (int i = 0; i < 4; i++) { float d0 = h[i] - mu; q = fmaf(d0, d0, q); }
    #pragma unroll
    for (int m = 16; m; m >>= 1) q += __shfl_xor_sync(0xffffffffu, q, m);
    float rstd = rsqrtf(q * (1.f / 128.f) + EPS);
    float4 gv = *(const float4*)&lng[lane << 2];
    float4 b2 = *(const float4*)&lnb[lane << 2];
    float4 o;
    o.x = (h[0]-mu)*rstd*gv.x + b2.x;
    o.y = (h[1]-mu)*rstd*gv.y + b2.y;
    o.z = (h[2]-mu)*rstd*gv.z + b2.z;
    o.w = (h[3]-mu)*rstd*gv.w + b2.w;
    *(float4*)&g_gru[(size_t)v * D + (lane << 2)] = o;
}

// ---------------- host ----------------
extern "C" void kernel_launch(void* const* d_in, const int* in_sizes, int n_in,
                              void* d_out, int out_size) {
    const float* node   = (const float*)d_in[0];
    const int*   src    = (const int*)  d_in[1];
    const int*   dst    = (const int*)  d_in[2];
    const float* W_edge = (const float*)d_in[3];
    const float* b_edge = (const float*)d_in[4];
    const float* W_pn   = (const float*)d_in[5];
    const float* b_pn   = (const float*)d_in[6];
    const float* W_ih   = (const float*)d_in[7];
    const float* b_ih   = (const float*)d_in[8];
    const float* W_hh   = (const float*)d_in[9];
    const float* b_hh   = (const float*)d_in[10];
    const float* ln_g   = (const float*)d_in[11];
    const float* ln_b   = (const float*)d_in[12];
    const float* Wk1    = (const float*)d_in[13];
    const float* bk1    = (const float*)d_in[14];
    const float* lnk1_g = (const float*)d_in[15];
    const float* lnk1_b = (const float*)d_in[16];
    const float* Wk2    = (const float*)d_in[17];
    const float* bk2    = (const float*)d_in[18];
    const float* lnk2_g = (const float*)d_in[19];
    const float* lnk2_b = (const float*)d_in[20];
    const float* Wc     = (const float*)d_in[21];
    const float* bc     = (const float*)d_in[22];
    const float* lnc_g  = (const float*)d_in[23];
    const float* lnc_b  = (const float*)d_in[24];
    int V = in_sizes[0] / D;
    int E = in_sizes[1];
    float* out = (float*)d_out;

    float *p_asum, *p_lmax, *p_hv, *p_ctx, *p_kf, *p_gi, *p_gh, *p_gru;
    uint32_t *p_WpnS, *p_WihS, *p_WhhS, *p_WcS, *p_Wk2S;
    uint32_t *p_An, *p_Ac, *p_Aq;
    cudaGetSymbolAddress((void**)&p_asum, g_asum);
    cudaGetSymbolAddress((void**)&p_lmax, g_lmax);
    cudaGetSymbolAddress((void**)&p_hv,   g_hv);
    cudaGetSymbolAddress((void**)&p_ctx,  g_ctx);
    cudaGetSymbolAddress((void**)&p_kf,   g_kf);
    cudaGetSymbolAddress((void**)&p_gi,   g_gi);
    cudaGetSymbolAddress((void**)&p_gh,   g_gh);
    cudaGetSymbolAddress((void**)&p_gru,  g_gru);
    cudaGetSymbolAddress((void**)&p_WpnS, g_WpnS);
    cudaGetSymbolAddress((void**)&p_WihS, g_WihS);
    cudaGetSymbolAddress((void**)&p_WhhS, g_WhhS);
    cudaGetSymbolAddress((void**)&p_WcS,  g_WcS);
    cudaGetSymbolAddress((void**)&p_Wk2S, g_Wk2S);
    cudaGetSymbolAddress((void**)&p_An,   g_Anode);
    cudaGetSymbolAddress((void**)&p_Ac,   g_Actx);
    cudaGetSymbolAddress((void**)&p_Aq,   g_Acat);

    static bool attr_set = false;
    if (!attr_set) {
        cudaFuncSetAttribute(k3_kernel, cudaFuncAttributeMaxDynamicSharedMemorySize, 103000);
        attr_set = true;
    }

    int NBv  = (V + 63) / 64;
    int nlog = (E + 7) / 8;
    int nnpj = (V + 7) / 8;
    int nzc  = (V * 32 + 255) / 256;
    int nzs  = (V / 4 + 255) / 256;
    int nexp = (E + 255) / 256;
    int NKRON = (E + 127) / 128;
    int NCTX  = (E + 63) / 64;

    // K1: logits + pack(node) + npj + weight packs + zeros
    int g1 = nlog + NBv + nnpj + 32 + 96 + 96 + 64 + 100 + 2 * nzc + 2 * nzs;
    k1_kernel<<<g1, 256>>>(node, src, dst, W_edge, b_edge,
                           W_pn, W_ih, W_hh, Wc, Wk2,
                           Wk1, bk1, lnk1_g, lnk1_b,
                           p_WpnS, p_WihS, p_WhhS, p_WcS, p_Wk2S, p_An,
                           p_ctx, p_kf, p_asum, p_lmax,
                           V, E, NBv, nlog, nnpj, nzc, nzs);

    // K2: hv + gh + expsum
    k2_kernel<<<NBv + 3 * NBv + nexp, 256>>>(p_An, p_WpnS, b_pn, p_hv,
                                             p_WhhS, b_hh, p_gh, dst, V, E, NBv);

    // K3: kron + context
    k3_kernel<<<NKRON + NCTX, 256, 102400>>>(src, dst, p_Wk2S, bk2,
                                             lnk2_g, lnk2_b, E, NKRON);

    // K4: pack relu(ctx)
    pack_k<<<NBv, 256>>>(p_ctx, 128, nullptr, 0, 1, p_Ac, V);

    // K5: gi
    mma_k<<<3 * NBv, 256>>>(p_Ac, p_WihS, 4, 384, b_ih, nullptr, nullptr,
                            p_gi, V, NBv);

    // K6: gates
    gates_k<<<(V + 7) / 8, 256>>>(node, ln_g, ln_b, V);

    // K7: pack cat(gru, kf)
    pack_k<<<NBv, 256>>>(p_gru, 128, p_kf, 128, 0, p_Aq, V);

    // K8: final GEMM + LN + relu
    mma_k<<<NBv, 256>>>(p_Aq, p_WcS, 8, 128, bc, lnc_g, lnc_b, out, V, NBv);
}

// round 9
// speedup vs baseline: 1.2158x; 1.2158x over previous
#include <cuda_runtime.h>
#include <cuda_fp16.h>
#include <math.h>
#include <stdint.h>

#define D     128
#define KP    20
#define VMAX  100000
#define EMAX  400000
#define EPS   1e-5f
#define NBMAX 1563   // (VMAX+63)/64

// ---------------- scratch (device globals; no allocations) ----------------
__device__ float g_npj  [VMAX * KP];
__device__ float g_logit[EMAX];
__device__ float g_aexp [EMAX];
__device__ float g_lmax [VMAX];
__device__ float g_asum [VMAX];
__device__ float g_hv   [VMAX * D];
__device__ float g_ctx  [VMAX * D];
__device__ float g_kf   [VMAX * D];
__device__ float g_gi   [VMAX * 3 * D];
__device__ float g_gh   [VMAX * 3 * D];
__device__ float g_gru  [VMAX * D];

// fragment-ordered fp16 WEIGHT streams (hi only; per (ny,chunk): 2048 u32)
__device__ uint32_t g_WpnS[1 * 4 * 2048];
__device__ uint32_t g_WihS[3 * 4 * 2048];
__device__ uint32_t g_WhhS[3 * 4 * 2048];
__device__ uint32_t g_WcS [1 * 8 * 2048];
__device__ uint32_t g_Wk2S[5 * 5120];

// COMPACT fragment-ordered fp16 hi/lo ACTIVATION streams
// per (mblock64, chunk32): 2048 u32 = hi[0,1024) lo[1024,2048)
__device__ uint32_t g_Anode[(size_t)NBMAX * 4 * 2048];
__device__ uint32_t g_Actx [(size_t)NBMAX * 4 * 2048];
__device__ uint32_t g_Acat [(size_t)NBMAX * 8 * 2048];

// ---------------- fp16 RN hi/lo split ----------------
__device__ __forceinline__ void split_pair(float a0, float a1,
                                           uint32_t& hi, uint32_t& lo) {
    __half h0 = __float2half_rn(a0), h1 = __float2half_rn(a1);
    float l0 = a0 - __half2float(h0);
    float l1 = a1 - __half2float(h1);
    __half2 hp = __halves2half2(h0, h1);
    __half2 lp = __floats2half2_rn(l0, l1);
    hi = *(uint32_t*)&hp;
    lo = *(uint32_t*)&lp;
}
__device__ __forceinline__ uint32_t pack_hi16(float a0, float a1) {
    __half2 hp = __floats2half2_rn(a0, a1);
    return *(uint32_t*)&hp;
}

#define MMA_F16(c, A, B) asm volatile( \
    "mma.sync.aligned.m16n8k16.row.col.f32.f16.f16.f32 " \
    "{%0,%1,%2,%3}, {%4,%5,%6,%7}, {%8,%9}, {%0,%1,%2,%3};\n" \
    : "+f"(c[0]), "+f"(c[1]), "+f"(c[2]), "+f"(c[3]) \
    : "r"(A.x), "r"(A.y), "r"(A.z), "r"(A.w), "r"(B.x), "r"(B.y))

// ---------------- utility kernels ----------------
__global__ void zero_kernel(float4* p, int n4) {
    int i = blockIdx.x * blockDim.x + threadIdx.x;
    if (i < n4) p[i] = make_float4(0.f, 0.f, 0.f, 0.f);
}

// pack weights (fp16 hi only): per (ny, chunk): 2048 u32
__global__ void pack_w_frag(const float* __restrict__ W, int K, int Ntot,
                            int transp, uint32_t* __restrict__ out) {
    int idx = blockIdx.x * blockDim.x + threadIdx.x;
    int total = (K / 2) * Ntot;
    if (idx >= total) return;
    int kp = idx / Ntot, n = idx - kp * Ntot;
    int k0 = 2 * kp;
    float w0, w1;
    if (transp) { w0 = W[n * K + k0]; w1 = W[n * K + k0 + 1]; }
    else        { w0 = W[k0 * Ntot + n]; w1 = W[(k0 + 1) * Ntot + n]; }
    int c = kp >> 4, kpl = kp & 15;
    int ny = n >> 7, nl = n & 127;
    int bi = ((((nl >> 3) * 2 + (kpl >> 3)) * 32 + ((nl & 7) << 2) + (kpl & 3)) << 1)
             + ((kpl >> 2) & 1);
    size_t base = ((size_t)(ny * (K >> 5) + c)) << 11;
    out[base + bi] = pack_hi16(w0, w1);
}

// Wk2 [400][128] -> kron stream (fp16 hi only): per chunk(5): 5120 u32
__global__ void pack_wk2(const float* __restrict__ W, uint32_t* __restrict__ out) {
    int idx = blockIdx.x * blockDim.x + threadIdx.x;
    if (idx >= 200 * 128) return;
    int kp = idx >> 7, n = idx & 127;
    float w0 = W[(2 * kp) * 128 + n];
    float w1 = W[(2 * kp + 1) * 128 + n];
    int c = kp / 40, kpl = kp - c * 40;
    int bi = ((((n >> 3) * 5 + (kpl >> 3)) * 32 + ((n & 7) << 2) + (kpl & 3)) << 1)
             + ((kpl >> 2) & 1);
    out[c * 5120 + bi] = pack_hi16(w0, w1);
}

// COMPACT activation pack (fp16 hi/lo)
__global__ void pack_act(const float* __restrict__ X0, int K0,
                         const float* __restrict__ X1, int K1, int relu,
                         uint32_t* __restrict__ out, int V) {
    int t = threadIdx.x;
    int mb = blockIdx.x;
    int K = K0 + K1;
    int Kch = K >> 5;
    for (int it = 0; it < Kch * 4; it++) {
        int c = it >> 2;
        int idx = ((it & 3) << 8) + t;       // 0..1023 within chunk
        int mt = idx >> 8;
        int ks = (idx >> 7) & 1;
        int ln = (idx >> 2) & 31;
        int ri = idx & 3;
        int row = mb * 64 + mt * 16 + (ri & 1) * 8 + (ln >> 2);
        if (row >= V) row = V - 1;
        int k = c * 32 + ks * 16 + ((ri >> 1) << 3) + ((ln & 3) << 1);
        float2 a;
        if (k < K0) a = *(const float2*)&X0[(size_t)row * K0 + k];
        else        a = *(const float2*)&X1[(size_t)row * K1 + (k - K0)];
        if (relu) { a.x = fmaxf(a.x, 0.f); a.y = fmaxf(a.y, 0.f); }
        uint32_t hi, lo;
        split_pair(a.x, a.y, hi, lo);
        size_t base = ((size_t)(mb * Kch + c)) << 11;
        out[base + idx] = hi;
        out[base + 1024 + idx] = lo;
    }
}

// ---------------- npj = relu(LN(x @ Wk1 + bk1)), [V,20] ----------------
__global__ void npj_kernel(const float* __restrict__ x,
                           const float* __restrict__ Wk1,
                           const float* __restrict__ bk1,
                           const float* __restrict__ g,
                           const float* __restrict__ b, int V) {
    __shared__ float xs[4][D];
    int warp = threadIdx.x >> 5, lane = threadIdx.x & 31;
    int v  = blockIdx.x * 4 + warp;
    int vc = v < V ? v : V - 1;
    *(float4*)&xs[warp][lane << 2] = *(const float4*)&x[vc * D + (lane << 2)];
    __syncwarp();
    float y = 0.f;
    if (lane < KP) {
        #pragma unroll 8
        for (int k = 0; k < D; k++) y = fmaf(xs[warp][k], Wk1[k * KP + lane], y);
        y += bk1[lane];
    }
    float s = (lane < KP) ? y : 0.f;
    #pragma unroll
    for (int m = 16; m; m >>= 1) s += __shfl_xor_sync(0xffffffffu, s, m);
    float mu = s * (1.f / KP);
    float dv = (lane < KP) ? (y - mu) * (y - mu) : 0.f;
    #pragma unroll
    for (int m = 16; m; m >>= 1) dv += __shfl_xor_sync(0xffffffffu, dv, m);
    float rstd = rsqrtf(dv * (1.f / KP) + EPS);
    if (v < V && lane < KP) {
        float val = (y - mu) * rstd * g[lane] + b[lane];
        g_npj[v * KP + lane] = fmaxf(val, 0.f);
    }
}

// ---------------- edge logits + segment max ----------------
__global__ void logits_kernel(const float* __restrict__ x,
                              const int* __restrict__ src,
                              const int* __restrict__ dst,
                              const float* __restrict__ We,
                              const float* __restrict__ be, int E) {
    int e = blockIdx.x * 4 + (threadIdx.x >> 5);
    if (e >= E) return;
    int lane = threadIdx.x & 31;
    int sn = src[e], dn = dst[e];
    float4 xd = *(const float4*)&x[dn * D + (lane << 2)];
    float4 w1 = *(const float4*)&We[lane << 2];
    float4 xv = *(const float4*)&x[sn * D + (lane << 2)];
    float4 w2 = *(const float4*)&We[D + (lane << 2)];
    float p = xd.x * w1.x + xd.y * w1.y + xd.z * w1.z + xd.w * w1.w
            + xv.x * w2.x + xv.y * w2.y + xv.z * w2.z + xv.w * w2.w;
    #pragma unroll
    for (int m = 16; m; m >>= 1) p += __shfl_xor_sync(0xffffffffu, p, m);
    if (lane == 0) {
        float lg = fmaxf(p + be[0], 0.f);
        g_logit[e] = lg;
        atomicMax((int*)&g_lmax[dn], __float_as_int(lg));  // valid: lg >= 0
    }
}

// ---------------- a = exp(logit - lmax[dst]); asum += a ----------------
__global__ void expsum_kernel(const int* __restrict__ dst, int E) {
    int e = blockIdx.x * blockDim.x + threadIdx.x;
    if (e >= E) return;
    int dn = dst[e];
    float a = expf(g_logit[e] - g_lmax[dn]);
    g_aexp[e] = a;
    atomicAdd(&g_asum[dn], a);
}

// ---------------- context scatter (vector atomics) ----------------
__global__ void context_kernel(const int* __restrict__ src,
                               const int* __restrict__ dst, int E) {
    int e = blockIdx.x * 8 + (threadIdx.x >> 5);
    if (e >= E) return;
    int lane = threadIdx.x & 31;
    int sn = src[e], dn = dst[e];
    float coef = g_aexp[e] / g_asum[dn];
    float4 h = *(const float4*)&g_hv[(size_t)sn * D + (lane << 2)];
    atomicAdd((float4*)&g_ctx[(size_t)dn * D + (lane << 2)],
              make_float4(h.x * coef, h.y * coef, h.z * coef, h.w * coef));
}

// =====================================================================
// Node GEMM, fp16 2-pass: (ah+al)·bh. A compact hi/lo, B hi only.
// Tile M=64 x N=128 (grid.y over N). 8 warps: wm=w&3, wn=w>>2.
// =====================================================================
__global__ __launch_bounds__(256)
void mma_gemm(const uint32_t* __restrict__ As, const uint32_t* __restrict__ Bs,
              int Kchunks, int Ntot,
              const float* __restrict__ bias,
              const float* __restrict__ lng, const float* __restrict__ lnb,
              float* __restrict__ out, int V) {
    __shared__ uint32_t sa[2048];   // hi [0,1024) lo [1024,2048)
    __shared__ uint32_t sb[2048];   // hi only
    __shared__ float red[2][64][2];

    int t = threadIdx.x;
    int lane = t & 31, w = t >> 5;
    int wm = w & 3, wn = w >> 2;
    int row0 = blockIdx.x * 64;
    int nb = blockIdx.y * 128;

    float acc[8][4];
    #pragma unroll
    for (int j = 0; j < 8; j++) { acc[j][0]=acc[j][1]=acc[j][2]=acc[j][3]=0.f; }

    const uint4* ag = (const uint4*)(As + (size_t)blockIdx.x * Kchunks * 2048);
    const uint4* bg = (const uint4*)(Bs + (size_t)blockIdx.y * Kchunks * 2048);

    uint4 pa0, pa1, pb0, pb1;
    pa0 = ag[t]; pa1 = ag[t + 256];
    pb0 = bg[t]; pb1 = bg[t + 256];

    for (int c = 0; c < Kchunks; c++) {
        __syncthreads();
        ((uint4*)sa)[t] = pa0; ((uint4*)sa)[t + 256] = pa1;
        ((uint4*)sb)[t] = pb0; ((uint4*)sb)[t + 256] = pb1;
        __syncthreads();
        if (c + 1 < Kchunks) {
            const uint4* a4 = ag + (size_t)(c + 1) * 512;
            const uint4* b4 = bg + (size_t)(c + 1) * 512;
            pa0 = a4[t]; pa1 = a4[t + 256];
            pb0 = b4[t]; pb1 = b4[t + 256];
        }
        #pragma unroll
        for (int ks = 0; ks < 2; ks++) {
            uint4 ah = ((const uint4*)sa)[(wm * 2 + ks) * 32 + lane];
            uint4 al = *(const uint4*)&sa[1024 + (((wm * 2 + ks) * 32 + lane) << 2)];
            #pragma unroll
            for (int j = 0; j < 8; j++) {
                int nt = wn * 8 + j;
                uint2 bh = ((const uint2*)sb)[(nt * 2 + ks) * 32 + lane];
                MMA_F16(acc[j], ah, bh);
                MMA_F16(acc[j], al, bh);
            }
        }
    }

    int rl = row0 + wm * 16 + (lane >> 2);
    int rh = rl + 8;
    #pragma unroll
    for (int j = 0; j < 8; j++) {
        int gc = nb + wn * 64 + j * 8 + ((lane & 3) << 1);
        float b0 = bias[gc], b1 = bias[gc + 1];
        acc[j][0] += b0; acc[j][1] += b1; acc[j][2] += b0; acc[j][3] += b1;
    }
    if (lng == nullptr) {
        #pragma unroll
        for (int j = 0; j < 8; j++) {
            int gc = nb + wn * 64 + j * 8 + ((lane & 3) << 1);
            if (rl < V) *(float2*)&out[(size_t)rl * Ntot + gc] = make_float2(acc[j][0], acc[j][1]);
            if (rh < V) *(float2*)&out[(size_t)rh * Ntot + gc] = make_float2(acc[j][2], acc[j][3]);
        }
    } else {
        float s_lo=0.f, q_lo=0.f, s_hi=0.f, q_hi=0.f;
        #pragma unroll
        for (int j = 0; j < 8; j++) {
            s_lo += acc[j][0] + acc[j][1];
            q_lo += acc[j][0]*acc[j][0] + acc[j][1]*acc[j][1];
            s_hi += acc[j][2] + acc[j][3];
            q_hi += acc[j][2]*acc[j][2] + acc[j][3]*acc[j][3];
        }
        #pragma unroll
        for (int m = 1; m <= 2; m <<= 1) {
            s_lo += __shfl_xor_sync(0xffffffffu, s_lo, m);
            q_lo += __shfl_xor_sync(0xffffffffu, q_lo, m);
            s_hi += __shfl_xor_sync(0xffffffffu, s_hi, m);
            q_hi += __shfl_xor_sync(0xffffffffu, q_hi, m);
        }
        int rloc = wm * 16 + (lane >> 2);
        if ((lane & 3) == 0) {
            red[wn][rloc][0] = s_lo;   red[wn][rloc][1] = q_lo;
            red[wn][rloc+8][0] = s_hi; red[wn][rloc+8][1] = q_hi;
        }
        __syncthreads();
        float ts_lo = s_lo + red[wn ^ 1][rloc][0];
        float tq_lo = q_lo + red[wn ^ 1][rloc][1];
        float ts_hi = s_hi + red[wn ^ 1][rloc + 8][0];
        float tq_hi = q_hi + red[wn ^ 1][rloc + 8][1];
        float mu_lo = ts_lo * (1.f/128.f);
        float mu_hi = ts_hi * (1.f/128.f);
        float rs_lo = rsqrtf(tq_lo * (1.f/128.f) - mu_lo*mu_lo + EPS);
        float rs_hi = rsqrtf(tq_hi * (1.f/128.f) - mu_hi*mu_hi + EPS);
        #pragma unroll
        for (int j = 0; j < 8; j++) {
            int gc = wn * 64 + j * 8 + ((lane & 3) << 1);
            float g0 = lng[gc], g1 = lng[gc+1];
            float bb0 = lnb[gc], bb1 = lnb[gc+1];
            if (rl < V) {
                float o0 = fmaxf((acc[j][0]-mu_lo)*rs_lo*g0 + bb0, 0.f);
                float o1 = fmaxf((acc[j][1]-mu_lo)*rs_lo*g1 + bb1, 0.f);
                *(float2*)&out[(size_t)rl * 128 + gc] = make_float2(o0, o1);
            }
            if (rh < V) {
                float o2 = fmaxf((acc[j][2]-mu_hi)*rs_hi*g0 + bb0, 0.f);
                float o3 = fmaxf((acc[j][3]-mu_hi)*rs_hi*g1 + bb1, 0.f);
                *(float2*)&out[(size_t)rh * 128 + gc] = make_float2(o2, o3);
            }
        }
    }
}

// =====================================================================
// Kron edge GEMM fp16 2-pass: 128 edges x 128 outs, K=400 (5 chunks of 80),
// LN + relu + atomic scatter to g_kf[dst].
// =====================================================================
__global__ __launch_bounds__(256, 2)
void kron_mma(const int* __restrict__ src, const int* __restrict__ dst,
              const uint32_t* __restrict__ Wk2S,
              const float* __restrict__ bk2,
              const float* __restrict__ lng, const float* __restrict__ lnb,
              int E) {
    extern __shared__ uint32_t dsm[];
    uint32_t* sa = dsm;               // 10240: hi [0,5120) lo [5120,10240)
    uint32_t* sb = dsm + 10240;       // 5120 (hi only)
    float* Ss = (float*)(dsm + 15360);   // 128*20
    float* Ds = Ss + 2560;               // 128*20
    __shared__ int ssrc[128], sdst[128];
    __shared__ float red[2][128][2];

    int t = threadIdx.x;
    int lane = t & 31, w = t >> 5;
    int wm = w & 3, wn = w >> 2;
    int e0 = blockIdx.x * 128;

    if (t < 128) {
        int ee = e0 + t; if (ee >= E) ee = E - 1;
        ssrc[t] = src[ee];
        sdst[t] = dst[ee];
    }
    __syncthreads();
    for (int idx = t; idx < 640; idx += 256) {
        int e = idx / 5, q = idx - e * 5;
        ((float4*)Ss)[idx] = *(const float4*)&g_npj[ssrc[e] * KP + q * 4];
        ((float4*)Ds)[idx] = *(const float4*)&g_npj[sdst[e] * KP + q * 4];
    }

    float acc[2][8][4];
    #pragma unroll
    for (int r = 0; r < 2; r++)
        #pragma unroll
        for (int j = 0; j < 8; j++) { acc[r][j][0]=acc[r][j][1]=acc[r][j][2]=acc[r][j][3]=0.f; }

    int be = t >> 1, ih = t & 1;
    int amt = be >> 4;
    int ribase = (be >> 3) & 1;
    int alnb = (be & 7) << 2;

    for (int c = 0; c < 5; c++) {
        __syncthreads();
        {
            const float* ds = &Ds[be * 20];
            #pragma unroll
            for (int iv = 0; iv < 2; iv++) {
                int il = ih * 2 + iv;
                float sv = Ss[be * 20 + c * 4 + il];
                #pragma unroll
                for (int q = 0; q < 10; q++) {
                    float2 d = *(const float2*)&ds[2 * q];
                    float p0 = sv * d.x, p1 = sv * d.y;
                    int kp = il * 10 + q;
                    int ai = (((amt * 5 + (kp >> 3)) * 32 + alnb + (kp & 3)) << 2)
                             + ribase + (((kp >> 2) & 1) << 1);
                    uint32_t hi, lo;
                    split_pair(p0, p1, hi, lo);
                    sa[ai] = hi;
                    sa[5120 + ai] = lo;
                }
            }
        }
        {
            const uint4* bsrc = (const uint4*)(Wk2S + c * 5120);
            #pragma unroll
            for (int i = 0; i < 5; i++)
                ((uint4*)sb)[t + (i << 8)] = bsrc[t + (i << 8)];
        }
        __syncthreads();
        #pragma unroll
        for (int ks = 0; ks < 5; ks++) {
            uint4 ah0 = ((const uint4*)sa)[((wm * 2 + 0) * 5 + ks) * 32 + lane];
            uint4 al0 = ((const uint4*)sa)[1280 + ((wm * 2 + 0) * 5 + ks) * 32 + lane];
            uint4 ah1 = ((const uint4*)sa)[((wm * 2 + 1) * 5 + ks) * 32 + lane];
            uint4 al1 = ((const uint4*)sa)[1280 + ((wm * 2 + 1) * 5 + ks) * 32 + lane];
            #pragma unroll
            for (int j = 0; j < 8; j++) {
                int nt = wn * 8 + j;
                uint2 bh = ((const uint2*)sb)[(nt * 5 + ks) * 32 + lane];
                MMA_F16(acc[0][j], ah0, bh);
                MMA_F16(acc[0][j], al0, bh);
                MMA_F16(acc[1][j], ah1, bh);
                MMA_F16(acc[1][j], al1, bh);
            }
        }
    }

    #pragma unroll
    for (int r = 0; r < 2; r++)
        #pragma unroll
        for (int j = 0; j < 8; j++) {
            int gc = wn * 64 + j * 8 + ((lane & 3) << 1);
            float b0 = bk2[gc], b1 = bk2[gc + 1];
            acc[r][j][0] += b0; acc[r][j][1] += b1;
            acc[r][j][2] += b0; acc[r][j][3] += b1;
        }
    float sum[2][2], sq[2][2];
    #pragma unroll
    for (int r = 0; r < 2; r++) {
        float s_lo=0.f, q_lo=0.f, s_hi=0.f, q_hi=0.f;
        #pragma unroll
        for (int j = 0; j < 8; j++) {
            s_lo += acc[r][j][0] + acc[r][j][1];
            q_lo += acc[r][j][0]*acc[r][j][0] + acc[r][j][1]*acc[r][j][1];
            s_hi += acc[r][j][2] + acc[r][j][3];
            q_hi += acc[r][j][2]*acc[r][j][2] + acc[r][j][3]*acc[r][j][3];
        }
        #pragma unroll
        for (int m = 1; m <= 2; m <<= 1) {
            s_lo += __shfl_xor_sync(0xffffffffu, s_lo, m);
            q_lo += __shfl_xor_sync(0xffffffffu, q_lo, m);
            s_hi += __shfl_xor_sync(0xffffffffu, s_hi, m);
            q_hi += __shfl_xor_sync(0xffffffffu, q_hi, m);
        }
        sum[r][0] = s_lo; sq[r][0] = q_lo;
        sum[r][1] = s_hi; sq[r][1] = q_hi;
        if ((lane & 3) == 0) {
            int rloc = wm * 32 + r * 16 + (lane >> 2);
            red[wn][rloc][0] = s_lo;     red[wn][rloc][1] = q_lo;
            red[wn][rloc + 8][0] = s_hi; red[wn][rloc + 8][1] = q_hi;
        }
    }
    __syncthreads();
    #pragma unroll
    for (int r = 0; r < 2; r++) {
        #pragma unroll
        for (int h = 0; h < 2; h++) {
            int rloc = wm * 32 + r * 16 + h * 8 + (lane >> 2);
            float ts = sum[r][h] + red[wn ^ 1][rloc][0];
            float tq = sq[r][h] + red[wn ^ 1][rloc][1];
            float mu = ts * (1.f / 128.f);
            float rs = rsqrtf(tq * (1.f / 128.f) - mu * mu + EPS);
            int ge = e0 + rloc;
            if (ge < E) {
                int dn = sdst[rloc];
                #pragma unroll
                for (int j = 0; j < 8; j++) {
                    int gc = wn * 64 + j * 8 + ((lane & 3) << 1);
                    float g0 = lng[gc], g1 = lng[gc + 1];
                    float bb0 = lnb[gc], bb1 = lnb[gc + 1];
                    float* p = &g_kf[(size_t)dn * 128 + gc];
                    atomicAdd(p,     fmaxf((acc[r][j][2*h  ]-mu)*rs*g0 + bb0, 0.f));
                    atomicAdd(p + 1, fmaxf((acc[r][j][2*h+1]-mu)*rs*g1 + bb1, 0.f));
                }
            }
        }
    }
}

// ---------------- GRU gates + relu + LN ----------------
__global__ void gates_kernel(const float* __restrict__ x,
                             const float* __restrict__ lng,
                             const float* __restrict__ lnb, int V) {
    int v = blockIdx.x * 8 + (threadIdx.x >> 5);
    if (v >= V) return;
    int lane = threadIdx.x & 31;
    const float* gi = &g_gi[(size_t)v * 384];
    const float* gh = &g_gh[(size_t)v * 384];
    float4 gir = *(const float4*)&gi[(lane << 2)];
    float4 giz = *(const float4*)&gi[128 + (lane << 2)];
    float4 gin = *(const float4*)&gi[256 + (lane << 2)];
    float4 ghr = *(const float4*)&gh[(lane << 2)];
    float4 ghz = *(const float4*)&gh[128 + (lane << 2)];
    float4 ghn = *(const float4*)&gh[256 + (lane << 2)];
    float4 xv  = *(const float4*)&x[(size_t)v * D + (lane << 2)];
    float h[4];
    #pragma unroll
    for (int i = 0; i < 4; i++) {
        float r = 1.f / (1.f + expf(-((&gir.x)[i] + (&ghr.x)[i])));
        float z = 1.f / (1.f + expf(-((&giz.x)[i] + (&ghz.x)[i])));
        float n = tanhf((&gin.x)[i] + r * (&ghn.x)[i]);
        h[i] = fmaxf((1.f - z) * n + z * (&xv.x)[i], 0.f);
    }
    float s = h[0] + h[1] + h[2] + h[3];
    #pragma unroll
    for (int m = 16; m; m >>= 1) s += __shfl_xor_sync(0xffffffffu, s, m);
    float mu = s * (1.f / 128.f), q = 0.f;
    #pragma unroll
    for (int i = 0; i < 4; i++) { float d0 = h[i] - mu; q = fmaf(d0, d0, q); }
    #pragma unroll
    for (int m = 16; m; m >>= 1) q += __shfl_xor_sync(0xffffffffu, q, m);
    float rstd = rsqrtf(q * (1.f / 128.f) + EPS);
    float4 gv = *(const float4*)&lng[lane << 2];
    float4 b2 = *(const float4*)&lnb[lane << 2];
    float4 o;
    o.x = (h[0] - mu) * rstd * gv.x + b2.x;
    o.y = (h[1] - mu) * rstd * gv.y + b2.y;
    o.z = (h[2] - mu) * rstd * gv.z + b2.z;
    o.w = (h[3] - mu) * rstd * gv.w + b2.w;
    *(float4*)&g_gru[(size_t)v * D + (lane << 2)] = o;
}

// ---------------- host ----------------
extern "C" void kernel_launch(void* const* d_in, const int* in_sizes, int n_in,
                              void* d_out, int out_size) {
    const float* node   = (const float*)d_in[0];
    const int*   src    = (const int*)  d_in[1];
    const int*   dst    = (const int*)  d_in[2];
    const float* W_edge = (const float*)d_in[3];
    const float* b_edge = (const float*)d_in[4];
    const float* W_pn   = (const float*)d_in[5];
    const float* b_pn   = (const float*)d_in[6];
    const float* W_ih   = (const float*)d_in[7];
    const float* b_ih   = (const float*)d_in[8];
    const float* W_hh   = (const float*)d_in[9];
    const float* b_hh   = (const float*)d_in[10];
    const float* ln_g   = (const float*)d_in[11];
    const float* ln_b   = (const float*)d_in[12];
    const float* Wk1    = (const float*)d_in[13];
    const float* bk1    = (const float*)d_in[14];
    const float* lnk1_g = (const float*)d_in[15];
    const float* lnk1_b = (const float*)d_in[16];
    const float* Wk2    = (const float*)d_in[17];
    const float* bk2    = (const float*)d_in[18];
    const float* lnk2_g = (const float*)d_in[19];
    const float* lnk2_b = (const float*)d_in[20];
    const float* Wc     = (const float*)d_in[21];
    const float* bc     = (const float*)d_in[22];
    const float* lnc_g  = (const float*)d_in[23];
    const float* lnc_b  = (const float*)d_in[24];
    int V = in_sizes[0] / D;
    int E = in_sizes[1];
    float* out = (float*)d_out;

    float *p_asum, *p_lmax, *p_hv, *p_ctx, *p_kf, *p_gi, *p_gh, *p_gru;
    uint32_t *p_WpnS, *p_WihS, *p_WhhS, *p_WcS, *p_Wk2S;
    uint32_t *p_An, *p_Ac, *p_Aq;
    cudaGetSymbolAddress((void**)&p_asum, g_asum);
    cudaGetSymbolAddress((void**)&p_lmax, g_lmax);
    cudaGetSymbolAddress((void**)&p_hv,   g_hv);
    cudaGetSymbolAddress((void**)&p_ctx,  g_ctx);
    cudaGetSymbolAddress((void**)&p_kf,   g_kf);
    cudaGetSymbolAddress((void**)&p_gi,   g_gi);
    cudaGetSymbolAddress((void**)&p_gh,   g_gh);
    cudaGetSymbolAddress((void**)&p_gru,  g_gru);
    cudaGetSymbolAddress((void**)&p_WpnS, g_WpnS);
    cudaGetSymbolAddress((void**)&p_WihS, g_WihS);
    cudaGetSymbolAddress((void**)&p_WhhS, g_WhhS);
    cudaGetSymbolAddress((void**)&p_WcS,  g_WcS);
    cudaGetSymbolAddress((void**)&p_Wk2S, g_Wk2S);
    cudaGetSymbolAddress((void**)&p_An,   g_Anode);
    cudaGetSymbolAddress((void**)&p_Ac,   g_Actx);
    cudaGetSymbolAddress((void**)&p_Aq,   g_Acat);

    static bool attr_set = false;
    if (!attr_set) {
        cudaFuncSetAttribute(kron_mma, cudaFuncAttributeMaxDynamicSharedMemorySize, 82000);
        attr_set = true;
    }

    int NBv = (V + 63) / 64;

    // zero accumulators
    {
        int n4 = V * D / 4;
        zero_kernel<<<(n4 + 255) / 256, 256>>>((float4*)p_ctx, n4);
        zero_kernel<<<(n4 + 255) / 256, 256>>>((float4*)p_kf,  n4);
        n4 = V / 4;
        zero_kernel<<<(n4 + 255) / 256, 256>>>((float4*)p_asum, n4);
        zero_kernel<<<(n4 + 255) / 256, 256>>>((float4*)p_lmax, n4);
    }

    // pack weights (fp16 hi only)
    pack_w_frag<<<(64 * 128 + 255) / 256, 256>>>(W_pn, 128, 128, 0, p_WpnS);
    pack_w_frag<<<(64 * 384 + 255) / 256, 256>>>(W_ih, 128, 384, 1, p_WihS);
    pack_w_frag<<<(64 * 384 + 255) / 256, 256>>>(W_hh, 128, 384, 1, p_WhhS);
    pack_w_frag<<<(128 * 128 + 255) / 256, 256>>>(Wc, 256, 128, 0, p_WcS);
    pack_wk2<<<(200 * 128 + 255) / 256, 256>>>(Wk2, p_Wk2S);

    // pack node activations (fp16 hi/lo)
    pack_act<<<NBv, 256>>>(node, 128, nullptr, 0, 0, p_An, V);

    npj_kernel<<<(V + 3) / 4, 128>>>(node, Wk1, bk1, lnk1_g, lnk1_b, V);
    logits_kernel<<<(E + 3) / 4, 128>>>(node, src, dst, W_edge, b_edge, E);
    expsum_kernel<<<(E + 255) / 256, 256>>>(dst, E);

    // hv = node @ W_pn + b_pn
    mma_gemm<<<dim3(NBv, 1), 256>>>(p_An, p_WpnS, 4, 128,
                                    b_pn, nullptr, nullptr, p_hv, V);

    // edge kron GEMM + LN + relu + atomic scatter
    kron_mma<<<(E + 127) / 128, 256, 81920>>>(src, dst, p_Wk2S,
                                              bk2, lnk2_g, lnk2_b, E);

    // context scatter (float4 atomics)
    context_kernel<<<(E + 7) / 8, 256>>>(src, dst, E);

    // pack relu(ctx)
    pack_act<<<NBv, 256>>>(p_ctx, 128, nullptr, 0, 1, p_Ac, V);

    // gi = relu(ctx) @ W_ih^T + b_ih ; gh = node @ W_hh^T + b_hh
    mma_gemm<<<dim3(NBv, 3), 256>>>(p_Ac, p_WihS, 4, 384,
                                    b_ih, nullptr, nullptr, p_gi, V);
    mma_gemm<<<dim3(NBv, 3), 256>>>(p_An, p_WhhS, 4, 384,
                                    b_hh, nullptr, nullptr, p_gh, V);

    gates_kernel<<<(V + 7) / 8, 256>>>(node, ln_g, ln_b, V);

    // pack cat(gru, kf)
    pack_act<<<NBv, 256>>>(p_gru, 128, p_kf, 128, 0, p_Aq, V);

    // out = relu(LN(cat @ Wc + bc))
    mma_gemm<<<dim3(NBv, 1), 256>>>(p_Aq, p_WcS, 8, 128,
                                    bc, lnc_g, lnc_b, out, V);
}

// round 10
// speedup vs baseline: 1.3456x; 1.1067x over previous
#include <cuda_runtime.h>
#include <cuda_fp16.h>
#include <math.h>
#include <stdint.h>

#define D     128
#define KP    20
#define VMAX  100000
#define EMAX  400000
#define EPS   1e-5f
#define NBMAX 1563   // (VMAX+63)/64

// ---------------- scratch (device globals; no allocations) ----------------
__device__ float g_npj  [VMAX * KP];
__device__ float g_logit[EMAX];
__device__ float g_aexp [EMAX];
__device__ float g_lmax [VMAX];
__device__ float g_asum [VMAX];
__device__ float g_hv   [VMAX * D];
__device__ float g_ctx  [VMAX * D];
__device__ float g_kf   [VMAX * D];
__device__ float g_gi   [VMAX * 3 * D];
__device__ float g_gh   [VMAX * 3 * D];

// fragment-ordered fp16 WEIGHT streams (hi only; per (ny,chunk): 2048 u32)
__device__ uint32_t g_WpnS[1 * 4 * 2048];
__device__ uint32_t g_WihS[3 * 4 * 2048];
__device__ uint32_t g_WhhS[3 * 4 * 2048];
__device__ uint32_t g_WcS [1 * 8 * 2048];
__device__ uint32_t g_Wk2S[5 * 5120];

// COMPACT fragment-ordered fp16 hi/lo ACTIVATION streams
// per (mblock64, chunk32): 2048 u32 = hi[0,1024) lo[1024,2048)
__device__ uint32_t g_Anode[(size_t)NBMAX * 4 * 2048];
__device__ uint32_t g_Actx [(size_t)NBMAX * 4 * 2048];
__device__ uint32_t g_Acat [(size_t)NBMAX * 8 * 2048];

// ---------------- fp16 RN hi/lo split ----------------
__device__ __forceinline__ void split_pair(float a0, float a1,
                                           uint32_t& hi, uint32_t& lo) {
    __half h0 = __float2half_rn(a0), h1 = __float2half_rn(a1);
    float l0 = a0 - __half2float(h0);
    float l1 = a1 - __half2float(h1);
    __half2 hp = __halves2half2(h0, h1);
    __half2 lp = __floats2half2_rn(l0, l1);
    hi = *(uint32_t*)&hp;
    lo = *(uint32_t*)&lp;
}
__device__ __forceinline__ uint32_t pack_hi16(float a0, float a1) {
    __half2 hp = __floats2half2_rn(a0, a1);
    return *(uint32_t*)&hp;
}

#define MMA_F16(c, A, B) asm volatile( \
    "mma.sync.aligned.m16n8k16.row.col.f32.f16.f16.f32 " \
    "{%0,%1,%2,%3}, {%4,%5,%6,%7}, {%8,%9}, {%0,%1,%2,%3};\n" \
    : "+f"(c[0]), "+f"(c[1]), "+f"(c[2]), "+f"(c[3]) \
    : "r"(A.x), "r"(A.y), "r"(A.z), "r"(A.w), "r"(B.x), "r"(B.y))

// ---------------- utility kernels ----------------
__global__ void zero_kernel(float4* p, int n4) {
    int i = blockIdx.x * blockDim.x + threadIdx.x;
    if (i < n4) p[i] = make_float4(0.f, 0.f, 0.f, 0.f);
}

// pack weights (fp16 hi only): per (ny, chunk): 2048 u32
__global__ void pack_w_frag(const float* __restrict__ W, int K, int Ntot,
                            int transp, uint32_t* __restrict__ out) {
    int idx = blockIdx.x * blockDim.x + threadIdx.x;
    int total = (K / 2) * Ntot;
    if (idx >= total) return;
    int kp = idx / Ntot, n = idx - kp * Ntot;
    int k0 = 2 * kp;
    float w0, w1;
    if (transp) { w0 = W[n * K + k0]; w1 = W[n * K + k0 + 1]; }
    else        { w0 = W[k0 * Ntot + n]; w1 = W[(k0 + 1) * Ntot + n]; }
    int c = kp >> 4, kpl = kp & 15;
    int ny = n >> 7, nl = n & 127;
    int bi = ((((nl >> 3) * 2 + (kpl >> 3)) * 32 + ((nl & 7) << 2) + (kpl & 3)) << 1)
             + ((kpl >> 2) & 1);
    size_t base = ((size_t)(ny * (K >> 5) + c)) << 11;
    out[base + bi] = pack_hi16(w0, w1);
}

// Wk2 [400][128] -> kron stream (fp16 hi only): per chunk(5): 5120 u32
__global__ void pack_wk2(const float* __restrict__ W, uint32_t* __restrict__ out) {
    int idx = blockIdx.x * blockDim.x + threadIdx.x;
    if (idx >= 200 * 128) return;
    int kp = idx >> 7, n = idx & 127;
    float w0 = W[(2 * kp) * 128 + n];
    float w1 = W[(2 * kp + 1) * 128 + n];
    int c = kp / 40, kpl = kp - c * 40;
    int bi = ((((n >> 3) * 5 + (kpl >> 3)) * 32 + ((n & 7) << 2) + (kpl & 3)) << 1)
             + ((kpl >> 2) & 1);
    out[c * 5120 + bi] = pack_hi16(w0, w1);
}

// COMPACT activation pack (fp16 hi/lo) with output chunk offset.
// Packs X[V, K0(+K1)] into chunks [coff, coff + K/32) of a KchTot-chunk stream.
__global__ void pack_act(const float* __restrict__ X0, int K0,
                         const float* __restrict__ X1, int K1, int relu,
                         uint32_t* __restrict__ out, int V,
                         int coff, int KchTot) {
    int t = threadIdx.x;
    int mb = blockIdx.x;
    int K = K0 + K1;
    int Kch = K >> 5;
    for (int it = 0; it < Kch * 4; it++) {
        int c = it >> 2;
        int idx = ((it & 3) << 8) + t;       // 0..1023 within chunk
        int mt = idx >> 8;
        int ks = (idx >> 7) & 1;
        int ln = (idx >> 2) & 31;
        int ri = idx & 3;
        int row = mb * 64 + mt * 16 + (ri & 1) * 8 + (ln >> 2);
        if (row >= V) row = V - 1;
        int k = c * 32 + ks * 16 + ((ri >> 1) << 3) + ((ln & 3) << 1);
        float2 a;
        if (k < K0) a = *(const float2*)&X0[(size_t)row * K0 + k];
        else        a = *(const float2*)&X1[(size_t)row * K1 + (k - K0)];
        if (relu) { a.x = fmaxf(a.x, 0.f); a.y = fmaxf(a.y, 0.f); }
        uint32_t hi, lo;
        split_pair(a.x, a.y, hi, lo);
        size_t base = ((size_t)(mb * KchTot + coff + c)) << 11;
        out[base + idx] = hi;
        out[base + 1024 + idx] = lo;
    }
}

// ---------------- npj = relu(LN(x @ Wk1 + bk1)), [V,20] ----------------
__global__ void npj_kernel(const float* __restrict__ x,
                           const float* __restrict__ Wk1,
                           const float* __restrict__ bk1,
                           const float* __restrict__ g,
                           const float* __restrict__ b, int V) {
    __shared__ float xs[4][D];
    int warp = threadIdx.x >> 5, lane = threadIdx.x & 31;
    int v  = blockIdx.x * 4 + warp;
    int vc = v < V ? v : V - 1;
    *(float4*)&xs[warp][lane << 2] = *(const float4*)&x[vc * D + (lane << 2)];
    __syncwarp();
    float y = 0.f;
    if (lane < KP) {
        #pragma unroll 8
        for (int k = 0; k < D; k++) y = fmaf(xs[warp][k], Wk1[k * KP + lane], y);
        y += bk1[lane];
    }
    float s = (lane < KP) ? y : 0.f;
    #pragma unroll
    for (int m = 16; m; m >>= 1) s += __shfl_xor_sync(0xffffffffu, s, m);
    float mu = s * (1.f / KP);
    float dv = (lane < KP) ? (y - mu) * (y - mu) : 0.f;
    #pragma unroll
    for (int m = 16; m; m >>= 1) dv += __shfl_xor_sync(0xffffffffu, dv, m);
    float rstd = rsqrtf(dv * (1.f / KP) + EPS);
    if (v < V && lane < KP) {
        float val = (y - mu) * rstd * g[lane] + b[lane];
        g_npj[v * KP + lane] = fmaxf(val, 0.f);
    }
}

// ---------------- edge logits + segment max ----------------
__global__ void logits_kernel(const float* __restrict__ x,
                              const int* __restrict__ src,
                              const int* __restrict__ dst,
                              const float* __restrict__ We,
                              const float* __restrict__ be, int E) {
    int e = blockIdx.x * 4 + (threadIdx.x >> 5);
    if (e >= E) return;
    int lane = threadIdx.x & 31;
    int sn = src[e], dn = dst[e];
    float4 xd = *(const float4*)&x[dn * D + (lane << 2)];
    float4 w1 = *(const float4*)&We[lane << 2];
    float4 xv = *(const float4*)&x[sn * D + (lane << 2)];
    float4 w2 = *(const float4*)&We[D + (lane << 2)];
    float p = xd.x * w1.x + xd.y * w1.y + xd.z * w1.z + xd.w * w1.w
            + xv.x * w2.x + xv.y * w2.y + xv.z * w2.z + xv.w * w2.w;
    #pragma unroll
    for (int m = 16; m; m >>= 1) p += __shfl_xor_sync(0xffffffffu, p, m);
    if (lane == 0) {
        float lg = fmaxf(p + be[0], 0.f);
        g_logit[e] = lg;
        atomicMax((int*)&g_lmax[dn], __float_as_int(lg));  // valid: lg >= 0
    }
}

// ---------------- a = exp(logit - lmax[dst]); asum += a ----------------
__global__ void expsum_kernel(const int* __restrict__ dst, int E) {
    int e = blockIdx.x * blockDim.x + threadIdx.x;
    if (e >= E) return;
    int dn = dst[e];
    float a = expf(g_logit[e] - g_lmax[dn]);
    g_aexp[e] = a;
    atomicAdd(&g_asum[dn], a);
}

// ---------------- context scatter (vector atomics) ----------------
__global__ void context_kernel(const int* __restrict__ src,
                               const int* __restrict__ dst, int E) {
    int e = blockIdx.x * 8 + (threadIdx.x >> 5);
    if (e >= E) return;
    int lane = threadIdx.x & 31;
    int sn = src[e], dn = dst[e];
    float coef = g_aexp[e] / g_asum[dn];
    float4 h = *(const float4*)&g_hv[(size_t)sn * D + (lane << 2)];
    atomicAdd((float4*)&g_ctx[(size_t)dn * D + (lane << 2)],
              make_float4(h.x * coef, h.y * coef, h.z * coef, h.w * coef));
}

// =====================================================================
// Node GEMM, fp16 2-pass: (ah+al)·bh. A compact hi/lo, B hi only.
// Tile M=64 x N=128 (grid.y over N). 8 warps: wm=w&3, wn=w>>2.
// =====================================================================
__global__ __launch_bounds__(256)
void mma_gemm(const uint32_t* __restrict__ As, const uint32_t* __restrict__ Bs,
              int Kchunks, int Ntot,
              const float* __restrict__ bias,
              const float* __restrict__ lng, const float* __restrict__ lnb,
              float* __restrict__ out, int V) {
    __shared__ uint32_t sa[2048];   // hi [0,1024) lo [1024,2048)
    __shared__ uint32_t sb[2048];   // hi only
    __shared__ float red[2][64][2];

    int t = threadIdx.x;
    int lane = t & 31, w = t >> 5;
    int wm = w & 3, wn = w >> 2;
    int row0 = blockIdx.x * 64;
    int nb = blockIdx.y * 128;

    float acc[8][4];
    #pragma unroll
    for (int j = 0; j < 8; j++) { acc[j][0]=acc[j][1]=acc[j][2]=acc[j][3]=0.f; }

    const uint4* ag = (const uint4*)(As + (size_t)blockIdx.x * Kchunks * 2048);
    const uint4* bg = (const uint4*)(Bs + (size_t)blockIdx.y * Kchunks * 2048);

    uint4 pa0, pa1, pb0, pb1;
    pa0 = ag[t]; pa1 = ag[t + 256];
    pb0 = bg[t]; pb1 = bg[t + 256];

    for (int c = 0; c < Kchunks; c++) {
        __syncthreads();
        ((uint4*)sa)[t] = pa0; ((uint4*)sa)[t + 256] = pa1;
        ((uint4*)sb)[t] = pb0; ((uint4*)sb)[t + 256] = pb1;
        __syncthreads();
        if (c + 1 < Kchunks) {
            const uint4* a4 = ag + (size_t)(c + 1) * 512;
            const uint4* b4 = bg + (size_t)(c + 1) * 512;
            pa0 = a4[t]; pa1 = a4[t + 256];
            pb0 = b4[t]; pb1 = b4[t + 256];
        }
        #pragma unroll
        for (int ks = 0; ks < 2; ks++) {
            uint4 ah = ((const uint4*)sa)[(wm * 2 + ks) * 32 + lane];
            uint4 al = *(const uint4*)&sa[1024 + (((wm * 2 + ks) * 32 + lane) << 2)];
            #pragma unroll
            for (int j = 0; j < 8; j++) {
                int nt = wn * 8 + j;
                uint2 bh = ((const uint2*)sb)[(nt * 2 + ks) * 32 + lane];
                MMA_F16(acc[j], ah, bh);
                MMA_F16(acc[j], al, bh);
            }
        }
    }

    int rl = row0 + wm * 16 + (lane >> 2);
    int rh = rl + 8;
    #pragma unroll
    for (int j = 0; j < 8; j++) {
        int gc = nb + wn * 64 + j * 8 + ((lane & 3) << 1);
        float b0 = bias[gc], b1 = bias[gc + 1];
        acc[j][0] += b0; acc[j][1] += b1; acc[j][2] += b0; acc[j][3] += b1;
    }
    if (lng == nullptr) {
        #pragma unroll
        for (int j = 0; j < 8; j++) {
            int gc = nb + wn * 64 + j * 8 + ((lane & 3) << 1);
            if (rl < V) *(float2*)&out[(size_t)rl * Ntot + gc] = make_float2(acc[j][0], acc[j][1]);
            if (rh < V) *(float2*)&out[(size_t)rh * Ntot + gc] = make_float2(acc[j][2], acc[j][3]);
        }
    } else {
        float s_lo=0.f, q_lo=0.f, s_hi=0.f, q_hi=0.f;
        #pragma unroll
        for (int j = 0; j < 8; j++) {
            s_lo += acc[j][0] + acc[j][1];
            q_lo += acc[j][0]*acc[j][0] + acc[j][1]*acc[j][1];
            s_hi += acc[j][2] + acc[j][3];
            q_hi += acc[j][2]*acc[j][2] + acc[j][3]*acc[j][3];
        }
        #pragma unroll
        for (int m = 1; m <= 2; m <<= 1) {
            s_lo += __shfl_xor_sync(0xffffffffu, s_lo, m);
            q_lo += __shfl_xor_sync(0xffffffffu, q_lo, m);
            s_hi += __shfl_xor_sync(0xffffffffu, s_hi, m);
            q_hi += __shfl_xor_sync(0xffffffffu, q_hi, m);
        }
        int rloc = wm * 16 + (lane >> 2);
        if ((lane & 3) == 0) {
            red[wn][rloc][0] = s_lo;   red[wn][rloc][1] = q_lo;
            red[wn][rloc+8][0] = s_hi; red[wn][rloc+8][1] = q_hi;
        }
        __syncthreads();
        float ts_lo = s_lo + red[wn ^ 1][rloc][0];
        float tq_lo = q_lo + red[wn ^ 1][rloc][1];
        float ts_hi = s_hi + red[wn ^ 1][rloc + 8][0];
        float tq_hi = q_hi + red[wn ^ 1][rloc + 8][1];
        float mu_lo = ts_lo * (1.f/128.f);
        float mu_hi = ts_hi * (1.f/128.f);
        float rs_lo = rsqrtf(tq_lo * (1.f/128.f) - mu_lo*mu_lo + EPS);
        float rs_hi = rsqrtf(tq_hi * (1.f/128.f) - mu_hi*mu_hi + EPS);
        #pragma unroll
        for (int j = 0; j < 8; j++) {
            int gc = wn * 64 + j * 8 + ((lane & 3) << 1);
            float g0 = lng[gc], g1 = lng[gc+1];
            float bb0 = lnb[gc], bb1 = lnb[gc+1];
            if (rl < V) {
                float o0 = fmaxf((acc[j][0]-mu_lo)*rs_lo*g0 + bb0, 0.f);
                float o1 = fmaxf((acc[j][1]-mu_lo)*rs_lo*g1 + bb1, 0.f);
                *(float2*)&out[(size_t)rl * 128 + gc] = make_float2(o0, o1);
            }
            if (rh < V) {
                float o2 = fmaxf((acc[j][2]-mu_hi)*rs_hi*g0 + bb0, 0.f);
                float o3 = fmaxf((acc[j][3]-mu_hi)*rs_hi*g1 + bb1, 0.f);
                *(float2*)&out[(size_t)rh * 128 + gc] = make_float2(o2, o3);
            }
        }
    }
}

// =====================================================================
// Kron edge GEMM fp16 1-PASS (ah·bh only): 128 edges x 128 outs, K=400
// (5 chunks of 80), LN + relu + atomic scatter to g_kf[dst].
// =====================================================================
__global__ __launch_bounds__(256, 2)
void kron_mma(const int* __restrict__ src, const int* __restrict__ dst,
              const uint32_t* __restrict__ Wk2S,
              const float* __restrict__ bk2,
              const float* __restrict__ lng, const float* __restrict__ lnb,
              int E) {
    extern __shared__ uint32_t dsm[];
    uint32_t* sa = dsm;               // 5120 (hi only)
    uint32_t* sb = dsm + 5120;        // 5120 (hi only)
    float* Ss = (float*)(dsm + 10240);   // 128*20
    float* Ds = Ss + 2560;               // 128*20
    __shared__ int ssrc[128], sdst[128];
    __shared__ float red[2][128][2];

    int t = threadIdx.x;
    int lane = t & 31, w = t >> 5;
    int wm = w & 3, wn = w >> 2;
    int e0 = blockIdx.x * 128;

    if (t < 128) {
        int ee = e0 + t; if (ee >= E) ee = E - 1;
        ssrc[t] = src[ee];
        sdst[t] = dst[ee];
    }
    __syncthreads();
    for (int idx = t; idx < 640; idx += 256) {
        int e = idx / 5, q = idx - e * 5;
        ((float4*)Ss)[idx] = *(const float4*)&g_npj[ssrc[e] * KP + q * 4];
        ((float4*)Ds)[idx] = *(const float4*)&g_npj[sdst[e] * KP + q * 4];
    }

    float acc[2][8][4];
    #pragma unroll
    for (int r = 0; r < 2; r++)
        #pragma unroll
        for (int j = 0; j < 8; j++) { acc[r][j][0]=acc[r][j][1]=acc[r][j][2]=acc[r][j][3]=0.f; }

    int be = t >> 1, ih = t & 1;
    int amt = be >> 4;
    int ribase = (be >> 3) & 1;
    int alnb = (be & 7) << 2;

    for (int c = 0; c < 5; c++) {
        __syncthreads();
        {
            const float* ds = &Ds[be * 20];
            #pragma unroll
            for (int iv = 0; iv < 2; iv++) {
                int il = ih * 2 + iv;
                float sv = Ss[be * 20 + c * 4 + il];
                #pragma unroll
                for (int q = 0; q < 10; q++) {
                    float2 d = *(const float2*)&ds[2 * q];
                    float p0 = sv * d.x, p1 = sv * d.y;
                    int kp = il * 10 + q;
                    int ai = (((amt * 5 + (kp >> 3)) * 32 + alnb + (kp & 3)) << 2)
                             + ribase + (((kp >> 2) & 1) << 1);
                    sa[ai] = pack_hi16(p0, p1);
                }
            }
        }
        {
            const uint4* bsrc = (const uint4*)(Wk2S + c * 5120);
            #pragma unroll
            for (int i = 0; i < 5; i++)
                ((uint4*)sb)[t + (i << 8)] = bsrc[t + (i << 8)];
        }
        __syncthreads();
        #pragma unroll
        for (int ks = 0; ks < 5; ks++) {
            uint4 ah0 = ((const uint4*)sa)[((wm * 2 + 0) * 5 + ks) * 32 + lane];
            uint4 ah1 = ((const uint4*)sa)[((wm * 2 + 1) * 5 + ks) * 32 + lane];
            #pragma unroll
            for (int j = 0; j < 8; j++) {
                int nt = wn * 8 + j;
                uint2 bh = ((const uint2*)sb)[(nt * 5 + ks) * 32 + lane];
                MMA_F16(acc[0][j], ah0, bh);
                MMA_F16(acc[1][j], ah1, bh);
            }
        }
    }

    #pragma unroll
    for (int r = 0; r < 2; r++)
        #pragma unroll
        for (int j = 0; j < 8; j++) {
            int gc = wn * 64 + j * 8 + ((lane & 3) << 1);
            float b0 = bk2[gc], b1 = bk2[gc + 1];
            acc[r][j][0] += b0; acc[r][j][1] += b1;
            acc[r][j][2] += b0; acc[r][j][3] += b1;
        }
    float sum[2][2], sq[2][2];
    #pragma unroll
    for (int r = 0; r < 2; r++) {
        float s_lo=0.f, q_lo=0.f, s_hi=0.f, q_hi=0.f;
        #pragma unroll
        for (int j = 0; j < 8; j++) {
            s_lo += acc[r][j][0] + acc[r][j][1];
            q_lo += acc[r][j][0]*acc[r][j][0] + acc[r][j][1]*acc[r][j][1];
            s_hi += acc[r][j][2] + acc[r][j][3];
            q_hi += acc[r][j][2]*acc[r][j][2] + acc[r][j][3]*acc[r][j][3];
        }
        #pragma unroll
        for (int m = 1; m <= 2; m <<= 1) {
            s_lo += __shfl_xor_sync(0xffffffffu, s_lo, m);
            q_lo += __shfl_xor_sync(0xffffffffu, q_lo, m);
            s_hi += __shfl_xor_sync(0xffffffffu, s_hi, m);
            q_hi += __shfl_xor_sync(0xffffffffu, q_hi, m);
        }
        sum[r][0] = s_lo; sq[r][0] = q_lo;
        sum[r][1] = s_hi; sq[r][1] = q_hi;
        if ((lane & 3) == 0) {
            int rloc = wm * 32 + r * 16 + (lane >> 2);
            red[wn][rloc][0] = s_lo;     red[wn][rloc][1] = q_lo;
            red[wn][rloc + 8][0] = s_hi; red[wn][rloc + 8][1] = q_hi;
        }
    }
    __syncthreads();
    #pragma unroll
    for (int r = 0; r < 2; r++) {
        #pragma unroll
        for (int h = 0; h < 2; h++) {
            int rloc = wm * 32 + r * 16 + h * 8 + (lane >> 2);
            float ts = sum[r][h] + red[wn ^ 1][rloc][0];
            float tq = sq[r][h] + red[wn ^ 1][rloc][1];
            float mu = ts * (1.f / 128.f);
            float rs = rsqrtf(tq * (1.f / 128.f) - mu * mu + EPS);
            int ge = e0 + rloc;
            if (ge < E) {
                int dn = sdst[rloc];
                #pragma unroll
                for (int j = 0; j < 8; j++) {
                    int gc = wn * 64 + j * 8 + ((lane & 3) << 1);
                    float g0 = lng[gc], g1 = lng[gc + 1];
                    float bb0 = lnb[gc], bb1 = lnb[gc + 1];
                    float* p = &g_kf[(size_t)dn * 128 + gc];
                    atomicAdd(p,     fmaxf((acc[r][j][2*h  ]-mu)*rs*g0 + bb0, 0.f));
                    atomicAdd(p + 1, fmaxf((acc[r][j][2*h+1]-mu)*rs*g1 + bb1, 0.f));
                }
            }
        }
    }
}

// ---------------- GRU gates + relu + LN -> packed Acat chunks 0-3 ----------
__global__ void gates_kernel(const float* __restrict__ x,
                             const float* __restrict__ lng,
                             const float* __restrict__ lnb,
                             uint32_t* __restrict__ Acat, int V) {
    int v = blockIdx.x * 8 + (threadIdx.x >> 5);
    if (v >= V) return;
    int lane = threadIdx.x & 31;
    const float* gi = &g_gi[(size_t)v * 384];
    const float* gh = &g_gh[(size_t)v * 384];
    float4 gir = *(const float4*)&gi[(lane << 2)];
    float4 giz = *(const float4*)&gi[128 + (lane << 2)];
    float4 gin = *(const float4*)&gi[256 + (lane << 2)];
    float4 ghr = *(const float4*)&gh[(lane << 2)];
    float4 ghz = *(const float4*)&gh[128 + (lane << 2)];
    float4 ghn = *(const float4*)&gh[256 + (lane << 2)];
    float4 xv  = *(const float4*)&x[(size_t)v * D + (lane << 2)];
    float h[4];
    #pragma unroll
    for (int i = 0; i < 4; i++) {
        float r = 1.f / (1.f + expf(-((&gir.x)[i] + (&ghr.x)[i])));
        float z = 1.f / (1.f + expf(-((&giz.x)[i] + (&ghz.x)[i])));
        float n = tanhf((&gin.x)[i] + r * (&ghn.x)[i]);
        h[i] = fmaxf((1.f - z) * n + z * (&xv.x)[i], 0.f);
    }
    float s = h[0] + h[1] + h[2] + h[3];
    #pragma unroll
    for (int m = 16; m; m >>= 1) s += __shfl_xor_sync(0xffffffffu, s, m);
    float mu = s * (1.f / 128.f), q = 0.f;
    #pragma unroll
    for (int i = 0; i < 4; i++) { float d0 = h[i] - mu; q = fmaf(d0, d0, q); }
    #pragma unroll
    for (int m = 16; m; m >>= 1) q += __shfl_xor_sync(0xffffffffu, q, m);
    float rstd = rsqrtf(q * (1.f / 128.f) + EPS);
    float4 gv = *(const float4*)&lng[lane << 2];
    float4 b2 = *(const float4*)&lnb[lane << 2];
    float o[4];
    o[0] = (h[0]-mu)*rstd*gv.x + b2.x;
    o[1] = (h[1]-mu)*rstd*gv.y + b2.y;
    o[2] = (h[2]-mu)*rstd*gv.z + b2.z;
    o[3] = (h[3]-mu)*rstd*gv.w + b2.w;
    // write fragment layout directly into Acat chunks 0-3 (KchTot = 8)
    int mb = v >> 6;
    int r = v & 63;
    int mt = r >> 4, rb = (r >> 3) & 1, lh = r & 7;
    #pragma unroll
    for (int pp = 0; pp < 2; pp++) {
        int kp = lane * 2 + pp;               // pair index 0..63
        int ll = kp & 3;
        int ri = (((kp >> 2) & 1) << 1) | rb;
        int ks = (kp >> 3) & 1;
        int c  = kp >> 4;
        int idx = mt * 256 + ks * 128 + ((lh << 2) | ll) * 4 + ri;
        uint32_t hi, lo;
        split_pair(o[2 * pp], o[2 * pp + 1], hi, lo);
        size_t base = ((size_t)(mb * 8 + c)) << 11;
        Acat[base + idx] = hi;
        Acat[base + 1024 + idx] = lo;
    }
}

// ---------------- host ----------------
extern "C" void kernel_launch(void* const* d_in, const int* in_sizes, int n_in,
                              void* d_out, int out_size) {
    const float* node   = (const float*)d_in[0];
    const int*   src    = (const int*)  d_in[1];
    const int*   dst    = (const int*)  d_in[2];
    const float* W_edge = (const float*)d_in[3];
    const float* b_edge = (const float*)d_in[4];
    const float* W_pn   = (const float*)d_in[5];
    const float* b_pn   = (const float*)d_in[6];
    const float* W_ih   = (const float*)d_in[7];
    const float* b_ih   = (const float*)d_in[8];
    const float* W_hh   = (const float*)d_in[9];
    const float* b_hh   = (const float*)d_in[10];
    const float* ln_g   = (const float*)d_in[11];
    const float* ln_b   = (const float*)d_in[12];
    const float* Wk1    = (const float*)d_in[13];
    const float* bk1    = (const float*)d_in[14];
    const float* lnk1_g = (const float*)d_in[15];
    const float* lnk1_b = (const float*)d_in[16];
    const float* Wk2    = (const float*)d_in[17];
    const float* bk2    = (const float*)d_in[18];
    const float* lnk2_g = (const float*)d_in[19];
    const float* lnk2_b = (const float*)d_in[20];
    const float* Wc     = (const float*)d_in[21];
    const float* bc     = (const float*)d_in[22];
    const float* lnc_g  = (const float*)d_in[23];
    const float* lnc_b  = (const float*)d_in[24];
    int V = in_sizes[0] / D;
    int E = in_sizes[1];
    float* out = (float*)d_out;

    float *p_asum, *p_lmax, *p_hv, *p_ctx, *p_kf, *p_gi, *p_gh;
    uint32_t *p_WpnS, *p_WihS, *p_WhhS, *p_WcS, *p_Wk2S;
    uint32_t *p_An, *p_Ac, *p_Aq;
    cudaGetSymbolAddress((void**)&p_asum, g_asum);
    cudaGetSymbolAddress((void**)&p_lmax, g_lmax);
    cudaGetSymbolAddress((void**)&p_hv,   g_hv);
    cudaGetSymbolAddress((void**)&p_ctx,  g_ctx);
    cudaGetSymbolAddress((void**)&p_kf,   g_kf);
    cudaGetSymbolAddress((void**)&p_gi,   g_gi);
    cudaGetSymbolAddress((void**)&p_gh,   g_gh);
    cudaGetSymbolAddress((void**)&p_WpnS, g_WpnS);
    cudaGetSymbolAddress((void**)&p_WihS, g_WihS);
    cudaGetSymbolAddress((void**)&p_WhhS, g_WhhS);
    cudaGetSymbolAddress((void**)&p_WcS,  g_WcS);
    cudaGetSymbolAddress((void**)&p_Wk2S, g_Wk2S);
    cudaGetSymbolAddress((void**)&p_An,   g_Anode);
    cudaGetSymbolAddress((void**)&p_Ac,   g_Actx);
    cudaGetSymbolAddress((void**)&p_Aq,   g_Acat);

    static bool attr_set = false;
    if (!attr_set) {
        cudaFuncSetAttribute(kron_mma, cudaFuncAttributeMaxDynamicSharedMemorySize, 62000);
        attr_set = true;
    }

    int NBv = (V + 63) / 64;

    // zero accumulators
    {
        int n4 = V * D / 4;
        zero_kernel<<<(n4 + 255) / 256, 256>>>((float4*)p_ctx, n4);
        zero_kernel<<<(n4 + 255) / 256, 256>>>((float4*)p_kf,  n4);
        n4 = V / 4;
        zero_kernel<<<(n4 + 255) / 256, 256>>>((float4*)p_asum, n4);
        zero_kernel<<<(n4 + 255) / 256, 256>>>((float4*)p_lmax, n4);
    }

    // pack weights (fp16 hi only)
    pack_w_frag<<<(64 * 128 + 255) / 256, 256>>>(W_pn, 128, 128, 0, p_WpnS);
    pack_w_frag<<<(64 * 384 + 255) / 256, 256>>>(W_ih, 128, 384, 1, p_WihS);
    pack_w_frag<<<(64 * 384 + 255) / 256, 256>>>(W_hh, 128, 384, 1, p_WhhS);
    pack_w_frag<<<(128 * 128 + 255) / 256, 256>>>(Wc, 256, 128, 0, p_WcS);
    pack_wk2<<<(200 * 128 + 255) / 256, 256>>>(Wk2, p_Wk2S);

    // pack node activations
    pack_act<<<NBv, 256>>>(node, 128, nullptr, 0, 0, p_An, V, 0, 4);

    npj_kernel<<<(V + 3) / 4, 128>>>(node, Wk1, bk1, lnk1_g, lnk1_b, V);
    logits_kernel<<<(E + 3) / 4, 128>>>(node, src, dst, W_edge, b_edge, E);
    expsum_kernel<<<(E + 255) / 256, 256>>>(dst, E);

    // hv = node @ W_pn + b_pn
    mma_gemm<<<dim3(NBv, 1), 256>>>(p_An, p_WpnS, 4, 128,
                                    b_pn, nullptr, nullptr, p_hv, V);

    // edge kron GEMM (1-pass) + LN + relu + atomic scatter to kf
    kron_mma<<<(E + 127) / 128, 256, 61440>>>(src, dst, p_Wk2S,
                                              bk2, lnk2_g, lnk2_b, E);

    // pack kf into Acat chunks 4-7 (after kron)
    pack_act<<<NBv, 256>>>(p_kf, 128, nullptr, 0, 0, p_Aq, V, 4, 8);

    // context scatter (float4 atomics)
    context_kernel<<<(E + 7) / 8, 256>>>(src, dst, E);

    // pack relu(ctx)
    pack_act<<<NBv, 256>>>(p_ctx, 128, nullptr, 0, 1, p_Ac, V, 0, 4);

    // gi = relu(ctx) @ W_ih^T + b_ih ; gh = node @ W_hh^T + b_hh
    mma_gemm<<<dim3(NBv, 3), 256>>>(p_Ac, p_WihS, 4, 384,
                                    b_ih, nullptr, nullptr, p_gi, V);
    mma_gemm<<<dim3(NBv, 3), 256>>>(p_An, p_WhhS, 4, 384,
                                    b_hh, nullptr, nullptr, p_gh, V);

    // gates -> packed Acat chunks 0-3 directly
    gates_kernel<<<(V + 7) / 8, 256>>>(node, ln_g, ln_b, p_Aq, V);

    // out = relu(LN(cat @ Wc + bc))
    mma_gemm<<<dim3(NBv, 1), 256>>>(p_Aq, p_WcS, 8, 128,
                                    bc, lnc_g, lnc_b, out, V);
}

// round 11
// speedup vs baseline: 1.3846x; 1.0290x over previous
#include <cuda_runtime.h>
#include <cuda_fp16.h>
#include <math.h>
#include <stdint.h>

#define D     128
#define KP    20
#define VMAX  100000
#define EMAX  400000
#define EPS   1e-5f
#define NBMAX 1563   // (VMAX+63)/64

// ---------------- scratch (device globals; no allocations) ----------------
__device__ float g_npj  [VMAX * KP];
__device__ float g_aexp [EMAX];
__device__ float g_asum [VMAX];
__device__ float g_hv   [VMAX * D];
__device__ float g_ctx  [VMAX * D];
__device__ float g_kf   [VMAX * D];
__device__ float g_gi   [VMAX * 3 * D];
__device__ float g_gh   [VMAX * 3 * D];

// fragment-ordered fp16 WEIGHT streams (hi only; per (ny,chunk): 2048 u32)
__device__ uint32_t g_WpnS[1 * 4 * 2048];
__device__ uint32_t g_WihS[3 * 4 * 2048];
__device__ uint32_t g_WhhS[3 * 4 * 2048];
__device__ uint32_t g_WcS [1 * 8 * 2048];
__device__ uint32_t g_Wk2S[5 * 5120];

// COMPACT fragment-ordered fp16 hi/lo ACTIVATION streams
// per (mblock64, chunk32): 2048 u32 = hi[0,1024) lo[1024,2048)
__device__ uint32_t g_Anode[(size_t)NBMAX * 4 * 2048];
__device__ uint32_t g_Actx [(size_t)NBMAX * 4 * 2048];
__device__ uint32_t g_Acat [(size_t)NBMAX * 8 * 2048];

// ---------------- fp16 RN hi/lo split ----------------
__device__ __forceinline__ void split_pair(float a0, float a1,
                                           uint32_t& hi, uint32_t& lo) {
    __half h0 = __float2half_rn(a0), h1 = __float2half_rn(a1);
    float l0 = a0 - __half2float(h0);
    float l1 = a1 - __half2float(h1);
    __half2 hp = __halves2half2(h0, h1);
    __half2 lp = __floats2half2_rn(l0, l1);
    hi = *(uint32_t*)&hp;
    lo = *(uint32_t*)&lp;
}
__device__ __forceinline__ uint32_t pack_hi16(float a0, float a1) {
    __half2 hp = __floats2half2_rn(a0, a1);
    return *(uint32_t*)&hp;
}

#define MMA_F16(c, A, B) asm volatile( \
    "mma.sync.aligned.m16n8k16.row.col.f32.f16.f16.f32 " \
    "{%0,%1,%2,%3}, {%4,%5,%6,%7}, {%8,%9}, {%0,%1,%2,%3};\n" \
    : "+f"(c[0]), "+f"(c[1]), "+f"(c[2]), "+f"(c[3]) \
    : "r"(A.x), "r"(A.y), "r"(A.z), "r"(A.w), "r"(B.x), "r"(B.y))

// ---------------- utility kernels ----------------
__global__ void zero_kernel(float4* p, int n4) {
    int i = blockIdx.x * blockDim.x + threadIdx.x;
    if (i < n4) p[i] = make_float4(0.f, 0.f, 0.f, 0.f);
}

// pack weights (fp16 hi only): per (ny, chunk): 2048 u32
__global__ void pack_w_frag(const float* __restrict__ W, int K, int Ntot,
                            int transp, uint32_t* __restrict__ out) {
    int idx = blockIdx.x * blockDim.x + threadIdx.x;
    int total = (K / 2) * Ntot;
    if (idx >= total) return;
    int kp = idx / Ntot, n = idx - kp * Ntot;
    int k0 = 2 * kp;
    float w0, w1;
    if (transp) { w0 = W[n * K + k0]; w1 = W[n * K + k0 + 1]; }
    else        { w0 = W[k0 * Ntot + n]; w1 = W[(k0 + 1) * Ntot + n]; }
    int c = kp >> 4, kpl = kp & 15;
    int ny = n >> 7, nl = n & 127;
    int bi = ((((nl >> 3) * 2 + (kpl >> 3)) * 32 + ((nl & 7) << 2) + (kpl & 3)) << 1)
             + ((kpl >> 2) & 1);
    size_t base = ((size_t)(ny * (K >> 5) + c)) << 11;
    out[base + bi] = pack_hi16(w0, w1);
}

// Wk2 [400][128] -> kron stream (fp16 hi only): per chunk(5): 5120 u32
__global__ void pack_wk2(const float* __restrict__ W, uint32_t* __restrict__ out) {
    int idx = blockIdx.x * blockDim.x + threadIdx.x;
    if (idx >= 200 * 128) return;
    int kp = idx >> 7, n = idx & 127;
    float w0 = W[(2 * kp) * 128 + n];
    float w1 = W[(2 * kp + 1) * 128 + n];
    int c = kp / 40, kpl = kp - c * 40;
    int bi = ((((n >> 3) * 5 + (kpl >> 3)) * 32 + ((n & 7) << 2) + (kpl & 3)) << 1)
             + ((kpl >> 2) & 1);
    out[c * 5120 + bi] = pack_hi16(w0, w1);
}

// COMPACT activation pack (fp16 hi/lo) with output chunk offset.
__global__ void pack_act(const float* __restrict__ X0, int K0,
                         const float* __restrict__ X1, int K1, int relu,
                         uint32_t* __restrict__ out, int V,
                         int coff, int KchTot) {
    int t = threadIdx.x;
    int mb = blockIdx.x;
    int K = K0 + K1;
    int Kch = K >> 5;
    for (int it = 0; it < Kch * 4; it++) {
        int c = it >> 2;
        int idx = ((it & 3) << 8) + t;       // 0..1023 within chunk
        int mt = idx >> 8;
        int ks = (idx >> 7) & 1;
        int ln = (idx >> 2) & 31;
        int ri = idx & 3;
        int row = mb * 64 + mt * 16 + (ri & 1) * 8 + (ln >> 2);
        if (row >= V) row = V - 1;
        int k = c * 32 + ks * 16 + ((ri >> 1) << 3) + ((ln & 3) << 1);
        float2 a;
        if (k < K0) a = *(const float2*)&X0[(size_t)row * K0 + k];
        else        a = *(const float2*)&X1[(size_t)row * K1 + (k - K0)];
        if (relu) { a.x = fmaxf(a.x, 0.f); a.y = fmaxf(a.y, 0.f); }
        uint32_t hi, lo;
        split_pair(a.x, a.y, hi, lo);
        size_t base = ((size_t)(mb * KchTot + coff + c)) << 11;
        out[base + idx] = hi;
        out[base + 1024 + idx] = lo;
    }
}

// ---------------- npj = relu(LN(x @ Wk1 + bk1)), [V,20] ----------------
__global__ void npj_kernel(const float* __restrict__ x,
                           const float* __restrict__ Wk1,
                           const float* __restrict__ bk1,
                           const float* __restrict__ g,
                           const float* __restrict__ b, int V) {
    __shared__ float xs[4][D];
    int warp = threadIdx.x >> 5, lane = threadIdx.x & 31;
    int v  = blockIdx.x * 4 + warp;
    int vc = v < V ? v : V - 1;
    *(float4*)&xs[warp][lane << 2] = *(const float4*)&x[vc * D + (lane << 2)];
    __syncwarp();
    float y = 0.f;
    if (lane < KP) {
        #pragma unroll 8
        for (int k = 0; k < D; k++) y = fmaf(xs[warp][k], Wk1[k * KP + lane], y);
        y += bk1[lane];
    }
    float s = (lane < KP) ? y : 0.f;
    #pragma unroll
    for (int m = 16; m; m >>= 1) s += __shfl_xor_sync(0xffffffffu, s, m);
    float mu = s * (1.f / KP);
    float dv = (lane < KP) ? (y - mu) * (y - mu) : 0.f;
    #pragma unroll
    for (int m = 16; m; m >>= 1) dv += __shfl_xor_sync(0xffffffffu, dv, m);
    float rstd = rsqrtf(dv * (1.f / KP) + EPS);
    if (v < V && lane < KP) {
        float val = (y - mu) * rstd * g[lane] + b[lane];
        g_npj[v * KP + lane] = fmaxf(val, 0.f);
    }
}

// ---- edge logits + exp + segment sum (no max pass; logits bounded small) ----
__global__ void logits_kernel(const float* __restrict__ x,
                              const int* __restrict__ src,
                              const int* __restrict__ dst,
                              const float* __restrict__ We,
                              const float* __restrict__ be, int E) {
    int e = blockIdx.x * 4 + (threadIdx.x >> 5);
    if (e >= E) return;
    int lane = threadIdx.x & 31;
    int sn = src[e], dn = dst[e];
    float4 xd = *(const float4*)&x[dn * D + (lane << 2)];
    float4 w1 = *(const float4*)&We[lane << 2];
    float4 xv = *(const float4*)&x[sn * D + (lane << 2)];
    float4 w2 = *(const float4*)&We[D + (lane << 2)];
    float p = xd.x * w1.x + xd.y * w1.y + xd.z * w1.z + xd.w * w1.w
            + xv.x * w2.x + xv.y * w2.y + xv.z * w2.z + xv.w * w2.w;
    #pragma unroll
    for (int m = 16; m; m >>= 1) p += __shfl_xor_sync(0xffffffffu, p, m);
    if (lane == 0) {
        float lg = fmaxf(p + be[0], 0.f);
        float a = expf(lg);          // softmax shift-invariant; lg in [0, ~8]
        g_aexp[e] = a;
        atomicAdd(&g_asum[dn], a);
    }
}

// ---------------- context scatter (vector atomics) ----------------
__global__ void context_kernel(const int* __restrict__ src,
                               const int* __restrict__ dst, int E) {
    int e = blockIdx.x * 8 + (threadIdx.x >> 5);
    if (e >= E) return;
    int lane = threadIdx.x & 31;
    int sn = src[e], dn = dst[e];
    float coef = g_aexp[e] / g_asum[dn];
    float4 h = *(const float4*)&g_hv[(size_t)sn * D + (lane << 2)];
    atomicAdd((float4*)&g_ctx[(size_t)dn * D + (lane << 2)],
              make_float4(h.x * coef, h.y * coef, h.z * coef, h.w * coef));
}

// =====================================================================
// Node GEMM, fp16; passes=2: (ah+al)·bh, passes=1: ah·bh only.
// Tile M=64 x N=128 (grid.y over N). 8 warps: wm=w&3, wn=w>>2.
// =====================================================================
__global__ __launch_bounds__(256)
void mma_gemm(const uint32_t* __restrict__ As, const uint32_t* __restrict__ Bs,
              int Kchunks, int Ntot, int passes,
              const float* __restrict__ bias,
              const float* __restrict__ lng, const float* __restrict__ lnb,
              float* __restrict__ out, int V) {
    __shared__ uint32_t sa[2048];   // hi [0,1024) lo [1024,2048)
    __shared__ uint32_t sb[2048];   // hi only
    __shared__ float red[2][64][2];

    int t = threadIdx.x;
    int lane = t & 31, w = t >> 5;
    int wm = w & 3, wn = w >> 2;
    int row0 = blockIdx.x * 64;
    int nb = blockIdx.y * 128;

    float acc[8][4];
    #pragma unroll
    for (int j = 0; j < 8; j++) { acc[j][0]=acc[j][1]=acc[j][2]=acc[j][3]=0.f; }

    const uint4* ag = (const uint4*)(As + (size_t)blockIdx.x * Kchunks * 2048);
    const uint4* bg = (const uint4*)(Bs + (size_t)blockIdx.y * Kchunks * 2048);

    if (passes == 2) {
        uint4 pa0, pa1, pb0, pb1;
        pa0 = ag[t]; pa1 = ag[t + 256];
        pb0 = bg[t]; pb1 = bg[t + 256];
        for (int c = 0; c < Kchunks; c++) {
            __syncthreads();
            ((uint4*)sa)[t] = pa0; ((uint4*)sa)[t + 256] = pa1;
            ((uint4*)sb)[t] = pb0; ((uint4*)sb)[t + 256] = pb1;
            __syncthreads();
            if (c + 1 < Kchunks) {
                const uint4* a4 = ag + (size_t)(c + 1) * 512;
                const uint4* b4 = bg + (size_t)(c + 1) * 512;
                pa0 = a4[t]; pa1 = a4[t + 256];
                pb0 = b4[t]; pb1 = b4[t + 256];
            }
            #pragma unroll
            for (int ks = 0; ks < 2; ks++) {
                uint4 ah = ((const uint4*)sa)[(wm * 2 + ks) * 32 + lane];
                uint4 al = *(const uint4*)&sa[1024 + (((wm * 2 + ks) * 32 + lane) << 2)];
                #pragma unroll
                for (int j = 0; j < 8; j++) {
                    int nt = wn * 8 + j;
                    uint2 bh = ((const uint2*)sb)[(nt * 2 + ks) * 32 + lane];
                    MMA_F16(acc[j], ah, bh);
                    MMA_F16(acc[j], al, bh);
                }
            }
        }
    } else {
        uint4 pa0, pb0, pb1;
        pa0 = ag[t];
        pb0 = bg[t]; pb1 = bg[t + 256];
        for (int c = 0; c < Kchunks; c++) {
            __syncthreads();
            ((uint4*)sa)[t] = pa0;
            ((uint4*)sb)[t] = pb0; ((uint4*)sb)[t + 256] = pb1;
            __syncthreads();
            if (c + 1 < Kchunks) {
                const uint4* a4 = ag + (size_t)(c + 1) * 512;
                const uint4* b4 = bg + (size_t)(c + 1) * 512;
                pa0 = a4[t];
                pb0 = b4[t]; pb1 = b4[t + 256];
            }
            #pragma unroll
            for (int ks = 0; ks < 2; ks++) {
                uint4 ah = ((const uint4*)sa)[(wm * 2 + ks) * 32 + lane];
                #pragma unroll
                for (int j = 0; j < 8; j++) {
                    int nt = wn * 8 + j;
                    uint2 bh = ((const uint2*)sb)[(nt * 2 + ks) * 32 + lane];
                    MMA_F16(acc[j], ah, bh);
                }
            }
        }
    }

    int rl = row0 + wm * 16 + (lane >> 2);
    int rh = rl + 8;
    #pragma unroll
    for (int j = 0; j < 8; j++) {
        int gc = nb + wn * 64 + j * 8 + ((lane & 3) << 1);
        float b0 = bias[gc], b1 = bias[gc + 1];
        acc[j][0] += b0; acc[j][1] += b1; acc[j][2] += b0; acc[j][3] += b1;
    }
    if (lng == nullptr) {
        #pragma unroll
        for (int j = 0; j < 8; j++) {
            int gc = nb + wn * 64 + j * 8 + ((lane & 3) << 1);
            if (rl < V) *(float2*)&out[(size_t)rl * Ntot + gc] = make_float2(acc[j][0], acc[j][1]);
            if (rh < V) *(float2*)&out[(size_t)rh * Ntot + gc] = make_float2(acc[j][2], acc[j][3]);
        }
    } else {
        float s_lo=0.f, q_lo=0.f, s_hi=0.f, q_hi=0.f;
        #pragma unroll
        for (int j = 0; j < 8; j++) {
            s_lo += acc[j][0] + acc[j][1];
            q_lo += acc[j][0]*acc[j][0] + acc[j][1]*acc[j][1];
            s_hi += acc[j][2] + acc[j][3];
            q_hi += acc[j][2]*acc[j][2] + acc[j][3]*acc[j][3];
        }
        #pragma unroll
        for (int m = 1; m <= 2; m <<= 1) {
            s_lo += __shfl_xor_sync(0xffffffffu, s_lo, m);
            q_lo += __shfl_xor_sync(0xffffffffu, q_lo, m);
            s_hi += __shfl_xor_sync(0xffffffffu, s_hi, m);
            q_hi += __shfl_xor_sync(0xffffffffu, q_hi, m);
        }
        int rloc = wm * 16 + (lane >> 2);
        if ((lane & 3) == 0) {
            red[wn][rloc][0] = s_lo;   red[wn][rloc][1] = q_lo;
            red[wn][rloc+8][0] = s_hi; red[wn][rloc+8][1] = q_hi;
        }
        __syncthreads();
        float ts_lo = s_lo + red[wn ^ 1][rloc][0];
        float tq_lo = q_lo + red[wn ^ 1][rloc][1];
        float ts_hi = s_hi + red[wn ^ 1][rloc + 8][0];
        float tq_hi = q_hi + red[wn ^ 1][rloc + 8][1];
        float mu_lo = ts_lo * (1.f/128.f);
        float mu_hi = ts_hi * (1.f/128.f);
        float rs_lo = rsqrtf(tq_lo * (1.f/128.f) - mu_lo*mu_lo + EPS);
        float rs_hi = rsqrtf(tq_hi * (1.f/128.f) - mu_hi*mu_hi + EPS);
        #pragma unroll
        for (int j = 0; j < 8; j++) {
            int gc = wn * 64 + j * 8 + ((lane & 3) << 1);
            float g0 = lng[gc], g1 = lng[gc+1];
            float bb0 = lnb[gc], bb1 = lnb[gc+1];
            if (rl < V) {
                float o0 = fmaxf((acc[j][0]-mu_lo)*rs_lo*g0 + bb0, 0.f);
                float o1 = fmaxf((acc[j][1]-mu_lo)*rs_lo*g1 + bb1, 0.f);
                *(float2*)&out[(size_t)rl * 128 + gc] = make_float2(o0, o1);
            }
            if (rh < V) {
                float o2 = fmaxf((acc[j][2]-mu_hi)*rs_hi*g0 + bb0, 0.f);
                float o3 = fmaxf((acc[j][3]-mu_hi)*rs_hi*g1 + bb1, 0.f);
                *(float2*)&out[(size_t)rh * 128 + gc] = make_float2(o2, o3);
            }
        }
    }
}

// =====================================================================
// Kron edge GEMM fp16 1-PASS: 128 edges x 128 outs, K=400 (5 chunks of 80),
// LN + relu + atomic scatter to g_kf[dst].
// =====================================================================
__global__ __launch_bounds__(256, 2)
void kron_mma(const int* __restrict__ src, const int* __restrict__ dst,
              const uint32_t* __restrict__ Wk2S,
              const float* __restrict__ bk2,
              const float* __restrict__ lng, const float* __restrict__ lnb,
              int E) {
    extern __shared__ uint32_t dsm[];
    uint32_t* sa = dsm;               // 5120 (hi only)
    uint32_t* sb = dsm + 5120;        // 5120 (hi only)
    float* Ss = (float*)(dsm + 10240);   // 128*20
    float* Ds = Ss + 2560;               // 128*20
    __shared__ int ssrc[128], sdst[128];
    __shared__ float red[2][128][2];

    int t = threadIdx.x;
    int lane = t & 31, w = t >> 5;
    int wm = w & 3, wn = w >> 2;
    int e0 = blockIdx.x * 128;

    if (t < 128) {
        int ee = e0 + t; if (ee >= E) ee = E - 1;
        ssrc[t] = src[ee];
        sdst[t] = dst[ee];
    }
    __syncthreads();
    for (int idx = t; idx < 640; idx += 256) {
        int e = idx / 5, q = idx - e * 5;
        ((float4*)Ss)[idx] = *(const float4*)&g_npj[ssrc[e] * KP + q * 4];
        ((float4*)Ds)[idx] = *(const float4*)&g_npj[sdst[e] * KP + q * 4];
    }

    float acc[2][8][4];
    #pragma unroll
    for (int r = 0; r < 2; r++)
        #pragma unroll
        for (int j = 0; j < 8; j++) { acc[r][j][0]=acc[r][j][1]=acc[r][j][2]=acc[r][j][3]=0.f; }

    int be = t >> 1, ih = t & 1;
    int amt = be >> 4;
    int ribase = (be >> 3) & 1;
    int alnb = (be & 7) << 2;

    for (int c = 0; c < 5; c++) {
        __syncthreads();
        {
            const float* ds = &Ds[be * 20];
            #pragma unroll
            for (int iv = 0; iv < 2; iv++) {
                int il = ih * 2 + iv;
                float sv = Ss[be * 20 + c * 4 + il];
                #pragma unroll
                for (int q = 0; q < 10; q++) {
                    float2 d = *(const float2*)&ds[2 * q];
                    float p0 = sv * d.x, p1 = sv * d.y;
                    int kp = il * 10 + q;
                    int ai = (((amt * 5 + (kp >> 3)) * 32 + alnb + (kp & 3)) << 2)
                             + ribase + (((kp >> 2) & 1) << 1);
                    sa[ai] = pack_hi16(p0, p1);
                }
            }
        }
        {
            const uint4* bsrc = (const uint4*)(Wk2S + c * 5120);
            #pragma unroll
            for (int i = 0; i < 5; i++)
                ((uint4*)sb)[t + (i << 8)] = bsrc[t + (i << 8)];
        }
        __syncthreads();
        #pragma unroll
        for (int ks = 0; ks < 5; ks++) {
            uint4 ah0 = ((const uint4*)sa)[((wm * 2 + 0) * 5 + ks) * 32 + lane];
            uint4 ah1 = ((const uint4*)sa)[((wm * 2 + 1) * 5 + ks) * 32 + lane];
            #pragma unroll
            for (int j = 0; j < 8; j++) {
                int nt = wn * 8 + j;
                uint2 bh = ((const uint2*)sb)[(nt * 5 + ks) * 32 + lane];
                MMA_F16(acc[0][j], ah0, bh);
                MMA_F16(acc[1][j], ah1, bh);
            }
        }
    }

    #pragma unroll
    for (int r = 0; r < 2; r++)
        #pragma unroll
        for (int j = 0; j < 8; j++) {
            int gc = wn * 64 + j * 8 + ((lane & 3) << 1);
            float b0 = bk2[gc], b1 = bk2[gc + 1];
            acc[r][j][0] += b0; acc[r][j][1] += b1;
            acc[r][j][2] += b0; acc[r][j][3] += b1;
        }
    float sum[2][2], sq[2][2];
    #pragma unroll
    for (int r = 0; r < 2; r++) {
        float s_lo=0.f, q_lo=0.f, s_hi=0.f, q_hi=0.f;
        #pragma unroll
        for (int j = 0; j < 8; j++) {
            s_lo += acc[r][j][0] + acc[r][j][1];
            q_lo += acc[r][j][0]*acc[r][j][0] + acc[r][j][1]*acc[r][j][1];
            s_hi += acc[r][j][2] + acc[r][j][3];
            q_hi += acc[r][j][2]*acc[r][j][2] + acc[r][j][3]*acc[r][j][3];
        }
        #pragma unroll
        for (int m = 1; m <= 2; m <<= 1) {
            s_lo += __shfl_xor_sync(0xffffffffu, s_lo, m);
            q_lo += __shfl_xor_sync(0xffffffffu, q_lo, m);
            s_hi += __shfl_xor_sync(0xffffffffu, s_hi, m);
            q_hi += __shfl_xor_sync(0xffffffffu, q_hi, m);
        }
        sum[r][0] = s_lo; sq[r][0] = q_lo;
        sum[r][1] = s_hi; sq[r][1] = q_hi;
        if ((lane & 3) == 0) {
            int rloc = wm * 32 + r * 16 + (lane >> 2);
            red[wn][rloc][0] = s_lo;     red[wn][rloc][1] = q_lo;
            red[wn][rloc + 8][0] = s_hi; red[wn][rloc + 8][1] = q_hi;
        }
    }
    __syncthreads();
    #pragma unroll
    for (int r = 0; r < 2; r++) {
        #pragma unroll
        for (int h = 0; h < 2; h++) {
            int rloc = wm * 32 + r * 16 + h * 8 + (lane >> 2);
            float ts = sum[r][h] + red[wn ^ 1][rloc][0];
            float tq = sq[r][h] + red[wn ^ 1][rloc][1];
            float mu = ts * (1.f / 128.f);
            float rs = rsqrtf(tq * (1.f / 128.f) - mu * mu + EPS);
            int ge = e0 + rloc;
            if (ge < E) {
                int dn = sdst[rloc];
                #pragma unroll
                for (int j = 0; j < 8; j++) {
                    int gc = wn * 64 + j * 8 + ((lane & 3) << 1);
                    float g0 = lng[gc], g1 = lng[gc + 1];
                    float bb0 = lnb[gc], bb1 = lnb[gc + 1];
                    float* p = &g_kf[(size_t)dn * 128 + gc];
                    atomicAdd(p,     fmaxf((acc[r][j][2*h  ]-mu)*rs*g0 + bb0, 0.f));
                    atomicAdd(p + 1, fmaxf((acc[r][j][2*h+1]-mu)*rs*g1 + bb1, 0.f));
                }
            }
        }
    }
}

// ---------------- GRU gates + relu + LN -> packed Acat chunks 0-3 ----------
__global__ void gates_kernel(const float* __restrict__ x,
                             const float* __restrict__ lng,
                             const float* __restrict__ lnb,
                             uint32_t* __restrict__ Acat, int V) {
    int v = blockIdx.x * 8 + (threadIdx.x >> 5);
    if (v >= V) return;
    int lane = threadIdx.x & 31;
    const float* gi = &g_gi[(size_t)v * 384];
    const float* gh = &g_gh[(size_t)v * 384];
    float4 gir = *(const float4*)&gi[(lane << 2)];
    float4 giz = *(const float4*)&gi[128 + (lane << 2)];
    float4 gin = *(const float4*)&gi[256 + (lane << 2)];
    float4 ghr = *(const float4*)&gh[(lane << 2)];
    float4 ghz = *(const float4*)&gh[128 + (lane << 2)];
    float4 ghn = *(const float4*)&gh[256 + (lane << 2)];
    float4 xv  = *(const float4*)&x[(size_t)v * D + (lane << 2)];
    float h[4];
    #pragma unroll
    for (int i = 0; i < 4; i++) {
        float r = 1.f / (1.f + expf(-((&gir.x)[i] + (&ghr.x)[i])));
        float z = 1.f / (1.f + expf(-((&giz.x)[i] + (&ghz.x)[i])));
        float n = tanhf((&gin.x)[i] + r * (&ghn.x)[i]);
        h[i] = fmaxf((1.f - z) * n + z * (&xv.x)[i], 0.f);
    }
    float s = h[0] + h[1] + h[2] + h[3];
    #pragma unroll
    for (int m = 16; m; m >>= 1) s += __shfl_xor_sync(0xffffffffu, s, m);
    float mu = s * (1.f / 128.f), q = 0.f;
    #pragma unroll
    for (int i = 0; i < 4; i++) { float d0 = h[i] - mu; q = fmaf(d0, d0, q); }
    #pragma unroll
    for (int m = 16; m; m >>= 1) q += __shfl_xor_sync(0xffffffffu, q, m);
    float rstd = rsqrtf(q * (1.f / 128.f) + EPS);
    float4 gv = *(const float4*)&lng[lane << 2];
    float4 b2 = *(const float4*)&lnb[lane << 2];
    float o[4];
    o[0] = (h[0]-mu)*rstd*gv.x + b2.x;
    o[1] = (h[1]-mu)*rstd*gv.y + b2.y;
    o[2] = (h[2]-mu)*rstd*gv.z + b2.z;
    o[3] = (h[3]-mu)*rstd*gv.w + b2.w;
    int mb = v >> 6;
    int r = v & 63;
    int mt = r >> 4, rb = (r >> 3) & 1, lh = r & 7;
    #pragma unroll
    for (int pp = 0; pp < 2; pp++) {
        int kp = lane * 2 + pp;
        int ll = kp & 3;
        int ri = (((kp >> 2) & 1) << 1) | rb;
        int ks = (kp >> 3) & 1;
        int c  = kp >> 4;
        int idx = mt * 256 + ks * 128 + ((lh << 2) | ll) * 4 + ri;
        uint32_t hi, lo;
        split_pair(o[2 * pp], o[2 * pp + 1], hi, lo);
        size_t base = ((size_t)(mb * 8 + c)) << 11;
        Acat[base + idx] = hi;
        Acat[base + 1024 + idx] = lo;
    }
}

// ---------------- host ----------------
extern "C" void kernel_launch(void* const* d_in, const int* in_sizes, int n_in,
                              void* d_out, int out_size) {
    const float* node   = (const float*)d_in[0];
    const int*   src    = (const int*)  d_in[1];
    const int*   dst    = (const int*)  d_in[2];
    const float* W_edge = (const float*)d_in[3];
    const float* b_edge = (const float*)d_in[4];
    const float* W_pn   = (const float*)d_in[5];
    const float* b_pn   = (const float*)d_in[6];
    const float* W_ih   = (const float*)d_in[7];
    const float* b_ih   = (const float*)d_in[8];
    const float* W_hh   = (const float*)d_in[9];
    const float* b_hh   = (const float*)d_in[10];
    const float* ln_g   = (const float*)d_in[11];
    const float* ln_b   = (const float*)d_in[12];
    const float* Wk1    = (const float*)d_in[13];
    const float* bk1    = (const float*)d_in[14];
    const float* lnk1_g = (const float*)d_in[15];
    const float* lnk1_b = (const float*)d_in[16];
    const float* Wk2    = (const float*)d_in[17];
    const float* bk2    = (const float*)d_in[18];
    const float* lnk2_g = (const float*)d_in[19];
    const float* lnk2_b = (const float*)d_in[20];
    const float* Wc     = (const float*)d_in[21];
    const float* bc     = (const float*)d_in[22];
    const float* lnc_g  = (const float*)d_in[23];
    const float* lnc_b  = (const float*)d_in[24];
    int V = in_sizes[0] / D;
    int E = in_sizes[1];
    float* out = (float*)d_out;

    float *p_asum, *p_hv, *p_ctx, *p_kf, *p_gi, *p_gh;
    uint32_t *p_WpnS, *p_WihS, *p_WhhS, *p_WcS, *p_Wk2S;
    uint32_t *p_An, *p_Ac, *p_Aq;
    cudaGetSymbolAddress((void**)&p_asum, g_asum);
    cudaGetSymbolAddress((void**)&p_hv,   g_hv);
    cudaGetSymbolAddress((void**)&p_ctx,  g_ctx);
    cudaGetSymbolAddress((void**)&p_kf,   g_kf);
    cudaGetSymbolAddress((void**)&p_gi,   g_gi);
    cudaGetSymbolAddress((void**)&p_gh,   g_gh);
    cudaGetSymbolAddress((void**)&p_WpnS, g_WpnS);
    cudaGetSymbolAddress((void**)&p_WihS, g_WihS);
    cudaGetSymbolAddress((void**)&p_WhhS, g_WhhS);
    cudaGetSymbolAddress((void**)&p_WcS,  g_WcS);
    cudaGetSymbolAddress((void**)&p_Wk2S, g_Wk2S);
    cudaGetSymbolAddress((void**)&p_An,   g_Anode);
    cudaGetSymbolAddress((void**)&p_Ac,   g_Actx);
    cudaGetSymbolAddress((void**)&p_Aq,   g_Acat);

    static bool attr_set = false;
    if (!attr_set) {
        cudaFuncSetAttribute(kron_mma, cudaFuncAttributeMaxDynamicSharedMemorySize, 62000);
        attr_set = true;
    }

    int NBv = (V + 63) / 64;

    // zero accumulators
    {
        int n4 = V * D / 4;
        zero_kernel<<<(n4 + 255) / 256, 256>>>((float4*)p_ctx, n4);
        zero_kernel<<<(n4 + 255) / 256, 256>>>((float4*)p_kf,  n4);
        n4 = V / 4;
        zero_kernel<<<(n4 + 255) / 256, 256>>>((float4*)p_asum, n4);
    }

    // pack weights (fp16 hi only)
    pack_w_frag<<<(64 * 128 + 255) / 256, 256>>>(W_pn, 128, 128, 0, p_WpnS);
    pack_w_frag<<<(64 * 384 + 255) / 256, 256>>>(W_ih, 128, 384, 1, p_WihS);
    pack_w_frag<<<(64 * 384 + 255) / 256, 256>>>(W_hh, 128, 384, 1, p_WhhS);
    pack_w_frag<<<(128 * 128 + 255) / 256, 256>>>(Wc, 256, 128, 0, p_WcS);
    pack_wk2<<<(200 * 128 + 255) / 256, 256>>>(Wk2, p_Wk2S);

    // pack node activations
    pack_act<<<NBv, 256>>>(node, 128, nullptr, 0, 0, p_An, V, 0, 4);

    npj_kernel<<<(V + 3) / 4, 128>>>(node, Wk1, bk1, lnk1_g, lnk1_b, V);
    logits_kernel<<<(E + 3) / 4, 128>>>(node, src, dst, W_edge, b_edge, E);

    // hv = node @ W_pn + b_pn (2-pass)
    mma_gemm<<<dim3(NBv, 1), 256>>>(p_An, p_WpnS, 4, 128, 2,
                                    b_pn, nullptr, nullptr, p_hv, V);

    // edge kron GEMM (1-pass) + LN + relu + atomic scatter to kf
    kron_mma<<<(E + 127) / 128, 256, 61440>>>(src, dst, p_Wk2S,
                                              bk2, lnk2_g, lnk2_b, E);

    // pack kf into Acat chunks 4-7
    pack_act<<<NBv, 256>>>(p_kf, 128, nullptr, 0, 0, p_Aq, V, 4, 8);

    // context scatter (float4 atomics)
    context_kernel<<<(E + 7) / 8, 256>>>(src, dst, E);

    // pack relu(ctx)
    pack_act<<<NBv, 256>>>(p_ctx, 128, nullptr, 0, 1, p_Ac, V, 0, 4);

    // gi = relu(ctx) @ W_ih^T + b_ih ; gh = node @ W_hh^T + b_hh (1-pass)
    mma_gemm<<<dim3(NBv, 3), 256>>>(p_Ac, p_WihS, 4, 384, 1,
                                    b_ih, nullptr, nullptr, p_gi, V);
    mma_gemm<<<dim3(NBv, 3), 256>>>(p_An, p_WhhS, 4, 384, 1,
                                    b_hh, nullptr, nullptr, p_gh, V);

    // gates -> packed Acat chunks 0-3 directly
    gates_kernel<<<(V + 7) / 8, 256>>>(node, ln_g, ln_b, p_Aq, V);

    // out = relu(LN(cat @ Wc + bc)) (2-pass)
    mma_gemm<<<dim3(NBv, 1), 256>>>(p_Aq, p_WcS, 8, 128, 2,
                                    bc, lnc_g, lnc_b, out, V);
}

// round 12
// speedup vs baseline: 1.5179x; 1.0963x over previous
#include <cuda_runtime.h>
#include <cuda_fp16.h>
#include <math.h>
#include <stdint.h>

#define D     128
#define KP    20
#define VMAX  100000
#define EMAX  400000
#define EPS   1e-5f
#define NBMAX 1563   // (VMAX+63)/64

// ---------------- scratch (device globals; no allocations) ----------------
__device__ float g_npj  [VMAX * KP];
__device__ float g_aexp [EMAX];
__device__ float g_asum [VMAX];
__device__ float2 g_uw  [VMAX];            // per-node edge-logit dots (u, w)
__device__ float g_hv   [VMAX * D];
__device__ float g_ctx  [VMAX * D];
__device__ float g_kf   [VMAX * D];
__device__ uint32_t g_giH[(size_t)VMAX * 192];   // fp16x2 gi (384 halves/row)
__device__ uint32_t g_ghH[(size_t)VMAX * 192];   // fp16x2 gh

// fragment-ordered fp16 WEIGHT streams (hi only; per (ny,chunk): 2048 u32)
__device__ uint32_t g_WpnS[1 * 4 * 2048];
__device__ uint32_t g_WihS[3 * 4 * 2048];
__device__ uint32_t g_WhhS[3 * 4 * 2048];
__device__ uint32_t g_WcS [1 * 8 * 2048];
__device__ uint32_t g_Wk2S[5 * 5120];

// COMPACT fragment-ordered fp16 hi/lo ACTIVATION streams
__device__ uint32_t g_Anode[(size_t)NBMAX * 4 * 2048];
__device__ uint32_t g_Actx [(size_t)NBMAX * 4 * 2048];
__device__ uint32_t g_Acat [(size_t)NBMAX * 8 * 2048];

// ---------------- fp16 RN hi/lo split ----------------
__device__ __forceinline__ void split_pair(float a0, float a1,
                                           uint32_t& hi, uint32_t& lo) {
    __half h0 = __float2half_rn(a0), h1 = __float2half_rn(a1);
    float l0 = a0 - __half2float(h0);
    float l1 = a1 - __half2float(h1);
    __half2 hp = __halves2half2(h0, h1);
    __half2 lp = __floats2half2_rn(l0, l1);
    hi = *(uint32_t*)&hp;
    lo = *(uint32_t*)&lp;
}
__device__ __forceinline__ uint32_t pack_hi16(float a0, float a1) {
    __half2 hp = __floats2half2_rn(a0, a1);
    return *(uint32_t*)&hp;
}

#define MMA_F16(c, A, B) asm volatile( \
    "mma.sync.aligned.m16n8k16.row.col.f32.f16.f16.f32 " \
    "{%0,%1,%2,%3}, {%4,%5,%6,%7}, {%8,%9}, {%0,%1,%2,%3};\n" \
    : "+f"(c[0]), "+f"(c[1]), "+f"(c[2]), "+f"(c[3]) \
    : "r"(A.x), "r"(A.y), "r"(A.z), "r"(A.w), "r"(B.x), "r"(B.y))

// ---------------- utility kernels ----------------
__global__ void zero_kernel(float4* p, int n4) {
    int i = blockIdx.x * blockDim.x + threadIdx.x;
    if (i < n4) p[i] = make_float4(0.f, 0.f, 0.f, 0.f);
}

__global__ void pack_w_frag(const float* __restrict__ W, int K, int Ntot,
                            int transp, uint32_t* __restrict__ out) {
    int idx = blockIdx.x * blockDim.x + threadIdx.x;
    int total = (K / 2) * Ntot;
    if (idx >= total) return;
    int kp = idx / Ntot, n = idx - kp * Ntot;
    int k0 = 2 * kp;
    float w0, w1;
    if (transp) { w0 = W[n * K + k0]; w1 = W[n * K + k0 + 1]; }
    else        { w0 = W[k0 * Ntot + n]; w1 = W[(k0 + 1) * Ntot + n]; }
    int c = kp >> 4, kpl = kp & 15;
    int ny = n >> 7, nl = n & 127;
    int bi = ((((nl >> 3) * 2 + (kpl >> 3)) * 32 + ((nl & 7) << 2) + (kpl & 3)) << 1)
             + ((kpl >> 2) & 1);
    size_t base = ((size_t)(ny * (K >> 5) + c)) << 11;
    out[base + bi] = pack_hi16(w0, w1);
}

__global__ void pack_wk2(const float* __restrict__ W, uint32_t* __restrict__ out) {
    int idx = blockIdx.x * blockDim.x + threadIdx.x;
    if (idx >= 200 * 128) return;
    int kp = idx >> 7, n = idx & 127;
    float w0 = W[(2 * kp) * 128 + n];
    float w1 = W[(2 * kp + 1) * 128 + n];
    int c = kp / 40, kpl = kp - c * 40;
    int bi = ((((n >> 3) * 5 + (kpl >> 3)) * 32 + ((n & 7) << 2) + (kpl & 3)) << 1)
             + ((kpl >> 2) & 1);
    out[c * 5120 + bi] = pack_hi16(w0, w1);
}

__global__ void pack_act(const float* __restrict__ X0, int K0,
                         const float* __restrict__ X1, int K1, int relu,
                         uint32_t* __restrict__ out, int V,
                         int coff, int KchTot) {
    int t = threadIdx.x;
    int mb = blockIdx.x;
    int K = K0 + K1;
    int Kch = K >> 5;
    for (int it = 0; it < Kch * 4; it++) {
        int c = it >> 2;
        int idx = ((it & 3) << 8) + t;
        int mt = idx >> 8;
        int ks = (idx >> 7) & 1;
        int ln = (idx >> 2) & 31;
        int ri = idx & 3;
        int row = mb * 64 + mt * 16 + (ri & 1) * 8 + (ln >> 2);
        if (row >= V) row = V - 1;
        int k = c * 32 + ks * 16 + ((ri >> 1) << 3) + ((ln & 3) << 1);
        float2 a;
        if (k < K0) a = *(const float2*)&X0[(size_t)row * K0 + k];
        else        a = *(const float2*)&X1[(size_t)row * K1 + (k - K0)];
        if (relu) { a.x = fmaxf(a.x, 0.f); a.y = fmaxf(a.y, 0.f); }
        uint32_t hi, lo;
        split_pair(a.x, a.y, hi, lo);
        size_t base = ((size_t)(mb * KchTot + coff + c)) << 11;
        out[base + idx] = hi;
        out[base + 1024 + idx] = lo;
    }
}

// ---------------- npj = relu(LN(x @ Wk1 + bk1)), [V,20] ----------------
__global__ void npj_kernel(const float* __restrict__ x,
                           const float* __restrict__ Wk1,
                           const float* __restrict__ bk1,
                           const float* __restrict__ g,
                           const float* __restrict__ b, int V) {
    __shared__ float xs[4][D];
    int warp = threadIdx.x >> 5, lane = threadIdx.x & 31;
    int v  = blockIdx.x * 4 + warp;
    int vc = v < V ? v : V - 1;
    *(float4*)&xs[warp][lane << 2] = *(const float4*)&x[vc * D + (lane << 2)];
    __syncwarp();
    float y = 0.f;
    if (lane < KP) {
        #pragma unroll 8
        for (int k = 0; k < D; k++) y = fmaf(xs[warp][k], Wk1[k * KP + lane], y);
        y += bk1[lane];
    }
    float s = (lane < KP) ? y : 0.f;
    #pragma unroll
    for (int m = 16; m; m >>= 1) s += __shfl_xor_sync(0xffffffffu, s, m);
    float mu = s * (1.f / KP);
    float dv = (lane < KP) ? (y - mu) * (y - mu) : 0.f;
    #pragma unroll
    for (int m = 16; m; m >>= 1) dv += __shfl_xor_sync(0xffffffffu, dv, m);
    float rstd = rsqrtf(dv * (1.f / KP) + EPS);
    if (v < V && lane < KP) {
        float val = (y - mu) * rstd * g[lane] + b[lane];
        g_npj[v * KP + lane] = fmaxf(val, 0.f);
    }
}

// ---- per-node edge-logit dots: u[v] = x[v]·We[0:128], w[v] = x[v]·We[128:256]
__global__ void edgedot_kernel(const float* __restrict__ x,
                               const float* __restrict__ We, int V) {
    int v = blockIdx.x * 8 + (threadIdx.x >> 5);
    if (v >= V) return;
    int lane = threadIdx.x & 31;
    float4 xv = *(const float4*)&x[(size_t)v * D + (lane << 2)];
    float4 w1 = *(const float4*)&We[lane << 2];
    float4 w2 = *(const float4*)&We[D + (lane << 2)];
    float u = xv.x * w1.x + xv.y * w1.y + xv.z * w1.z + xv.w * w1.w;
    float w = xv.x * w2.x + xv.y * w2.y + xv.z * w2.z + xv.w * w2.w;
    #pragma unroll
    for (int m = 16; m; m >>= 1) {
        u += __shfl_xor_sync(0xffffffffu, u, m);
        w += __shfl_xor_sync(0xffffffffu, w, m);
    }
    if (lane == 0) g_uw[v] = make_float2(u, w);
}

// ---- edge logits from scalars + exp + segment sum (no max pass) ----
__global__ void logits_kernel(const int* __restrict__ src,
                              const int* __restrict__ dst,
                              const float* __restrict__ be, int E) {
    int e = blockIdx.x * blockDim.x + threadIdx.x;
    if (e >= E) return;
    int sn = src[e], dn = dst[e];
    float2 ud = __ldg(&g_uw[dn]);
    float2 us = __ldg(&g_uw[sn]);
    float lg = fmaxf(ud.x + us.y + be[0], 0.f);
    float a = expf(lg);              // softmax shift-invariant; lg in [0, ~8]
    g_aexp[e] = a;
    atomicAdd(&g_asum[dn], a);
}

// ---------------- context scatter (vector atomics) ----------------
__global__ void context_kernel(const int* __restrict__ src,
                               const int* __restrict__ dst, int E) {
    int e = blockIdx.x * 8 + (threadIdx.x >> 5);
    if (e >= E) return;
    int lane = threadIdx.x & 31;
    int sn = src[e], dn = dst[e];
    float coef = g_aexp[e] / g_asum[dn];
    float4 h = *(const float4*)&g_hv[(size_t)sn * D + (lane << 2)];
    atomicAdd((float4*)&g_ctx[(size_t)dn * D + (lane << 2)],
              make_float4(h.x * coef, h.y * coef, h.z * coef, h.w * coef));
}

// =====================================================================
// Node GEMM, fp16; passes=2: (ah+al)·bh, passes=1: ah·bh.
// out_half=1: store packed __half2 (out cast to uint32_t*), plain store only.
// =====================================================================
__global__ __launch_bounds__(256)
void mma_gemm(const uint32_t* __restrict__ As, const uint32_t* __restrict__ Bs,
              int Kchunks, int Ntot, int passes, int out_half,
              const float* __restrict__ bias,
              const float* __restrict__ lng, const float* __restrict__ lnb,
              float* __restrict__ out, int V) {
    __shared__ uint32_t sa[2048];
    __shared__ uint32_t sb[2048];
    __shared__ float red[2][64][2];

    int t = threadIdx.x;
    int lane = t & 31, w = t >> 5;
    int wm = w & 3, wn = w >> 2;
    int row0 = blockIdx.x * 64;
    int nb = blockIdx.y * 128;

    float acc[8][4];
    #pragma unroll
    for (int j = 0; j < 8; j++) { acc[j][0]=acc[j][1]=acc[j][2]=acc[j][3]=0.f; }

    const uint4* ag = (const uint4*)(As + (size_t)blockIdx.x * Kchunks * 2048);
    const uint4* bg = (const uint4*)(Bs + (size_t)blockIdx.y * Kchunks * 2048);

    if (passes == 2) {
        uint4 pa0, pa1, pb0, pb1;
        pa0 = ag[t]; pa1 = ag[t + 256];
        pb0 = bg[t]; pb1 = bg[t + 256];
        for (int c = 0; c < Kchunks; c++) {
            __syncthreads();
            ((uint4*)sa)[t] = pa0; ((uint4*)sa)[t + 256] = pa1;
            ((uint4*)sb)[t] = pb0; ((uint4*)sb)[t + 256] = pb1;
            __syncthreads();
            if (c + 1 < Kchunks) {
                const uint4* a4 = ag + (size_t)(c + 1) * 512;
                const uint4* b4 = bg + (size_t)(c + 1) * 512;
                pa0 = a4[t]; pa1 = a4[t + 256];
                pb0 = b4[t]; pb1 = b4[t + 256];
            }
            #pragma unroll
            for (int ks = 0; ks < 2; ks++) {
                uint4 ah = ((const uint4*)sa)[(wm * 2 + ks) * 32 + lane];
                uint4 al = *(const uint4*)&sa[1024 + (((wm * 2 + ks) * 32 + lane) << 2)];
                #pragma unroll
                for (int j = 0; j < 8; j++) {
                    int nt = wn * 8 + j;
                    uint2 bh = ((const uint2*)sb)[(nt * 2 + ks) * 32 + lane];
                    MMA_F16(acc[j], ah, bh);
                    MMA_F16(acc[j], al, bh);
                }
            }
        }
    } else {
        uint4 pa0, pb0, pb1;
        pa0 = ag[t];
        pb0 = bg[t]; pb1 = bg[t + 256];
        for (int c = 0; c < Kchunks; c++) {
            __syncthreads();
            ((uint4*)sa)[t] = pa0;
            ((uint4*)sb)[t] = pb0; ((uint4*)sb)[t + 256] = pb1;
            __syncthreads();
            if (c + 1 < Kchunks) {
                const uint4* a4 = ag + (size_t)(c + 1) * 512;
                const uint4* b4 = bg + (size_t)(c + 1) * 512;
                pa0 = a4[t];
                pb0 = b4[t]; pb1 = b4[t + 256];
            }
            #pragma unroll
            for (int ks = 0; ks < 2; ks++) {
                uint4 ah = ((const uint4*)sa)[(wm * 2 + ks) * 32 + lane];
                #pragma unroll
                for (int j = 0; j < 8; j++) {
                    int nt = wn * 8 + j;
                    uint2 bh = ((const uint2*)sb)[(nt * 2 + ks) * 32 + lane];
                    MMA_F16(acc[j], ah, bh);
                }
            }
        }
    }

    int rl = row0 + wm * 16 + (lane >> 2);
    int rh = rl + 8;
    #pragma unroll
    for (int j = 0; j < 8; j++) {
        int gc = nb + wn * 64 + j * 8 + ((lane & 3) << 1);
        float b0 = bias[gc], b1 = bias[gc + 1];
        acc[j][0] += b0; acc[j][1] += b1; acc[j][2] += b0; acc[j][3] += b1;
    }
    if (lng == nullptr) {
        if (out_half) {
            uint32_t* oh = (uint32_t*)out;
            int ld2 = Ntot >> 1;
            #pragma unroll
            for (int j = 0; j < 8; j++) {
                int gc = nb + wn * 64 + j * 8 + ((lane & 3) << 1);
                if (rl < V) oh[(size_t)rl * ld2 + (gc >> 1)] = pack_hi16(acc[j][0], acc[j][1]);
                if (rh < V) oh[(size_t)rh * ld2 + (gc >> 1)] = pack_hi16(acc[j][2], acc[j][3]);
            }
        } else {
            #pragma unroll
            for (int j = 0; j < 8; j++) {
                int gc = nb + wn * 64 + j * 8 + ((lane & 3) << 1);
                if (rl < V) *(float2*)&out[(size_t)rl * Ntot + gc] = make_float2(acc[j][0], acc[j][1]);
                if (rh < V) *(float2*)&out[(size_t)rh * Ntot + gc] = make_float2(acc[j][2], acc[j][3]);
            }
        }
    } else {
        float s_lo=0.f, q_lo=0.f, s_hi=0.f, q_hi=0.f;
        #pragma unroll
        for (int j = 0; j < 8; j++) {
            s_lo += acc[j][0] + acc[j][1];
            q_lo += acc[j][0]*acc[j][0] + acc[j][1]*acc[j][1];
            s_hi += acc[j][2] + acc[j][3];
            q_hi += acc[j][2]*acc[j][2] + acc[j][3]*acc[j][3];
        }
        #pragma unroll
        for (int m = 1; m <= 2; m <<= 1) {
            s_lo += __shfl_xor_sync(0xffffffffu, s_lo, m);
            q_lo += __shfl_xor_sync(0xffffffffu, q_lo, m);
            s_hi += __shfl_xor_sync(0xffffffffu, s_hi, m);
            q_hi += __shfl_xor_sync(0xffffffffu, q_hi, m);
        }
        int rloc = wm * 16 + (lane >> 2);
        if ((lane & 3) == 0) {
            red[wn][rloc][0] = s_lo;   red[wn][rloc][1] = q_lo;
            red[wn][rloc+8][0] = s_hi; red[wn][rloc+8][1] = q_hi;
        }
        __syncthreads();
        float ts_lo = s_lo + red[wn ^ 1][rloc][0];
        float tq_lo = q_lo + red[wn ^ 1][rloc][1];
        float ts_hi = s_hi + red[wn ^ 1][rloc + 8][0];
        float tq_hi = q_hi + red[wn ^ 1][rloc + 8][1];
        float mu_lo = ts_lo * (1.f/128.f);
        float mu_hi = ts_hi * (1.f/128.f);
        float rs_lo = rsqrtf(tq_lo * (1.f/128.f) - mu_lo*mu_lo + EPS);
        float rs_hi = rsqrtf(tq_hi * (1.f/128.f) - mu_hi*mu_hi + EPS);
        #pragma unroll
        for (int j = 0; j < 8; j++) {
            int gc = wn * 64 + j * 8 + ((lane & 3) << 1);
            float g0 = lng[gc], g1 = lng[gc+1];
            float bb0 = lnb[gc], bb1 = lnb[gc+1];
            if (rl < V) {
                float o0 = fmaxf((acc[j][0]-mu_lo)*rs_lo*g0 + bb0, 0.f);
                float o1 = fmaxf((acc[j][1]-mu_lo)*rs_lo*g1 + bb1, 0.f);
                *(float2*)&out[(size_t)rl * 128 + gc] = make_float2(o0, o1);
            }
            if (rh < V) {
                float o2 = fmaxf((acc[j][2]-mu_hi)*rs_hi*g0 + bb0, 0.f);
                float o3 = fmaxf((acc[j][3]-mu_hi)*rs_hi*g1 + bb1, 0.f);
                *(float2*)&out[(size_t)rh * 128 + gc] = make_float2(o2, o3);
            }
        }
    }
}

// =====================================================================
// Kron edge GEMM fp16 1-PASS (unchanged from R11)
// =====================================================================
__global__ __launch_bounds__(256, 2)
void kron_mma(const int* __restrict__ src, const int* __restrict__ dst,
              const uint32_t* __restrict__ Wk2S,
              const float* __restrict__ bk2,
              const float* __restrict__ lng, const float* __restrict__ lnb,
              int E) {
    extern __shared__ uint32_t dsm[];
    uint32_t* sa = dsm;               // 5120
    uint32_t* sb = dsm + 5120;        // 5120
    float* Ss = (float*)(dsm + 10240);
    float* Ds = Ss + 2560;
    __shared__ int ssrc[128], sdst[128];
    __shared__ float red[2][128][2];

    int t = threadIdx.x;
    int lane = t & 31, w = t >> 5;
    int wm = w & 3, wn = w >> 2;
    int e0 = blockIdx.x * 128;

    if (t < 128) {
        int ee = e0 + t; if (ee >= E) ee = E - 1;
        ssrc[t] = src[ee];
        sdst[t] = dst[ee];
    }
    __syncthreads();
    for (int idx = t; idx < 640; idx += 256) {
        int e = idx / 5, q = idx - e * 5;
        ((float4*)Ss)[idx] = *(const float4*)&g_npj[ssrc[e] * KP + q * 4];
        ((float4*)Ds)[idx] = *(const float4*)&g_npj[sdst[e] * KP + q * 4];
    }

    float acc[2][8][4];
    #pragma unroll
    for (int r = 0; r < 2; r++)
        #pragma unroll
        for (int j = 0; j < 8; j++) { acc[r][j][0]=acc[r][j][1]=acc[r][j][2]=acc[r][j][3]=0.f; }

    int be = t >> 1, ih = t & 1;
    int amt = be >> 4;
    int ribase = (be >> 3) & 1;
    int alnb = (be & 7) << 2;

    for (int c = 0; c < 5; c++) {
        __syncthreads();
        {
            const float* ds = &Ds[be * 20];
            #pragma unroll
            for (int iv = 0; iv < 2; iv++) {
                int il = ih * 2 + iv;
                float sv = Ss[be * 20 + c * 4 + il];
                #pragma unroll
                for (int q = 0; q < 10; q++) {
                    float2 d = *(const float2*)&ds[2 * q];
                    float p0 = sv * d.x, p1 = sv * d.y;
                    int kp = il * 10 + q;
                    int ai = (((amt * 5 + (kp >> 3)) * 32 + alnb + (kp & 3)) << 2)
                             + ribase + (((kp >> 2) & 1) << 1);
                    sa[ai] = pack_hi16(p0, p1);
                }
            }
        }
        {
            const uint4* bsrc = (const uint4*)(Wk2S + c * 5120);
            #pragma unroll
            for (int i = 0; i < 5; i++)
                ((uint4*)sb)[t + (i << 8)] = bsrc[t + (i << 8)];
        }
        __syncthreads();
        #pragma unroll
        for (int ks = 0; ks < 5; ks++) {
            uint4 ah0 = ((const uint4*)sa)[((wm * 2 + 0) * 5 + ks) * 32 + lane];
            uint4 ah1 = ((const uint4*)sa)[((wm * 2 + 1) * 5 + ks) * 32 + lane];
            #pragma unroll
            for (int j = 0; j < 8; j++) {
                int nt = wn * 8 + j;
                uint2 bh = ((const uint2*)sb)[(nt * 5 + ks) * 32 + lane];
                MMA_F16(acc[0][j], ah0, bh);
                MMA_F16(acc[1][j], ah1, bh);
            }
        }
    }

    #pragma unroll
    for (int r = 0; r < 2; r++)
        #pragma unroll
        for (int j = 0; j < 8; j++) {
            int gc = wn * 64 + j * 8 + ((lane & 3) << 1);
            float b0 = bk2[gc], b1 = bk2[gc + 1];
            acc[r][j][0] += b0; acc[r][j][1] += b1;
            acc[r][j][2] += b0; acc[r][j][3] += b1;
        }
    float sum[2][2], sq[2][2];
    #pragma unroll
    for (int r = 0; r < 2; r++) {
        float s_lo=0.f, q_lo=0.f, s_hi=0.f, q_hi=0.f;
        #pragma unroll
        for (int j = 0; j < 8; j++) {
            s_lo += acc[r][j][0] + acc[r][j][1];
            q_lo += acc[r][j][0]*acc[r][j][0] + acc[r][j][1]*acc[r][j][1];
            s_hi += acc[r][j][2] + acc[r][j][3];
            q_hi += acc[r][j][2]*acc[r][j][2] + acc[r][j][3]*acc[r][j][3];
        }
        #pragma unroll
        for (int m = 1; m <= 2; m <<= 1) {
            s_lo += __shfl_xor_sync(0xffffffffu, s_lo, m);
            q_lo += __shfl_xor_sync(0xffffffffu, q_lo, m);
            s_hi += __shfl_xor_sync(0xffffffffu, s_hi, m);
            q_hi += __shfl_xor_sync(0xffffffffu, q_hi, m);
        }
        sum[r][0] = s_lo; sq[r][0] = q_lo;
        sum[r][1] = s_hi; sq[r][1] = q_hi;
        if ((lane & 3) == 0) {
            int rloc = wm * 32 + r * 16 + (lane >> 2);
            red[wn][rloc][0] = s_lo;     red[wn][rloc][1] = q_lo;
            red[wn][rloc + 8][0] = s_hi; red[wn][rloc + 8][1] = q_hi;
        }
    }
    __syncthreads();
    #pragma unroll
    for (int r = 0; r < 2; r++) {
        #pragma unroll
        for (int h = 0; h < 2; h++) {
            int rloc = wm * 32 + r * 16 + h * 8 + (lane >> 2);
            float ts = sum[r][h] + red[wn ^ 1][rloc][0];
            float tq = sq[r][h] + red[wn ^ 1][rloc][1];
            float mu = ts * (1.f / 128.f);
            float rs = rsqrtf(tq * (1.f / 128.f) - mu * mu + EPS);
            int ge = e0 + rloc;
            if (ge < E) {
                int dn = sdst[rloc];
                #pragma unroll
                for (int j = 0; j < 8; j++) {
                    int gc = wn * 64 + j * 8 + ((lane & 3) << 1);
                    float g0 = lng[gc], g1 = lng[gc + 1];
                    float bb0 = lnb[gc], bb1 = lnb[gc + 1];
                    float* p = &g_kf[(size_t)dn * 128 + gc];
                    atomicAdd(p,     fmaxf((acc[r][j][2*h  ]-mu)*rs*g0 + bb0, 0.f));
                    atomicAdd(p + 1, fmaxf((acc[r][j][2*h+1]-mu)*rs*g1 + bb1, 0.f));
                }
            }
        }
    }
}

// ---- GRU gates (fp16 gi/gh) + relu + LN -> Acat chunks 0-3; kf -> 4-7 ----
__global__ void gates_kernel(const float* __restrict__ x,
                             const float* __restrict__ lng,
                             const float* __restrict__ lnb,
                             uint32_t* __restrict__ Acat, int V) {
    int v = blockIdx.x * 8 + (threadIdx.x >> 5);
    if (v >= V) return;
    int lane = threadIdx.x & 31;
    const uint32_t* giH = &g_giH[(size_t)v * 192];
    const uint32_t* ghH = &g_ghH[(size_t)v * 192];
    float h[4];
    {
        uint2 uir = *(const uint2*)&giH[lane * 2];
        uint2 uiz = *(const uint2*)&giH[64 + lane * 2];
        uint2 uin = *(const uint2*)&giH[128 + lane * 2];
        uint2 uhr = *(const uint2*)&ghH[lane * 2];
        uint2 uhz = *(const uint2*)&ghH[64 + lane * 2];
        uint2 uhn = *(const uint2*)&ghH[128 + lane * 2];
        float4 xv = *(const float4*)&x[(size_t)v * D + (lane << 2)];
        #pragma unroll
        for (int half2i = 0; half2i < 2; half2i++) {
            float2 ir = __half22float2(*(__half2*)((half2i == 0) ? &uir.x : &uir.y));
            float2 iz = __half22float2(*(__half2*)((half2i == 0) ? &uiz.x : &uiz.y));
            float2 in_ = __half22float2(*(__half2*)((half2i == 0) ? &uin.x : &uin.y));
            float2 hr = __half22float2(*(__half2*)((half2i == 0) ? &uhr.x : &uhr.y));
            float2 hz = __half22float2(*(__half2*)((half2i == 0) ? &uhz.x : &uhz.y));
            float2 hn = __half22float2(*(__half2*)((half2i == 0) ? &uhn.x : &uhn.y));
            #pragma unroll
            for (int q = 0; q < 2; q++) {
                int i = half2i * 2 + q;
                float gir = (q == 0) ? ir.x : ir.y;
                float giz = (q == 0) ? iz.x : iz.y;
                float gin = (q == 0) ? in_.x : in_.y;
                float ghr = (q == 0) ? hr.x : hr.y;
                float ghz = (q == 0) ? hz.x : hz.y;
                float ghn = (q == 0) ? hn.x : hn.y;
                float r = 1.f / (1.f + expf(-(gir + ghr)));
                float z = 1.f / (1.f + expf(-(giz + ghz)));
                float n = tanhf(gin + r * ghn);
                h[i] = fmaxf((1.f - z) * n + z * (&xv.x)[i], 0.f);
            }
        }
    }
    float s = h[0] + h[1] + h[2] + h[3];
    #pragma unroll
    for (int m = 16; m; m >>= 1) s += __shfl_xor_sync(0xffffffffu, s, m);
    float mu = s * (1.f / 128.f), q = 0.f;
    #pragma unroll
    for (int i = 0; i < 4; i++) { float d0 = h[i] - mu; q = fmaf(d0, d0, q); }
    #pragma unroll
    for (int m = 16; m; m >>= 1) q += __shfl_xor_sync(0xffffffffu, q, m);
    float rstd = rsqrtf(q * (1.f / 128.f) + EPS);
    float4 gv = *(const float4*)&lng[lane << 2];
    float4 b2 = *(const float4*)&lnb[lane << 2];
    float o[4];
    o[0] = (h[0]-mu)*rstd*gv.x + b2.x;
    o[1] = (h[1]-mu)*rstd*gv.y + b2.y;
    o[2] = (h[2]-mu)*rstd*gv.z + b2.z;
    o[3] = (h[3]-mu)*rstd*gv.w + b2.w;
    float4 kv = *(const float4*)&g_kf[(size_t)v * D + (lane << 2)];
    int mb = v >> 6;
    int r = v & 63;
    int mt = r >> 4, rb = (r >> 3) & 1, lh = r & 7;
    #pragma unroll
    for (int pp = 0; pp < 2; pp++) {
        int kp = lane * 2 + pp;
        int ll = kp & 3;
        int ri = (((kp >> 2) & 1) << 1) | rb;
        int ks = (kp >> 3) & 1;
        int c  = kp >> 4;
        int idx = mt * 256 + ks * 128 + ((lh << 2) | ll) * 4 + ri;
        uint32_t hi, lo;
        // gru half -> chunks 0-3
        split_pair(o[2 * pp], o[2 * pp + 1], hi, lo);
        size_t base = ((size_t)(mb * 8 + c)) << 11;
        Acat[base + idx] = hi;
        Acat[base + 1024 + idx] = lo;
        // kf half -> chunks 4-7
        split_pair((&kv.x)[2 * pp], (&kv.x)[2 * pp + 1], hi, lo);
        base = ((size_t)(mb * 8 + 4 + c)) << 11;
        Acat[base + idx] = hi;
        Acat[base + 1024 + idx] = lo;
    }
}

// ---------------- host ----------------
extern "C" void kernel_launch(void* const* d_in, const int* in_sizes, int n_in,
                              void* d_out, int out_size) {
    const float* node   = (const float*)d_in[0];
    const int*   src    = (const int*)  d_in[1];
    const int*   dst    = (const int*)  d_in[2];
    const float* W_edge = (const float*)d_in[3];
    const float* b_edge = (const float*)d_in[4];
    const float* W_pn   = (const float*)d_in[5];
    const float* b_pn   = (const float*)d_in[6];
    const float* W_ih   = (const float*)d_in[7];
    const float* b_ih   = (const float*)d_in[8];
    const float* W_hh   = (const float*)d_in[9];
    const float* b_hh   = (const float*)d_in[10];
    const float* ln_g   = (const float*)d_in[11];
    const float* ln_b   = (const float*)d_in[12];
    const float* Wk1    = (const float*)d_in[13];
    const float* bk1    = (const float*)d_in[14];
    const float* lnk1_g = (const float*)d_in[15];
    const float* lnk1_b = (const float*)d_in[16];
    const float* Wk2    = (const float*)d_in[17];
    const float* bk2    = (const float*)d_in[18];
    const float* lnk2_g = (const float*)d_in[19];
    const float* lnk2_b = (const float*)d_in[20];
    const float* Wc     = (const float*)d_in[21];
    const float* bc     = (const float*)d_in[22];
    const float* lnc_g  = (const float*)d_in[23];
    const float* lnc_b  = (const float*)d_in[24];
    int V = in_sizes[0] / D;
    int E = in_sizes[1];
    float* out = (float*)d_out;

    float *p_asum, *p_hv, *p_ctx, *p_kf;
    uint32_t *p_giH, *p_ghH;
    uint32_t *p_WpnS, *p_WihS, *p_WhhS, *p_WcS, *p_Wk2S;
    uint32_t *p_An, *p_Ac, *p_Aq;
    cudaGetSymbolAddress((void**)&p_asum, g_asum);
    cudaGetSymbolAddress((void**)&p_hv,   g_hv);
    cudaGetSymbolAddress((void**)&p_ctx,  g_ctx);
    cudaGetSymbolAddress((void**)&p_kf,   g_kf);
    cudaGetSymbolAddress((void**)&p_giH,  g_giH);
    cudaGetSymbolAddress((void**)&p_ghH,  g_ghH);
    cudaGetSymbolAddress((void**)&p_WpnS, g_WpnS);
    cudaGetSymbolAddress((void**)&p_WihS, g_WihS);
    cudaGetSymbolAddress((void**)&p_WhhS, g_WhhS);
    cudaGetSymbolAddress((void**)&p_WcS,  g_WcS);
    cudaGetSymbolAddress((void**)&p_Wk2S, g_Wk2S);
    cudaGetSymbolAddress((void**)&p_An,   g_Anode);
    cudaGetSymbolAddress((void**)&p_Ac,   g_Actx);
    cudaGetSymbolAddress((void**)&p_Aq,   g_Acat);

    static bool attr_set = false;
    if (!attr_set) {
        cudaFuncSetAttribute(kron_mma, cudaFuncAttributeMaxDynamicSharedMemorySize, 62000);
        attr_set = true;
    }

    int NBv = (V + 63) / 64;

    // zero accumulators
    {
        int n4 = V * D / 4;
        zero_kernel<<<(n4 + 255) / 256, 256>>>((float4*)p_ctx, n4);
        zero_kernel<<<(n4 + 255) / 256, 256>>>((float4*)p_kf,  n4);
        n4 = V / 4;
        zero_kernel<<<(n4 + 255) / 256, 256>>>((float4*)p_asum, n4);
    }

    // pack weights (fp16 hi only)
    pack_w_frag<<<(64 * 128 + 255) / 256, 256>>>(W_pn, 128, 128, 0, p_WpnS);
    pack_w_frag<<<(64 * 384 + 255) / 256, 256>>>(W_ih, 128, 384, 1, p_WihS);
    pack_w_frag<<<(64 * 384 + 255) / 256, 256>>>(W_hh, 128, 384, 1, p_WhhS);
    pack_w_frag<<<(128 * 128 + 255) / 256, 256>>>(Wc, 256, 128, 0, p_WcS);
    pack_wk2<<<(200 * 128 + 255) / 256, 256>>>(Wk2, p_Wk2S);

    // pack node activations
    pack_act<<<NBv, 256>>>(node, 128, nullptr, 0, 0, p_An, V, 0, 4);

    npj_kernel<<<(V + 3) / 4, 128>>>(node, Wk1, bk1, lnk1_g, lnk1_b, V);
    edgedot_kernel<<<(V + 7) / 8, 256>>>(node, W_edge, V);
    logits_kernel<<<(E + 255) / 256, 256>>>(src, dst, b_edge, E);

    // hv = node @ W_pn + b_pn (2-pass)
    mma_gemm<<<dim3(NBv, 1), 256>>>(p_An, p_WpnS, 4, 128, 2, 0,
                                    b_pn, nullptr, nullptr, p_hv, V);

    // edge kron GEMM (1-pass) + LN + relu + atomic scatter to kf
    kron_mma<<<(E + 127) / 128, 256, 61440>>>(src, dst, p_Wk2S,
                                              bk2, lnk2_g, lnk2_b, E);

    // context scatter (float4 atomics)
    context_kernel<<<(E + 7) / 8, 256>>>(src, dst, E);

    // pack relu(ctx)
    pack_act<<<NBv, 256>>>(p_ctx, 128, nullptr, 0, 1, p_Ac, V, 0, 4);

    // gi / gh (1-pass, fp16 output)
    mma_gemm<<<dim3(NBv, 3), 256>>>(p_Ac, p_WihS, 4, 384, 1, 1,
                                    b_ih, nullptr, nullptr, (float*)p_giH, V);
    mma_gemm<<<dim3(NBv, 3), 256>>>(p_An, p_WhhS, 4, 384, 1, 1,
                                    b_hh, nullptr, nullptr, (float*)p_ghH, V);

    // gates -> Acat chunks 0-3; kf -> chunks 4-7
    gates_kernel<<<(V + 7) / 8, 256>>>(node, ln_g, ln_b, p_Aq, V);

    // out = relu(LN(cat @ Wc + bc)) (2-pass)
    mma_gemm<<<dim3(NBv, 1), 256>>>(p_Aq, p_WcS, 8, 128, 2, 0,
                                    bc, lnc_g, lnc_b, out, V);
}

// round 13
// speedup vs baseline: 1.5618x; 1.0289x over previous
#include <cuda_runtime.h>
#include <cuda_fp16.h>
#include <math.h>
#include <stdint.h>

#define D     128
#define KP    20
#define VMAX  100000
#define EMAX  400000
#define EPS   1e-5f
#define NBMAX 1563   // (VMAX+63)/64

// ---------------- scratch (device globals; no allocations) ----------------
__device__ __half g_npjH[VMAX * KP];             // fp16 npj
__device__ float g_aexp [EMAX];
__device__ float g_asum [VMAX];
__device__ float2 g_uw  [VMAX];                  // per-node edge-logit dots
__device__ uint32_t g_hvH[(size_t)VMAX * 64];    // fp16x2 hv (128 halves/row)
__device__ float g_ctx  [VMAX * D];
__device__ float g_kf   [VMAX * D];
__device__ uint32_t g_giH[(size_t)VMAX * 192];   // fp16x2 gi
__device__ uint32_t g_ghH[(size_t)VMAX * 192];   // fp16x2 gh

// fragment-ordered fp16 WEIGHT streams (hi only)
__device__ uint32_t g_WpnS[1 * 4 * 2048];
__device__ uint32_t g_WihS[3 * 4 * 2048];
__device__ uint32_t g_WhhS[3 * 4 * 2048];
__device__ uint32_t g_WcS [1 * 8 * 2048];
__device__ uint32_t g_Wk2S[5 * 5120];

// COMPACT fragment-ordered fp16 hi/lo ACTIVATION streams
__device__ uint32_t g_Anode[(size_t)NBMAX * 4 * 2048];
__device__ uint32_t g_Actx [(size_t)NBMAX * 4 * 2048];
__device__ uint32_t g_Acat [(size_t)NBMAX * 8 * 2048];

// ---------------- fp16 RN hi/lo split ----------------
__device__ __forceinline__ void split_pair(float a0, float a1,
                                           uint32_t& hi, uint32_t& lo) {
    __half h0 = __float2half_rn(a0), h1 = __float2half_rn(a1);
    float l0 = a0 - __half2float(h0);
    float l1 = a1 - __half2float(h1);
    __half2 hp = __halves2half2(h0, h1);
    __half2 lp = __floats2half2_rn(l0, l1);
    hi = *(uint32_t*)&hp;
    lo = *(uint32_t*)&lp;
}
__device__ __forceinline__ uint32_t pack_hi16(float a0, float a1) {
    __half2 hp = __floats2half2_rn(a0, a1);
    return *(uint32_t*)&hp;
}

#define MMA_F16(c, A, B) asm volatile( \
    "mma.sync.aligned.m16n8k16.row.col.f32.f16.f16.f32 " \
    "{%0,%1,%2,%3}, {%4,%5,%6,%7}, {%8,%9}, {%0,%1,%2,%3};\n" \
    : "+f"(c[0]), "+f"(c[1]), "+f"(c[2]), "+f"(c[3]) \
    : "r"(A.x), "r"(A.y), "r"(A.z), "r"(A.w), "r"(B.x), "r"(B.y))

// ---------------- utility kernels ----------------
__global__ void zero_kernel(float4* p, int n4) {
    int i = blockIdx.x * blockDim.x + threadIdx.x;
    if (i < n4) p[i] = make_float4(0.f, 0.f, 0.f, 0.f);
}

__global__ void pack_w_frag(const float* __restrict__ W, int K, int Ntot,
                            int transp, uint32_t* __restrict__ out) {
    int idx = blockIdx.x * blockDim.x + threadIdx.x;
    int total = (K / 2) * Ntot;
    if (idx >= total) return;
    int kp = idx / Ntot, n = idx - kp * Ntot;
    int k0 = 2 * kp;
    float w0, w1;
    if (transp) { w0 = W[n * K + k0]; w1 = W[n * K + k0 + 1]; }
    else        { w0 = W[k0 * Ntot + n]; w1 = W[(k0 + 1) * Ntot + n]; }
    int c = kp >> 4, kpl = kp & 15;
    int ny = n >> 7, nl = n & 127;
    int bi = ((((nl >> 3) * 2 + (kpl >> 3)) * 32 + ((nl & 7) << 2) + (kpl & 3)) << 1)
             + ((kpl >> 2) & 1);
    size_t base = ((size_t)(ny * (K >> 5) + c)) << 11;
    out[base + bi] = pack_hi16(w0, w1);
}

__global__ void pack_wk2(const float* __restrict__ W, uint32_t* __restrict__ out) {
    int idx = blockIdx.x * blockDim.x + threadIdx.x;
    if (idx >= 200 * 128) return;
    int kp = idx >> 7, n = idx & 127;
    float w0 = W[(2 * kp) * 128 + n];
    float w1 = W[(2 * kp + 1) * 128 + n];
    int c = kp / 40, kpl = kp - c * 40;
    int bi = ((((n >> 3) * 5 + (kpl >> 3)) * 32 + ((n & 7) << 2) + (kpl & 3)) << 1)
             + ((kpl >> 2) & 1);
    out[c * 5120 + bi] = pack_hi16(w0, w1);
}

__global__ void pack_act(const float* __restrict__ X0, int K0,
                         const float* __restrict__ X1, int K1, int relu,
                         uint32_t* __restrict__ out, int V,
                         int coff, int KchTot) {
    int t = threadIdx.x;
    int mb = blockIdx.x;
    int K = K0 + K1;
    int Kch = K >> 5;
    for (int it = 0; it < Kch * 4; it++) {
        int c = it >> 2;
        int idx = ((it & 3) << 8) + t;
        int mt = idx >> 8;
        int ks = (idx >> 7) & 1;
        int ln = (idx >> 2) & 31;
        int ri = idx & 3;
        int row = mb * 64 + mt * 16 + (ri & 1) * 8 + (ln >> 2);
        if (row >= V) row = V - 1;
        int k = c * 32 + ks * 16 + ((ri >> 1) << 3) + ((ln & 3) << 1);
        float2 a;
        if (k < K0) a = *(const float2*)&X0[(size_t)row * K0 + k];
        else        a = *(const float2*)&X1[(size_t)row * K1 + (k - K0)];
        if (relu) { a.x = fmaxf(a.x, 0.f); a.y = fmaxf(a.y, 0.f); }
        uint32_t hi, lo;
        split_pair(a.x, a.y, hi, lo);
        size_t base = ((size_t)(mb * KchTot + coff + c)) << 11;
        out[base + idx] = hi;
        out[base + 1024 + idx] = lo;
    }
}

// ---------------- npj = relu(LN(x @ Wk1 + bk1)) -> fp16, [V,20] ----------------
__global__ void npj_kernel(const float* __restrict__ x,
                           const float* __restrict__ Wk1,
                           const float* __restrict__ bk1,
                           const float* __restrict__ g,
                           const float* __restrict__ b, int V) {
    __shared__ float xs[4][D];
    int warp = threadIdx.x >> 5, lane = threadIdx.x & 31;
    int v  = blockIdx.x * 4 + warp;
    int vc = v < V ? v : V - 1;
    *(float4*)&xs[warp][lane << 2] = *(const float4*)&x[vc * D + (lane << 2)];
    __syncwarp();
    float y = 0.f;
    if (lane < KP) {
        #pragma unroll 8
        for (int k = 0; k < D; k++) y = fmaf(xs[warp][k], Wk1[k * KP + lane], y);
        y += bk1[lane];
    }
    float s = (lane < KP) ? y : 0.f;
    #pragma unroll
    for (int m = 16; m; m >>= 1) s += __shfl_xor_sync(0xffffffffu, s, m);
    float mu = s * (1.f / KP);
    float dv = (lane < KP) ? (y - mu) * (y - mu) : 0.f;
    #pragma unroll
    for (int m = 16; m; m >>= 1) dv += __shfl_xor_sync(0xffffffffu, dv, m);
    float rstd = rsqrtf(dv * (1.f / KP) + EPS);
    if (v < V && lane < KP) {
        float val = (y - mu) * rstd * g[lane] + b[lane];
        g_npjH[v * KP + lane] = __float2half_rn(fmaxf(val, 0.f));
    }
}

// ---- per-node edge-logit dots ----
__global__ void edgedot_kernel(const float* __restrict__ x,
                               const float* __restrict__ We, int V) {
    int v = blockIdx.x * 8 + (threadIdx.x >> 5);
    if (v >= V) return;
    int lane = threadIdx.x & 31;
    float4 xv = *(const float4*)&x[(size_t)v * D + (lane << 2)];
    float4 w1 = *(const float4*)&We[lane << 2];
    float4 w2 = *(const float4*)&We[D + (lane << 2)];
    float u = xv.x * w1.x + xv.y * w1.y + xv.z * w1.z + xv.w * w1.w;
    float w = xv.x * w2.x + xv.y * w2.y + xv.z * w2.z + xv.w * w2.w;
    #pragma unroll
    for (int m = 16; m; m >>= 1) {
        u += __shfl_xor_sync(0xffffffffu, u, m);
        w += __shfl_xor_sync(0xffffffffu, w, m);
    }
    if (lane == 0) g_uw[v] = make_float2(u, w);
}

// ---- edge logits from scalars + exp + segment sum ----
__global__ void logits_kernel(const int* __restrict__ src,
                              const int* __restrict__ dst,
                              const float* __restrict__ be, int E) {
    int e = blockIdx.x * blockDim.x + threadIdx.x;
    if (e >= E) return;
    int sn = src[e], dn = dst[e];
    float2 ud = __ldg(&g_uw[dn]);
    float2 us = __ldg(&g_uw[sn]);
    float lg = fmaxf(ud.x + us.y + be[0], 0.f);
    float a = expf(lg);
    g_aexp[e] = a;
    atomicAdd(&g_asum[dn], a);
}

// ---------------- context scatter: hv is fp16x2 ----------------
__global__ void context_kernel(const int* __restrict__ src,
                               const int* __restrict__ dst, int E) {
    int e = blockIdx.x * 8 + (threadIdx.x >> 5);
    if (e >= E) return;
    int lane = threadIdx.x & 31;
    int sn = src[e], dn = dst[e];
    float coef = g_aexp[e] / g_asum[dn];
    uint2 hraw = *(const uint2*)&g_hvH[(size_t)sn * 64 + lane * 2];
    float2 h01 = __half22float2(*(__half2*)&hraw.x);
    float2 h23 = __half22float2(*(__half2*)&hraw.y);
    atomicAdd((float4*)&g_ctx[(size_t)dn * D + (lane << 2)],
              make_float4(h01.x * coef, h01.y * coef, h23.x * coef, h23.y * coef));
}

// =====================================================================
// Node GEMM, fp16; passes=2: (ah+al)·bh, passes=1: ah·bh.
// out_half=1: store packed __half2 (out cast to uint32_t*).
// =====================================================================
__global__ __launch_bounds__(256)
void mma_gemm(const uint32_t* __restrict__ As, const uint32_t* __restrict__ Bs,
              int Kchunks, int Ntot, int passes, int out_half,
              const float* __restrict__ bias,
              const float* __restrict__ lng, const float* __restrict__ lnb,
              float* __restrict__ out, int V) {
    __shared__ uint32_t sa[2048];
    __shared__ uint32_t sb[2048];
    __shared__ float red[2][64][2];

    int t = threadIdx.x;
    int lane = t & 31, w = t >> 5;
    int wm = w & 3, wn = w >> 2;
    int row0 = blockIdx.x * 64;
    int nb = blockIdx.y * 128;

    float acc[8][4];
    #pragma unroll
    for (int j = 0; j < 8; j++) { acc[j][0]=acc[j][1]=acc[j][2]=acc[j][3]=0.f; }

    const uint4* ag = (const uint4*)(As + (size_t)blockIdx.x * Kchunks * 2048);
    const uint4* bg = (const uint4*)(Bs + (size_t)blockIdx.y * Kchunks * 2048);

    if (passes == 2) {
        uint4 pa0, pa1, pb0, pb1;
        pa0 = ag[t]; pa1 = ag[t + 256];
        pb0 = bg[t]; pb1 = bg[t + 256];
        for (int c = 0; c < Kchunks; c++) {
            __syncthreads();
            ((uint4*)sa)[t] = pa0; ((uint4*)sa)[t + 256] = pa1;
            ((uint4*)sb)[t] = pb0; ((uint4*)sb)[t + 256] = pb1;
            __syncthreads();
            if (c + 1 < Kchunks) {
                const uint4* a4 = ag + (size_t)(c + 1) * 512;
                const uint4* b4 = bg + (size_t)(c + 1) * 512;
                pa0 = a4[t]; pa1 = a4[t + 256];
                pb0 = b4[t]; pb1 = b4[t + 256];
            }
            #pragma unroll
            for (int ks = 0; ks < 2; ks++) {
                uint4 ah = ((const uint4*)sa)[(wm * 2 + ks) * 32 + lane];
                uint4 al = *(const uint4*)&sa[1024 + (((wm * 2 + ks) * 32 + lane) << 2)];
                #pragma unroll
                for (int j = 0; j < 8; j++) {
                    int nt = wn * 8 + j;
                    uint2 bh = ((const uint2*)sb)[(nt * 2 + ks) * 32 + lane];
                    MMA_F16(acc[j], ah, bh);
                    MMA_F16(acc[j], al, bh);
                }
            }
        }
    } else {
        uint4 pa0, pb0, pb1;
        pa0 = ag[t];
        pb0 = bg[t]; pb1 = bg[t + 256];
        for (int c = 0; c < Kchunks; c++) {
            __syncthreads();
            ((uint4*)sa)[t] = pa0;
            ((uint4*)sb)[t] = pb0; ((uint4*)sb)[t + 256] = pb1;
            __syncthreads();
            if (c + 1 < Kchunks) {
                const uint4* a4 = ag + (size_t)(c + 1) * 512;
                const uint4* b4 = bg + (size_t)(c + 1) * 512;
                pa0 = a4[t];
                pb0 = b4[t]; pb1 = b4[t + 256];
            }
            #pragma unroll
            for (int ks = 0; ks < 2; ks++) {
                uint4 ah = ((const uint4*)sa)[(wm * 2 + ks) * 32 + lane];
                #pragma unroll
                for (int j = 0; j < 8; j++) {
                    int nt = wn * 8 + j;
                    uint2 bh = ((const uint2*)sb)[(nt * 2 + ks) * 32 + lane];
                    MMA_F16(acc[j], ah, bh);
                }
            }
        }
    }

    int rl = row0 + wm * 16 + (lane >> 2);
    int rh = rl + 8;
    #pragma unroll
    for (int j = 0; j < 8; j++) {
        int gc = nb + wn * 64 + j * 8 + ((lane & 3) << 1);
        float b0 = bias[gc], b1 = bias[gc + 1];
        acc[j][0] += b0; acc[j][1] += b1; acc[j][2] += b0; acc[j][3] += b1;
    }
    if (lng == nullptr) {
        if (out_half) {
            uint32_t* oh = (uint32_t*)out;
            int ld2 = Ntot >> 1;
            #pragma unroll
            for (int j = 0; j < 8; j++) {
                int gc = nb + wn * 64 + j * 8 + ((lane & 3) << 1);
                if (rl < V) oh[(size_t)rl * ld2 + (gc >> 1)] = pack_hi16(acc[j][0], acc[j][1]);
                if (rh < V) oh[(size_t)rh * ld2 + (gc >> 1)] = pack_hi16(acc[j][2], acc[j][3]);
            }
        } else {
            #pragma unroll
            for (int j = 0; j < 8; j++) {
                int gc = nb + wn * 64 + j * 8 + ((lane & 3) << 1);
                if (rl < V) *(float2*)&out[(size_t)rl * Ntot + gc] = make_float2(acc[j][0], acc[j][1]);
                if (rh < V) *(float2*)&out[(size_t)rh * Ntot + gc] = make_float2(acc[j][2], acc[j][3]);
            }
        }
    } else {
        float s_lo=0.f, q_lo=0.f, s_hi=0.f, q_hi=0.f;
        #pragma unroll
        for (int j = 0; j < 8; j++) {
            s_lo += acc[j][0] + acc[j][1];
            q_lo += acc[j][0]*acc[j][0] + acc[j][1]*acc[j][1];
            s_hi += acc[j][2] + acc[j][3];
            q_hi += acc[j][2]*acc[j][2] + acc[j][3]*acc[j][3];
        }
        #pragma unroll
        for (int m = 1; m <= 2; m <<= 1) {
            s_lo += __shfl_xor_sync(0xffffffffu, s_lo, m);
            q_lo += __shfl_xor_sync(0xffffffffu, q_lo, m);
            s_hi += __shfl_xor_sync(0xffffffffu, s_hi, m);
            q_hi += __shfl_xor_sync(0xffffffffu, q_hi, m);
        }
        int rloc = wm * 16 + (lane >> 2);
        if ((lane & 3) == 0) {
            red[wn][rloc][0] = s_lo;   red[wn][rloc][1] = q_lo;
            red[wn][rloc+8][0] = s_hi; red[wn][rloc+8][1] = q_hi;
        }
        __syncthreads();
        float ts_lo = s_lo + red[wn ^ 1][rloc][0];
        float tq_lo = q_lo + red[wn ^ 1][rloc][1];
        float ts_hi = s_hi + red[wn ^ 1][rloc + 8][0];
        float tq_hi = q_hi + red[wn ^ 1][rloc + 8][1];
        float mu_lo = ts_lo * (1.f/128.f);
        float mu_hi = ts_hi * (1.f/128.f);
        float rs_lo = rsqrtf(tq_lo * (1.f/128.f) - mu_lo*mu_lo + EPS);
        float rs_hi = rsqrtf(tq_hi * (1.f/128.f) - mu_hi*mu_hi + EPS);
        #pragma unroll
        for (int j = 0; j < 8; j++) {
            int gc = wn * 64 + j * 8 + ((lane & 3) << 1);
            float g0 = lng[gc], g1 = lng[gc+1];
            float bb0 = lnb[gc], bb1 = lnb[gc+1];
            if (rl < V) {
                float o0 = fmaxf((acc[j][0]-mu_lo)*rs_lo*g0 + bb0, 0.f);
                float o1 = fmaxf((acc[j][1]-mu_lo)*rs_lo*g1 + bb1, 0.f);
                *(float2*)&out[(size_t)rl * 128 + gc] = make_float2(o0, o1);
            }
            if (rh < V) {
                float o2 = fmaxf((acc[j][2]-mu_hi)*rs_hi*g0 + bb0, 0.f);
                float o3 = fmaxf((acc[j][3]-mu_hi)*rs_hi*g1 + bb1, 0.f);
                *(float2*)&out[(size_t)rh * 128 + gc] = make_float2(o2, o3);
            }
        }
    }
}

// =====================================================================
// Kron edge GEMM fp16 1-PASS, npj in fp16, A-build via HMUL2.
// =====================================================================
__global__ __launch_bounds__(256, 2)
void kron_mma(const int* __restrict__ src, const int* __restrict__ dst,
              const uint32_t* __restrict__ Wk2S,
              const float* __restrict__ bk2,
              const float* __restrict__ lng, const float* __restrict__ lnb,
              int E) {
    extern __shared__ uint32_t dsm[];
    uint32_t* sa = dsm;               // 5120 u32
    uint32_t* sb = dsm + 5120;        // 5120 u32
    __half* Ss = (__half*)(dsm + 10240);  // 128*20 halves (1280 u32 total w/ Ds)
    __half* Ds = Ss + 2560;
    __shared__ int ssrc[128], sdst[128];
    __shared__ float red[2][128][2];

    int t = threadIdx.x;
    int lane = t & 31, w = t >> 5;
    int wm = w & 3, wn = w >> 2;
    int e0 = blockIdx.x * 128;

    if (t < 128) {
        int ee = e0 + t; if (ee >= E) ee = E - 1;
        ssrc[t] = src[ee];
        sdst[t] = dst[ee];
    }
    __syncthreads();
    // load npj rows (20 halves = 10 u32 per edge)
    const uint32_t* npjU = (const uint32_t*)g_npjH;
    for (int idx = t; idx < 1280; idx += 256) {
        int e = idx / 10, q = idx - e * 10;
        ((uint32_t*)Ss)[idx] = npjU[ssrc[e] * 10 + q];
        ((uint32_t*)Ds)[idx] = npjU[sdst[e] * 10 + q];
    }

    float acc[2][8][4];
    #pragma unroll
    for (int r = 0; r < 2; r++)
        #pragma unroll
        for (int j = 0; j < 8; j++) { acc[r][j][0]=acc[r][j][1]=acc[r][j][2]=acc[r][j][3]=0.f; }

    int be = t >> 1, ih = t & 1;
    int amt = be >> 4;
    int ribase = (be >> 3) & 1;
    int alnb = (be & 7) << 2;

    for (int c = 0; c < 5; c++) {
        __syncthreads();
        {
            const __half* ds = &Ds[be * 20];
            const __half* ss = &Ss[be * 20];
            #pragma unroll
            for (int iv = 0; iv < 2; iv++) {
                int il = ih * 2 + iv;
                __half2 sv2 = __half2half2(ss[c * 4 + il]);
                #pragma unroll
                for (int q = 0; q < 10; q++) {
                    __half2 d2 = *(const __half2*)&ds[2 * q];
                    __half2 p2 = __hmul2(sv2, d2);
                    int kp = il * 10 + q;
                    int ai = (((amt * 5 + (kp >> 3)) * 32 + alnb + (kp & 3)) << 2)
                             + ribase + (((kp >> 2) & 1) << 1);
                    sa[ai] = *(uint32_t*)&p2;
                }
            }
        }
        {
            const uint4* bsrc = (const uint4*)(Wk2S + c * 5120);
            #pragma unroll
            for (int i = 0; i < 5; i++)
                ((uint4*)sb)[t + (i << 8)] = bsrc[t + (i << 8)];
        }
        __syncthreads();
        #pragma unroll
        for (int ks = 0; ks < 5; ks++) {
            uint4 ah0 = ((const uint4*)sa)[((wm * 2 + 0) * 5 + ks) * 32 + lane];
            uint4 ah1 = ((const uint4*)sa)[((wm * 2 + 1) * 5 + ks) * 32 + lane];
            #pragma unroll
            for (int j = 0; j < 8; j++) {
                int nt = wn * 8 + j;
                uint2 bh = ((const uint2*)sb)[(nt * 5 + ks) * 32 + lane];
                MMA_F16(acc[0][j], ah0, bh);
                MMA_F16(acc[1][j], ah1, bh);
            }
        }
    }

    #pragma unroll
    for (int r = 0; r < 2; r++)
        #pragma unroll
        for (int j = 0; j < 8; j++) {
            int gc = wn * 64 + j * 8 + ((lane & 3) << 1);
            float b0 = bk2[gc], b1 = bk2[gc + 1];
            acc[r][j][0] += b0; acc[r][j][1] += b1;
            acc[r][j][2] += b0; acc[r][j][3] += b1;
        }
    float sum[2][2], sq[2][2];
    #pragma unroll
    for (int r = 0; r < 2; r++) {
        float s_lo=0.f, q_lo=0.f, s_hi=0.f, q_hi=0.f;
        #pragma unroll
        for (int j = 0; j < 8; j++) {
            s_lo += acc[r][j][0] + acc[r][j][1];
            q_lo += acc[r][j][0]*acc[r][j][0] + acc[r][j][1]*acc[r][j][1];
            s_hi += acc[r][j][2] + acc[r][j][3];
            q_hi += acc[r][j][2]*acc[r][j][2] + acc[r][j][3]*acc[r][j][3];
        }
        #pragma unroll
        for (int m = 1; m <= 2; m <<= 1) {
            s_lo += __shfl_xor_sync(0xffffffffu, s_lo, m);
            q_lo += __shfl_xor_sync(0xffffffffu, q_lo, m);
            s_hi += __shfl_xor_sync(0xffffffffu, s_hi, m);
            q_hi += __shfl_xor_sync(0xffffffffu, q_hi, m);
        }
        sum[r][0] = s_lo; sq[r][0] = q_lo;
        sum[r][1] = s_hi; sq[r][1] = q_hi;
        if ((lane & 3) == 0) {
            int rloc = wm * 32 + r * 16 + (lane >> 2);
            red[wn][rloc][0] = s_lo;     red[wn][rloc][1] = q_lo;
            red[wn][rloc + 8][0] = s_hi; red[wn][rloc + 8][1] = q_hi;
        }
    }
    __syncthreads();
    #pragma unroll
    for (int r = 0; r < 2; r++) {
        #pragma unroll
        for (int h = 0; h < 2; h++) {
            int rloc = wm * 32 + r * 16 + h * 8 + (lane >> 2);
            float ts = sum[r][h] + red[wn ^ 1][rloc][0];
            float tq = sq[r][h] + red[wn ^ 1][rloc][1];
            float mu = ts * (1.f / 128.f);
            float rs = rsqrtf(tq * (1.f / 128.f) - mu * mu + EPS);
            int ge = e0 + rloc;
            if (ge < E) {
                int dn = sdst[rloc];
                #pragma unroll
                for (int j = 0; j < 8; j++) {
                    int gc = wn * 64 + j * 8 + ((lane & 3) << 1);
                    float g0 = lng[gc], g1 = lng[gc + 1];
                    float bb0 = lnb[gc], bb1 = lnb[gc + 1];
                    float* p = &g_kf[(size_t)dn * 128 + gc];
                    atomicAdd(p,     fmaxf((acc[r][j][2*h  ]-mu)*rs*g0 + bb0, 0.f));
                    atomicAdd(p + 1, fmaxf((acc[r][j][2*h+1]-mu)*rs*g1 + bb1, 0.f));
                }
            }
        }
    }
}

// ---- GRU gates (fp16 gi/gh) + relu + LN -> Acat chunks 0-3; kf -> 4-7 ----
__global__ void gates_kernel(const float* __restrict__ x,
                             const float* __restrict__ lng,
                             const float* __restrict__ lnb,
                             uint32_t* __restrict__ Acat, int V) {
    int v = blockIdx.x * 8 + (threadIdx.x >> 5);
    if (v >= V) return;
    int lane = threadIdx.x & 31;
    const uint32_t* giH = &g_giH[(size_t)v * 192];
    const uint32_t* ghH = &g_ghH[(size_t)v * 192];
    float h[4];
    {
        uint2 uir = *(const uint2*)&giH[lane * 2];
        uint2 uiz = *(const uint2*)&giH[64 + lane * 2];
        uint2 uin = *(const uint2*)&giH[128 + lane * 2];
        uint2 uhr = *(const uint2*)&ghH[lane * 2];
        uint2 uhz = *(const uint2*)&ghH[64 + lane * 2];
        uint2 uhn = *(const uint2*)&ghH[128 + lane * 2];
        float4 xv = *(const float4*)&x[(size_t)v * D + (lane << 2)];
        #pragma unroll
        for (int hh = 0; hh < 2; hh++) {
            float2 ir = __half22float2(*(__half2*)((hh == 0) ? &uir.x : &uir.y));
            float2 iz = __half22float2(*(__half2*)((hh == 0) ? &uiz.x : &uiz.y));
            float2 in_ = __half22float2(*(__half2*)((hh == 0) ? &uin.x : &uin.y));
            float2 hr = __half22float2(*(__half2*)((hh == 0) ? &uhr.x : &uhr.y));
            float2 hz = __half22float2(*(__half2*)((hh == 0) ? &uhz.x : &uhz.y));
            float2 hn = __half22float2(*(__half2*)((hh == 0) ? &uhn.x : &uhn.y));
            #pragma unroll
            for (int q = 0; q < 2; q++) {
                int i = hh * 2 + q;
                float gir = (q == 0) ? ir.x : ir.y;
                float giz = (q == 0) ? iz.x : iz.y;
                float gin = (q == 0) ? in_.x : in_.y;
                float ghr = (q == 0) ? hr.x : hr.y;
                float ghz = (q == 0) ? hz.x : hz.y;
                float ghn = (q == 0) ? hn.x : hn.y;
                float r = 1.f / (1.f + expf(-(gir + ghr)));
                float z = 1.f / (1.f + expf(-(giz + ghz)));
                float n = tanhf(gin + r * ghn);
                h[i] = fmaxf((1.f - z) * n + z * (&xv.x)[i], 0.f);
            }
        }
    }
    float s = h[0] + h[1] + h[2] + h[3];
    #pragma unroll
    for (int m = 16; m; m >>= 1) s += __shfl_xor_sync(0xffffffffu, s, m);
    float mu = s * (1.f / 128.f), q = 0.f;
    #pragma unroll
    for (int i = 0; i < 4; i++) { float d0 = h[i] - mu; q = fmaf(d0, d0, q); }
    #pragma unroll
    for (int m = 16; m; m >>= 1) q += __shfl_xor_sync(0xffffffffu, q, m);
    float rstd = rsqrtf(q * (1.f / 128.f) + EPS);
    float4 gv = *(const float4*)&lng[lane << 2];
    float4 b2 = *(const float4*)&lnb[lane << 2];
    float o[4];
    o[0] = (h[0]-mu)*rstd*gv.x + b2.x;
    o[1] = (h[1]-mu)*rstd*gv.y + b2.y;
    o[2] = (h[2]-mu)*rstd*gv.z + b2.z;
    o[3] = (h[3]-mu)*rstd*gv.w + b2.w;
    float4 kv = *(const float4*)&g_kf[(size_t)v * D + (lane << 2)];
    int mb = v >> 6;
    int r = v & 63;
    int mt = r >> 4, rb = (r >> 3) & 1, lh = r & 7;
    #pragma unroll
    for (int pp = 0; pp < 2; pp++) {
        int kp = lane * 2 + pp;
        int ll = kp & 3;
        int ri = (((kp >> 2) & 1) << 1) | rb;
        int ks = (kp >> 3) & 1;
        int c  = kp >> 4;
        int idx = mt * 256 + ks * 128 + ((lh << 2) | ll) * 4 + ri;
        uint32_t hi, lo;
        split_pair(o[2 * pp], o[2 * pp + 1], hi, lo);
        size_t base = ((size_t)(mb * 8 + c)) << 11;
        Acat[base + idx] = hi;
        Acat[base + 1024 + idx] = lo;
        split_pair((&kv.x)[2 * pp], (&kv.x)[2 * pp + 1], hi, lo);
        base = ((size_t)(mb * 8 + 4 + c)) << 11;
        Acat[base + idx] = hi;
        Acat[base + 1024 + idx] = lo;
    }
}

// ---------------- host ----------------
extern "C" void kernel_launch(void* const* d_in, const int* in_sizes, int n_in,
                              void* d_out, int out_size) {
    const float* node   = (const float*)d_in[0];
    const int*   src    = (const int*)  d_in[1];
    const int*   dst    = (const int*)  d_in[2];
    const float* W_edge = (const float*)d_in[3];
    const float* b_edge = (const float*)d_in[4];
    const float* W_pn   = (const float*)d_in[5];
    const float* b_pn   = (const float*)d_in[6];
    const float* W_ih   = (const float*)d_in[7];
    const float* b_ih   = (const float*)d_in[8];
    const float* W_hh   = (const float*)d_in[9];
    const float* b_hh   = (const float*)d_in[10];
    const float* ln_g   = (const float*)d_in[11];
    const float* ln_b   = (const float*)d_in[12];
    const float* Wk1    = (const float*)d_in[13];
    const float* bk1    = (const float*)d_in[14];
    const float* lnk1_g = (const float*)d_in[15];
    const float* lnk1_b = (const float*)d_in[16];
    const float* Wk2    = (const float*)d_in[17];
    const float* bk2    = (const float*)d_in[18];
    const float* lnk2_g = (const float*)d_in[19];
    const float* lnk2_b = (const float*)d_in[20];
    const float* Wc     = (const float*)d_in[21];
    const float* bc     = (const float*)d_in[22];
    const float* lnc_g  = (const float*)d_in[23];
    const float* lnc_b  = (const float*)d_in[24];
    int V = in_sizes[0] / D;
    int E = in_sizes[1];
    float* out = (float*)d_out;

    float *p_asum, *p_ctx, *p_kf;
    uint32_t *p_hvH, *p_giH, *p_ghH;
    uint32_t *p_WpnS, *p_WihS, *p_WhhS, *p_WcS, *p_Wk2S;
    uint32_t *p_An, *p_Ac, *p_Aq;
    cudaGetSymbolAddress((void**)&p_asum, g_asum);
    cudaGetSymbolAddress((void**)&p_hvH,  g_hvH);
    cudaGetSymbolAddress((void**)&p_ctx,  g_ctx);
    cudaGetSymbolAddress((void**)&p_kf,   g_kf);
    cudaGetSymbolAddress((void**)&p_giH,  g_giH);
    cudaGetSymbolAddress((void**)&p_ghH,  g_ghH);
    cudaGetSymbolAddress((void**)&p_WpnS, g_WpnS);
    cudaGetSymbolAddress((void**)&p_WihS, g_WihS);
    cudaGetSymbolAddress((void**)&p_WhhS, g_WhhS);
    cudaGetSymbolAddress((void**)&p_WcS,  g_WcS);
    cudaGetSymbolAddress((void**)&p_Wk2S, g_Wk2S);
    cudaGetSymbolAddress((void**)&p_An,   g_Anode);
    cudaGetSymbolAddress((void**)&p_Ac,   g_Actx);
    cudaGetSymbolAddress((void**)&p_Aq,   g_Acat);

    static bool attr_set = false;
    if (!attr_set) {
        cudaFuncSetAttribute(kron_mma, cudaFuncAttributeMaxDynamicSharedMemorySize, 52000);
        attr_set = true;
    }

    int NBv = (V + 63) / 64;

    // zero accumulators
    {
        int n4 = V * D / 4;
        zero_kernel<<<(n4 + 255) / 256, 256>>>((float4*)p_ctx, n4);
        zero_kernel<<<(n4 + 255) / 256, 256>>>((float4*)p_kf,  n4);
        n4 = V / 4;
        zero_kernel<<<(n4 + 255) / 256, 256>>>((float4*)p_asum, n4);
    }

    // pack weights
    pack_w_frag<<<(64 * 128 + 255) / 256, 256>>>(W_pn, 128, 128, 0, p_WpnS);
    pack_w_frag<<<(64 * 384 + 255) / 256, 256>>>(W_ih, 128, 384, 1, p_WihS);
    pack_w_frag<<<(64 * 384 + 255) / 256, 256>>>(W_hh, 128, 384, 1, p_WhhS);
    pack_w_frag<<<(128 * 128 + 255) / 256, 256>>>(Wc, 256, 128, 0, p_WcS);
    pack_wk2<<<(200 * 128 + 255) / 256, 256>>>(Wk2, p_Wk2S);

    // pack node activations
    pack_act<<<NBv, 256>>>(node, 128, nullptr, 0, 0, p_An, V, 0, 4);

    npj_kernel<<<(V + 3) / 4, 128>>>(node, Wk1, bk1, lnk1_g, lnk1_b, V);
    edgedot_kernel<<<(V + 7) / 8, 256>>>(node, W_edge, V);
    logits_kernel<<<(E + 255) / 256, 256>>>(src, dst, b_edge, E);

    // hv = node @ W_pn + b_pn (1-pass, fp16 out)
    mma_gemm<<<dim3(NBv, 1), 256>>>(p_An, p_WpnS, 4, 128, 1, 1,
                                    b_pn, nullptr, nullptr, (float*)p_hvH, V);

    // edge kron GEMM (1-pass, half2 A-build) + LN + relu + scatter to kf
    kron_mma<<<(E + 127) / 128, 256, 51200>>>(src, dst, p_Wk2S,
                                              bk2, lnk2_g, lnk2_b, E);

    // context scatter (hv fp16 gather, fp32 atomics)
    context_kernel<<<(E + 7) / 8, 256>>>(src, dst, E);

    // pack relu(ctx)
    pack_act<<<NBv, 256>>>(p_ctx, 128, nullptr, 0, 1, p_Ac, V, 0, 4);

    // gi / gh (1-pass, fp16 output)
    mma_gemm<<<dim3(NBv, 3), 256>>>(p_Ac, p_WihS, 4, 384, 1, 1,
                                    b_ih, nullptr, nullptr, (float*)p_giH, V);
    mma_gemm<<<dim3(NBv, 3), 256>>>(p_An, p_WhhS, 4, 384, 1, 1,
                                    b_hh, nullptr, nullptr, (float*)p_ghH, V);

    // gates -> Acat chunks 0-3; kf -> chunks 4-7
    gates_kernel<<<(V + 7) / 8, 256>>>(node, ln_g, ln_b, p_Aq, V);

    // out = relu(LN(cat @ Wc + bc)) (2-pass)
    mma_gemm<<<dim3(NBv, 1), 256>>>(p_Aq, p_WcS, 8, 128, 2, 0,
                                    bc, lnc_g, lnc_b, out, V);
}

// round 14
// speedup vs baseline: 1.7547x; 1.1235x over previous
#include <cuda_runtime.h>
#include <cuda_fp16.h>
#include <math.h>
#include <stdint.h>

#define D     128
#define KP    20
#define VMAX  100000
#define EMAX  400000
#define EPS   1e-5f
#define NBMAX 1563   // (VMAX+63)/64

// ---------------- scratch (device globals; no allocations) ----------------
__device__ __half g_npjH[VMAX * KP];
__device__ float g_aexp [EMAX];
__device__ float g_asum [VMAX];
__device__ float2 g_uw  [VMAX];
__device__ uint32_t g_hvH[(size_t)VMAX * 64];
__device__ float g_ctx  [VMAX * D];
__device__ float g_kf   [VMAX * D];
__device__ uint32_t g_giH[(size_t)VMAX * 192];
__device__ uint32_t g_ghH[(size_t)VMAX * 192];

// fragment-ordered fp16 WEIGHT streams (hi only)
__device__ uint32_t g_WpnS[1 * 4 * 2048];
__device__ uint32_t g_WihS[3 * 4 * 2048];
__device__ uint32_t g_WhhS[3 * 4 * 2048];
__device__ uint32_t g_WcS [1 * 8 * 2048];
__device__ uint32_t g_Wk2S[5 * 5120];

// fragment-ordered fp16 ACTIVATION streams (hi only used; lo region reserved)
__device__ uint32_t g_Anode[(size_t)NBMAX * 4 * 2048];
__device__ uint32_t g_Actx [(size_t)NBMAX * 4 * 2048];
__device__ uint32_t g_Acat [(size_t)NBMAX * 8 * 2048];

__device__ __forceinline__ uint32_t pack_hi16(float a0, float a1) {
    __half2 hp = __floats2half2_rn(a0, a1);
    return *(uint32_t*)&hp;
}

#define MMA_F16(c, A, B) asm volatile( \
    "mma.sync.aligned.m16n8k16.row.col.f32.f16.f16.f32 " \
    "{%0,%1,%2,%3}, {%4,%5,%6,%7}, {%8,%9}, {%0,%1,%2,%3};\n" \
    : "+f"(c[0]), "+f"(c[1]), "+f"(c[2]), "+f"(c[3]) \
    : "r"(A.x), "r"(A.y), "r"(A.z), "r"(A.w), "r"(B.x), "r"(B.y))

// ---------------- fused zero: ctx, kf, asum ----------------
__global__ void zero_all(float4* ctx, float4* kf, float4* asum, int n4c, int n4s) {
    int i = blockIdx.x * blockDim.x + threadIdx.x;
    if (i < n4c) { ctx[i] = make_float4(0.f, 0.f, 0.f, 0.f); return; }
    i -= n4c;
    if (i < n4c) { kf[i] = make_float4(0.f, 0.f, 0.f, 0.f); return; }
    i -= n4c;
    if (i < n4s) asum[i] = make_float4(0.f, 0.f, 0.f, 0.f);
}

// ---------------- weight pack device fns ----------------
__device__ void dev_pack_w(const float* __restrict__ W, int K, int Ntot,
                           int transp, uint32_t* __restrict__ out, int b) {
    int idx = b * 256 + threadIdx.x;
    if (idx >= (K / 2) * Ntot) return;
    int kp = idx / Ntot, n = idx - kp * Ntot;
    int k0 = 2 * kp;
    float w0, w1;
    if (transp) { w0 = W[n * K + k0]; w1 = W[n * K + k0 + 1]; }
    else        { w0 = W[k0 * Ntot + n]; w1 = W[(k0 + 1) * Ntot + n]; }
    int c = kp >> 4, kpl = kp & 15;
    int ny = n >> 7, nl = n & 127;
    int bi = ((((nl >> 3) * 2 + (kpl >> 3)) * 32 + ((nl & 7) << 2) + (kpl & 3)) << 1)
             + ((kpl >> 2) & 1);
    size_t base = ((size_t)(ny * (K >> 5) + c)) << 11;
    out[base + bi] = pack_hi16(w0, w1);
}
__device__ void dev_pack_wk2(const float* __restrict__ W,
                             uint32_t* __restrict__ out, int b) {
    int idx = b * 256 + threadIdx.x;
    if (idx >= 200 * 128) return;
    int kp = idx >> 7, n = idx & 127;
    float w0 = W[(2 * kp) * 128 + n];
    float w1 = W[(2 * kp + 1) * 128 + n];
    int c = kp / 40, kpl = kp - c * 40;
    int bi = ((((n >> 3) * 5 + (kpl >> 3)) * 32 + ((n & 7) << 2) + (kpl & 3)) << 1)
             + ((kpl >> 2) & 1);
    out[c * 5120 + bi] = pack_hi16(w0, w1);
}

// fused weight pack: [0,32) Wpn, [32,128) Wih, [128,224) Whh, [224,288) Wc, [288,388) Wk2
__global__ void pack_w_all(const float* W_pn, const float* W_ih, const float* W_hh,
                           const float* Wc, const float* Wk2,
                           uint32_t* WpnS, uint32_t* WihS, uint32_t* WhhS,
                           uint32_t* WcS, uint32_t* Wk2S) {
    int b = blockIdx.x;
    if (b < 32)  { dev_pack_w(W_pn, 128, 128, 0, WpnS, b); return; }
    b -= 32;
    if (b < 96)  { dev_pack_w(W_ih, 128, 384, 1, WihS, b); return; }
    b -= 96;
    if (b < 96)  { dev_pack_w(W_hh, 128, 384, 1, WhhS, b); return; }
    b -= 96;
    if (b < 64)  { dev_pack_w(Wc, 256, 128, 0, WcS, b); return; }
    b -= 64;
    dev_pack_wk2(Wk2, Wk2S, b);
}

// activation pack (fp16 hi only)
__global__ void pack_act(const float* __restrict__ X0, int K0, int relu,
                         uint32_t* __restrict__ out, int V,
                         int coff, int KchTot) {
    int t = threadIdx.x;
    int mb = blockIdx.x;
    int Kch = K0 >> 5;
    for (int it = 0; it < Kch * 4; it++) {
        int c = it >> 2;
        int idx = ((it & 3) << 8) + t;
        int mt = idx >> 8;
        int ks = (idx >> 7) & 1;
        int ln = (idx >> 2) & 31;
        int ri = idx & 3;
        int row = mb * 64 + mt * 16 + (ri & 1) * 8 + (ln >> 2);
        if (row >= V) row = V - 1;
        int k = c * 32 + ks * 16 + ((ri >> 1) << 3) + ((ln & 3) << 1);
        float2 a = *(const float2*)&X0[(size_t)row * K0 + k];
        if (relu) { a.x = fmaxf(a.x, 0.f); a.y = fmaxf(a.y, 0.f); }
        size_t base = ((size_t)(mb * KchTot + coff + c)) << 11;
        out[base + idx] = pack_hi16(a.x, a.y);
    }
}

// ---- fused per-node: npj (fp16) + edge-logit dots ----
__global__ void node_pre_kernel(const float* __restrict__ x,
                                const float* __restrict__ Wk1,
                                const float* __restrict__ bk1,
                                const float* __restrict__ g,
                                const float* __restrict__ b,
                                const float* __restrict__ We, int V) {
    __shared__ float xs[8][D];
    int warp = threadIdx.x >> 5, lane = threadIdx.x & 31;
    int v = blockIdx.x * 8 + warp;
    int vc = v < V ? v : V - 1;
    float4 xv = *(const float4*)&x[(size_t)vc * D + (lane << 2)];
    *(float4*)&xs[warp][lane << 2] = xv;
    __syncwarp();
    // edgedot
    {
        float4 w1 = *(const float4*)&We[lane << 2];
        float4 w2 = *(const float4*)&We[D + (lane << 2)];
        float u = xv.x * w1.x + xv.y * w1.y + xv.z * w1.z + xv.w * w1.w;
        float w = xv.x * w2.x + xv.y * w2.y + xv.z * w2.z + xv.w * w2.w;
        #pragma unroll
        for (int m = 16; m; m >>= 1) {
            u += __shfl_xor_sync(0xffffffffu, u, m);
            w += __shfl_xor_sync(0xffffffffu, w, m);
        }
        if (lane == 0 && v < V) g_uw[v] = make_float2(u, w);
    }
    // npj
    float y = 0.f;
    if (lane < KP) {
        #pragma unroll 8
        for (int k = 0; k < D; k++) y = fmaf(xs[warp][k], Wk1[k * KP + lane], y);
        y += bk1[lane];
    }
    float s = (lane < KP) ? y : 0.f;
    #pragma unroll
    for (int m = 16; m; m >>= 1) s += __shfl_xor_sync(0xffffffffu, s, m);
    float mu = s * (1.f / KP);
    float dv = (lane < KP) ? (y - mu) * (y - mu) : 0.f;
    #pragma unroll
    for (int m = 16; m; m >>= 1) dv += __shfl_xor_sync(0xffffffffu, dv, m);
    float rstd = rsqrtf(dv * (1.f / KP) + EPS);
    if (v < V && lane < KP) {
        float val = (y - mu) * rstd * g[lane] + b[lane];
        g_npjH[v * KP + lane] = __float2half_rn(fmaxf(val, 0.f));
    }
}

// ---- edge logits from scalars + exp + segment sum ----
__global__ void logits_kernel(const int* __restrict__ src,
                              const int* __restrict__ dst,
                              const float* __restrict__ be, int E) {
    int e = blockIdx.x * blockDim.x + threadIdx.x;
    if (e >= E) return;
    int sn = src[e], dn = dst[e];
    float2 ud = __ldg(&g_uw[dn]);
    float2 us = __ldg(&g_uw[sn]);
    float lg = fmaxf(ud.x + us.y + be[0], 0.f);
    float a = expf(lg);
    g_aexp[e] = a;
    atomicAdd(&g_asum[dn], a);
}

// ---------------- context scatter: hv fp16 gather, fp32 atomics ----------------
__global__ void context_kernel(const int* __restrict__ src,
                               const int* __restrict__ dst, int E) {
    int e = blockIdx.x * 8 + (threadIdx.x >> 5);
    if (e >= E) return;
    int lane = threadIdx.x & 31;
    int sn = src[e], dn = dst[e];
    float coef = g_aexp[e] / g_asum[dn];
    uint2 hraw = *(const uint2*)&g_hvH[(size_t)sn * 64 + lane * 2];
    float2 h01 = __half22float2(*(__half2*)&hraw.x);
    float2 h23 = __half22float2(*(__half2*)&hraw.y);
    atomicAdd((float4*)&g_ctx[(size_t)dn * D + (lane << 2)],
              make_float4(h01.x * coef, h01.y * coef, h23.x * coef, h23.y * coef));
}

// =====================================================================
// Node GEMM, fp16 1-pass (ah·bh). out_half=1: store packed __half2.
// =====================================================================
__global__ __launch_bounds__(256)
void mma_gemm(const uint32_t* __restrict__ As, const uint32_t* __restrict__ Bs,
              int Kchunks, int Ntot, int out_half,
              const float* __restrict__ bias,
              const float* __restrict__ lng, const float* __restrict__ lnb,
              float* __restrict__ out, int V) {
    __shared__ uint32_t sa[1024];
    __shared__ uint32_t sb[2048];
    __shared__ float red[2][64][2];

    int t = threadIdx.x;
    int lane = t & 31, w = t >> 5;
    int wm = w & 3, wn = w >> 2;
    int row0 = blockIdx.x * 64;
    int nb = blockIdx.y * 128;

    float acc[8][4];
    #pragma unroll
    for (int j = 0; j < 8; j++) { acc[j][0]=acc[j][1]=acc[j][2]=acc[j][3]=0.f; }

    const uint4* ag = (const uint4*)(As + (size_t)blockIdx.x * Kchunks * 2048);
    const uint4* bg = (const uint4*)(Bs + (size_t)blockIdx.y * Kchunks * 2048);

    uint4 pa0, pb0, pb1;
    pa0 = ag[t];
    pb0 = bg[t]; pb1 = bg[t + 256];
    for (int c = 0; c < Kchunks; c++) {
        __syncthreads();
        if (t < 256) ((uint4*)sa)[t] = pa0;
        ((uint4*)sb)[t] = pb0; ((uint4*)sb)[t + 256] = pb1;
        __syncthreads();
        if (c + 1 < Kchunks) {
            const uint4* a4 = ag + (size_t)(c + 1) * 512;
            const uint4* b4 = bg + (size_t)(c + 1) * 512;
            pa0 = a4[t];
            pb0 = b4[t]; pb1 = b4[t + 256];
        }
        #pragma unroll
        for (int ks = 0; ks < 2; ks++) {
            uint4 ah = ((const uint4*)sa)[(wm * 2 + ks) * 32 + lane];
            #pragma unroll
            for (int j = 0; j < 8; j++) {
                int nt = wn * 8 + j;
                uint2 bh = ((const uint2*)sb)[(nt * 2 + ks) * 32 + lane];
                MMA_F16(acc[j], ah, bh);
            }
        }
    }

    int rl = row0 + wm * 16 + (lane >> 2);
    int rh = rl + 8;
    #pragma unroll
    for (int j = 0; j < 8; j++) {
        int gc = nb + wn * 64 + j * 8 + ((lane & 3) << 1);
        float b0 = bias[gc], b1 = bias[gc + 1];
        acc[j][0] += b0; acc[j][1] += b1; acc[j][2] += b0; acc[j][3] += b1;
    }
    if (lng == nullptr) {
        if (out_half) {
            uint32_t* oh = (uint32_t*)out;
            int ld2 = Ntot >> 1;
            #pragma unroll
            for (int j = 0; j < 8; j++) {
                int gc = nb + wn * 64 + j * 8 + ((lane & 3) << 1);
                if (rl < V) oh[(size_t)rl * ld2 + (gc >> 1)] = pack_hi16(acc[j][0], acc[j][1]);
                if (rh < V) oh[(size_t)rh * ld2 + (gc >> 1)] = pack_hi16(acc[j][2], acc[j][3]);
            }
        } else {
            #pragma unroll
            for (int j = 0; j < 8; j++) {
                int gc = nb + wn * 64 + j * 8 + ((lane & 3) << 1);
                if (rl < V) *(float2*)&out[(size_t)rl * Ntot + gc] = make_float2(acc[j][0], acc[j][1]);
                if (rh < V) *(float2*)&out[(size_t)rh * Ntot + gc] = make_float2(acc[j][2], acc[j][3]);
            }
        }
    } else {
        float s_lo=0.f, q_lo=0.f, s_hi=0.f, q_hi=0.f;
        #pragma unroll
        for (int j = 0; j < 8; j++) {
            s_lo += acc[j][0] + acc[j][1];
            q_lo += acc[j][0]*acc[j][0] + acc[j][1]*acc[j][1];
            s_hi += acc[j][2] + acc[j][3];
            q_hi += acc[j][2]*acc[j][2] + acc[j][3]*acc[j][3];
        }
        #pragma unroll
        for (int m = 1; m <= 2; m <<= 1) {
            s_lo += __shfl_xor_sync(0xffffffffu, s_lo, m);
            q_lo += __shfl_xor_sync(0xffffffffu, q_lo, m);
            s_hi += __shfl_xor_sync(0xffffffffu, s_hi, m);
            q_hi += __shfl_xor_sync(0xffffffffu, q_hi, m);
        }
        int rloc = wm * 16 + (lane >> 2);
        if ((lane & 3) == 0) {
            red[wn][rloc][0] = s_lo;   red[wn][rloc][1] = q_lo;
            red[wn][rloc+8][0] = s_hi; red[wn][rloc+8][1] = q_hi;
        }
        __syncthreads();
        float ts_lo = s_lo + red[wn ^ 1][rloc][0];
        float tq_lo = q_lo + red[wn ^ 1][rloc][1];
        float ts_hi = s_hi + red[wn ^ 1][rloc + 8][0];
        float tq_hi = q_hi + red[wn ^ 1][rloc + 8][1];
        float mu_lo = ts_lo * (1.f/128.f);
        float mu_hi = ts_hi * (1.f/128.f);
        float rs_lo = rsqrtf(tq_lo * (1.f/128.f) - mu_lo*mu_lo + EPS);
        float rs_hi = rsqrtf(tq_hi * (1.f/128.f) - mu_hi*mu_hi + EPS);
        #pragma unroll
        for (int j = 0; j < 8; j++) {
            int gc = wn * 64 + j * 8 + ((lane & 3) << 1);
            float g0 = lng[gc], g1 = lng[gc+1];
            float bb0 = lnb[gc], bb1 = lnb[gc+1];
            if (rl < V) {
                float o0 = fmaxf((acc[j][0]-mu_lo)*rs_lo*g0 + bb0, 0.f);
                float o1 = fmaxf((acc[j][1]-mu_lo)*rs_lo*g1 + bb1, 0.f);
                *(float2*)&out[(size_t)rl * 128 + gc] = make_float2(o0, o1);
            }
            if (rh < V) {
                float o2 = fmaxf((acc[j][2]-mu_hi)*rs_hi*g0 + bb0, 0.f);
                float o3 = fmaxf((acc[j][3]-mu_hi)*rs_hi*g1 + bb1, 0.f);
                *(float2*)&out[(size_t)rh * 128 + gc] = make_float2(o2, o3);
            }
        }
    }
}

// =====================================================================
// Kron edge GEMM fp16 1-PASS, npj fp16, A-build via HMUL2 (R13 body).
// =====================================================================
__global__ __launch_bounds__(256, 2)
void kron_mma(const int* __restrict__ src, const int* __restrict__ dst,
              const uint32_t* __restrict__ Wk2S,
              const float* __restrict__ bk2,
              const float* __restrict__ lng, const float* __restrict__ lnb,
              int E) {
    extern __shared__ uint32_t dsm[];
    uint32_t* sa = dsm;               // 5120 u32
    uint32_t* sb = dsm + 5120;        // 5120 u32
    __half* Ss = (__half*)(dsm + 10240);
    __half* Ds = Ss + 2560;
    __shared__ int ssrc[128], sdst[128];
    __shared__ float red[2][128][2];

    int t = threadIdx.x;
    int lane = t & 31, w = t >> 5;
    int wm = w & 3, wn = w >> 2;
    int e0 = blockIdx.x * 128;

    if (t < 128) {
        int ee = e0 + t; if (ee >= E) ee = E - 1;
        ssrc[t] = src[ee];
        sdst[t] = dst[ee];
    }
    __syncthreads();
    const uint32_t* npjU = (const uint32_t*)g_npjH;
    for (int idx = t; idx < 1280; idx += 256) {
        int e = idx / 10, q = idx - e * 10;
        ((uint32_t*)Ss)[idx] = npjU[ssrc[e] * 10 + q];
        ((uint32_t*)Ds)[idx] = npjU[sdst[e] * 10 + q];
    }

    float acc[2][8][4];
    #pragma unroll
    for (int r = 0; r < 2; r++)
        #pragma unroll
        for (int j = 0; j < 8; j++) { acc[r][j][0]=acc[r][j][1]=acc[r][j][2]=acc[r][j][3]=0.f; }

    int be = t >> 1, ih = t & 1;
    int amt = be >> 4;
    int ribase = (be >> 3) & 1;
    int alnb = (be & 7) << 2;

    for (int c = 0; c < 5; c++) {
        __syncthreads();
        {
            const __half* ds = &Ds[be * 20];
            const __half* ss = &Ss[be * 20];
            #pragma unroll
            for (int iv = 0; iv < 2; iv++) {
                int il = ih * 2 + iv;
                __half2 sv2 = __half2half2(ss[c * 4 + il]);
                #pragma unroll
                for (int q = 0; q < 10; q++) {
                    __half2 d2 = *(const __half2*)&ds[2 * q];
                    __half2 p2 = __hmul2(sv2, d2);
                    int kp = il * 10 + q;
                    int ai = (((amt * 5 + (kp >> 3)) * 32 + alnb + (kp & 3)) << 2)
                             + ribase + (((kp >> 2) & 1) << 1);
                    sa[ai] = *(uint32_t*)&p2;
                }
            }
        }
        {
            const uint4* bsrc = (const uint4*)(Wk2S + c * 5120);
            #pragma unroll
            for (int i = 0; i < 5; i++)
                ((uint4*)sb)[t + (i << 8)] = bsrc[t + (i << 8)];
        }
        __syncthreads();
        #pragma unroll
        for (int ks = 0; ks < 5; ks++) {
            uint4 ah0 = ((const uint4*)sa)[((wm * 2 + 0) * 5 + ks) * 32 + lane];
            uint4 ah1 = ((const uint4*)sa)[((wm * 2 + 1) * 5 + ks) * 32 + lane];
            #pragma unroll
            for (int j = 0; j < 8; j++) {
                int nt = wn * 8 + j;
                uint2 bh = ((const uint2*)sb)[(nt * 5 + ks) * 32 + lane];
                MMA_F16(acc[0][j], ah0, bh);
                MMA_F16(acc[1][j], ah1, bh);
            }
        }
    }

    #pragma unroll
    for (int r = 0; r < 2; r++)
        #pragma unroll
        for (int j = 0; j < 8; j++) {
            int gc = wn * 64 + j * 8 + ((lane & 3) << 1);
            float b0 = bk2[gc], b1 = bk2[gc + 1];
            acc[r][j][0] += b0; acc[r][j][1] += b1;
            acc[r][j][2] += b0; acc[r][j][3] += b1;
        }
    float sum[2][2], sq[2][2];
    #pragma unroll
    for (int r = 0; r < 2; r++) {
        float s_lo=0.f, q_lo=0.f, s_hi=0.f, q_hi=0.f;
        #pragma unroll
        for (int j = 0; j < 8; j++) {
            s_lo += acc[r][j][0] + acc[r][j][1];
            q_lo += acc[r][j][0]*acc[r][j][0] + acc[r][j][1]*acc[r][j][1];
            s_hi += acc[r][j][2] + acc[r][j][3];
            q_hi += acc[r][j][2]*acc[r][j][2] + acc[r][j][3]*acc[r][j][3];
        }
        #pragma unroll
        for (int m = 1; m <= 2; m <<= 1) {
            s_lo += __shfl_xor_sync(0xffffffffu, s_lo, m);
            q_lo += __shfl_xor_sync(0xffffffffu, q_lo, m);
            s_hi += __shfl_xor_sync(0xffffffffu, s_hi, m);
            q_hi += __shfl_xor_sync(0xffffffffu, q_hi, m);
        }
        sum[r][0] = s_lo; sq[r][0] = q_lo;
        sum[r][1] = s_hi; sq[r][1] = q_hi;
        if ((lane & 3) == 0) {
            int rloc = wm * 32 + r * 16 + (lane >> 2);
            red[wn][rloc][0] = s_lo;     red[wn][rloc][1] = q_lo;
            red[wn][rloc + 8][0] = s_hi; red[wn][rloc + 8][1] = q_hi;
        }
    }
    __syncthreads();
    #pragma unroll
    for (int r = 0; r < 2; r++) {
        #pragma unroll
        for (int h = 0; h < 2; h++) {
            int rloc = wm * 32 + r * 16 + h * 8 + (lane >> 2);
            float ts = sum[r][h] + red[wn ^ 1][rloc][0];
            float tq = sq[r][h] + red[wn ^ 1][rloc][1];
            float mu = ts * (1.f / 128.f);
            float rs = rsqrtf(tq * (1.f / 128.f) - mu * mu + EPS);
            int ge = e0 + rloc;
            if (ge < E) {
                int dn = sdst[rloc];
                #pragma unroll
                for (int j = 0; j < 8; j++) {
                    int gc = wn * 64 + j * 8 + ((lane & 3) << 1);
                    float g0 = lng[gc], g1 = lng[gc + 1];
                    float bb0 = lnb[gc], bb1 = lnb[gc + 1];
                    float* p = &g_kf[(size_t)dn * 128 + gc];
                    atomicAdd(p,     fmaxf((acc[r][j][2*h  ]-mu)*rs*g0 + bb0, 0.f));
                    atomicAdd(p + 1, fmaxf((acc[r][j][2*h+1]-mu)*rs*g1 + bb1, 0.f));
                }
            }
        }
    }
}

// ---- GRU gates (fp16 gi/gh) + relu + LN -> Acat chunks 0-3 (hi); kf -> 4-7 ----
__global__ void gates_kernel(const float* __restrict__ x,
                             const float* __restrict__ lng,
                             const float* __restrict__ lnb,
                             uint32_t* __restrict__ Acat, int V) {
    int v = blockIdx.x * 8 + (threadIdx.x >> 5);
    if (v >= V) return;
    int lane = threadIdx.x & 31;
    const uint32_t* giH = &g_giH[(size_t)v * 192];
    const uint32_t* ghH = &g_ghH[(size_t)v * 192];
    float h[4];
    {
        uint2 uir = *(const uint2*)&giH[lane * 2];
        uint2 uiz = *(const uint2*)&giH[64 + lane * 2];
        uint2 uin = *(const uint2*)&giH[128 + lane * 2];
        uint2 uhr = *(const uint2*)&ghH[lane * 2];
        uint2 uhz = *(const uint2*)&ghH[64 + lane * 2];
        uint2 uhn = *(const uint2*)&ghH[128 + lane * 2];
        float4 xv = *(const float4*)&x[(size_t)v * D + (lane << 2)];
        #pragma unroll
        for (int hh = 0; hh < 2; hh++) {
            float2 ir = __half22float2(*(__half2*)((hh == 0) ? &uir.x : &uir.y));
            float2 iz = __half22float2(*(__half2*)((hh == 0) ? &uiz.x : &uiz.y));
            float2 in_ = __half22float2(*(__half2*)((hh == 0) ? &uin.x : &uin.y));
            float2 hr = __half22float2(*(__half2*)((hh == 0) ? &uhr.x : &uhr.y));
            float2 hz = __half22float2(*(__half2*)((hh == 0) ? &uhz.x : &uhz.y));
            float2 hn = __half22float2(*(__half2*)((hh == 0) ? &uhn.x : &uhn.y));
            #pragma unroll
            for (int q = 0; q < 2; q++) {
                int i = hh * 2 + q;
                float gir = (q == 0) ? ir.x : ir.y;
                float giz = (q == 0) ? iz.x : iz.y;
                float gin = (q == 0) ? in_.x : in_.y;
                float ghr = (q == 0) ? hr.x : hr.y;
                float ghz = (q == 0) ? hz.x : hz.y;
                float ghn = (q == 0) ? hn.x : hn.y;
                float r = 1.f / (1.f + expf(-(gir + ghr)));
                float z = 1.f / (1.f + expf(-(giz + ghz)));
                float n = tanhf(gin + r * ghn);
                h[i] = fmaxf((1.f - z) * n + z * (&xv.x)[i], 0.f);
            }
        }
    }
    float s = h[0] + h[1] + h[2] + h[3];
    #pragma unroll
    for (int m = 16; m; m >>= 1) s += __shfl_xor_sync(0xffffffffu, s, m);
    float mu = s * (1.f / 128.f), q = 0.f;
    #pragma unroll
    for (int i = 0; i < 4; i++) { float d0 = h[i] - mu; q = fmaf(d0, d0, q); }
    #pragma unroll
    for (int m = 16; m; m >>= 1) q += __shfl_xor_sync(0xffffffffu, q, m);
    float rstd = rsqrtf(q * (1.f / 128.f) + EPS);
    float4 gv = *(const float4*)&lng[lane << 2];
    float4 b2 = *(const float4*)&lnb[lane << 2];
    float o[4];
    o[0] = (h[0]-mu)*rstd*gv.x + b2.x;
    o[1] = (h[1]-mu)*rstd*gv.y + b2.y;
    o[2] = (h[2]-mu)*rstd*gv.z + b2.z;
    o[3] = (h[3]-mu)*rstd*gv.w + b2.w;
    float4 kv = *(const float4*)&g_kf[(size_t)v * D + (lane << 2)];
    int mb = v >> 6;
    int r = v & 63;
    int mt = r >> 4, rb = (r >> 3) & 1, lh = r & 7;
    #pragma unroll
    for (int pp = 0; pp < 2; pp++) {
        int kp = lane * 2 + pp;
        int ll = kp & 3;
        int ri = (((kp >> 2) & 1) << 1) | rb;
        int ks = (kp >> 3) & 1;
        int c  = kp >> 4;
        int idx = mt * 256 + ks * 128 + ((lh << 2) | ll) * 4 + ri;
        size_t base = ((size_t)(mb * 8 + c)) << 11;
        Acat[base + idx] = pack_hi16(o[2 * pp], o[2 * pp + 1]);
        base = ((size_t)(mb * 8 + 4 + c)) << 11;
        Acat[base + idx] = pack_hi16((&kv.x)[2 * pp], (&kv.x)[2 * pp + 1]);
    }
}

// ---------------- host ----------------
extern "C" void kernel_launch(void* const* d_in, const int* in_sizes, int n_in,
                              void* d_out, int out_size) {
    const float* node   = (const float*)d_in[0];
    const int*   src    = (const int*)  d_in[1];
    const int*   dst    = (const int*)  d_in[2];
    const float* W_edge = (const float*)d_in[3];
    const float* b_edge = (const float*)d_in[4];
    const float* W_pn   = (const float*)d_in[5];
    const float* b_pn   = (const float*)d_in[6];
    const float* W_ih   = (const float*)d_in[7];
    const float* b_ih   = (const float*)d_in[8];
    const float* W_hh   = (const float*)d_in[9];
    const float* b_hh   = (const float*)d_in[10];
    const float* ln_g   = (const float*)d_in[11];
    const float* ln_b   = (const float*)d_in[12];
    const float* Wk1    = (const float*)d_in[13];
    const float* bk1    = (const float*)d_in[14];
    const float* lnk1_g = (const float*)d_in[15];
    const float* lnk1_b = (const float*)d_in[16];
    const float* Wk2    = (const float*)d_in[17];
    const float* bk2    = (const float*)d_in[18];
    const float* lnk2_g = (const float*)d_in[19];
    const float* lnk2_b = (const float*)d_in[20];
    const float* Wc     = (const float*)d_in[21];
    const float* bc     = (const float*)d_in[22];
    const float* lnc_g  = (const float*)d_in[23];
    const float* lnc_b  = (const float*)d_in[24];
    int V = in_sizes[0] / D;
    int E = in_sizes[1];
    float* out = (float*)d_out;

    float *p_asum, *p_ctx, *p_kf;
    uint32_t *p_hvH, *p_giH, *p_ghH;
    uint32_t *p_WpnS, *p_WihS, *p_WhhS, *p_WcS, *p_Wk2S;
    uint32_t *p_An, *p_Ac, *p_Aq;
    cudaGetSymbolAddress((void**)&p_asum, g_asum);
    cudaGetSymbolAddress((void**)&p_hvH,  g_hvH);
    cudaGetSymbolAddress((void**)&p_ctx,  g_ctx);
    cudaGetSymbolAddress((void**)&p_kf,   g_kf);
    cudaGetSymbolAddress((void**)&p_giH,  g_giH);
    cudaGetSymbolAddress((void**)&p_ghH,  g_ghH);
    cudaGetSymbolAddress((void**)&p_WpnS, g_WpnS);
    cudaGetSymbolAddress((void**)&p_WihS, g_WihS);
    cudaGetSymbolAddress((void**)&p_WhhS, g_WhhS);
    cudaGetSymbolAddress((void**)&p_WcS,  g_WcS);
    cudaGetSymbolAddress((void**)&p_Wk2S, g_Wk2S);
    cudaGetSymbolAddress((void**)&p_An,   g_Anode);
    cudaGetSymbolAddress((void**)&p_Ac,   g_Actx);
    cudaGetSymbolAddress((void**)&p_Aq,   g_Acat);

    static bool attr_set = false;
    if (!attr_set) {
        cudaFuncSetAttribute(kron_mma, cudaFuncAttributeMaxDynamicSharedMemorySize, 52000);
        attr_set = true;
    }

    int NBv = (V + 63) / 64;
    int n4c = V * 32;
    int n4s = V / 4;

    // fused zero: ctx + kf + asum
    zero_all<<<(2 * n4c + n4s + 255) / 256, 256>>>((float4*)p_ctx, (float4*)p_kf,
                                                   (float4*)p_asum, n4c, n4s);

    // fused weight packs: 32+96+96+64+100 = 388 blocks
    pack_w_all<<<388, 256>>>(W_pn, W_ih, W_hh, Wc, Wk2,
                             p_WpnS, p_WihS, p_WhhS, p_WcS, p_Wk2S);

    // pack node activations (hi only)
    pack_act<<<NBv, 256>>>(node, 128, 0, p_An, V, 0, 4);

    // fused npj + edgedot
    node_pre_kernel<<<(V + 7) / 8, 256>>>(node, Wk1, bk1, lnk1_g, lnk1_b, W_edge, V);

    logits_kernel<<<(E + 255) / 256, 256>>>(src, dst, b_edge, E);

    // hv = node @ W_pn + b_pn (1-pass, fp16 out)
    mma_gemm<<<dim3(NBv, 1), 256>>>(p_An, p_WpnS, 4, 128, 1,
                                    b_pn, nullptr, nullptr, (float*)p_hvH, V);

    // edge kron GEMM + LN + relu + scatter to kf
    kron_mma<<<(E + 127) / 128, 256, 51200>>>(src, dst, p_Wk2S,
                                              bk2, lnk2_g, lnk2_b, E);

    // context scatter
    context_kernel<<<(E + 7) / 8, 256>>>(src, dst, E);

    // pack relu(ctx) (hi only)
    pack_act<<<NBv, 256>>>(p_ctx, 128, 1, p_Ac, V, 0, 4);

    // gi / gh (1-pass, fp16 output)
    mma_gemm<<<dim3(NBv, 3), 256>>>(p_Ac, p_WihS, 4, 384, 1,
                                    b_ih, nullptr, nullptr, (float*)p_giH, V);
    mma_gemm<<<dim3(NBv, 3), 256>>>(p_An, p_WhhS, 4, 384, 1,
                                    b_hh, nullptr, nullptr, (float*)p_ghH, V);

    // gates -> Acat chunks 0-3; kf -> chunks 4-7 (hi only)
    gates_kernel<<<(V + 7) / 8, 256>>>(node, ln_g, ln_b, p_Aq, V);

    // out = relu(LN(cat @ Wc + bc)) (1-pass)
    mma_gemm<<<dim3(NBv, 1), 256>>>(p_Aq, p_WcS, 8, 128, 0,
                                    bc, lnc_g, lnc_b, out, V);
}

// round 15
// speedup vs baseline: 1.9040x; 1.0851x over previous
#include <cuda_runtime.h>
#include <cuda_fp16.h>
#include <math.h>
#include <stdint.h>

#define D     128
#define KP    20
#define VMAX  100000
#define EMAX  400000
#define EPS   1e-5f
#define NBMAX 1563   // (VMAX+63)/64

// ---------------- scratch (device globals; no allocations) ----------------
__device__ __half g_npjH[VMAX * KP];
__device__ float g_aexp [EMAX];
__device__ float g_asum [VMAX];
__device__ float2 g_uw  [VMAX];
__device__ uint32_t g_hvH[(size_t)VMAX * 64];
__device__ float g_ctx  [VMAX * D];
__device__ float g_kf   [VMAX * D];
__device__ uint32_t g_giH[(size_t)VMAX * 192];
__device__ uint32_t g_ghH[(size_t)VMAX * 192];

// fragment-ordered fp16 WEIGHT streams (hi only)
__device__ uint32_t g_WpnS[1 * 4 * 2048];
__device__ uint32_t g_WihS[3 * 4 * 2048];
__device__ uint32_t g_WhhS[3 * 4 * 2048];
__device__ uint32_t g_WcS [1 * 8 * 2048];
__device__ uint32_t g_Wk2S[5 * 5120];
__device__ uint32_t g_Wk1S[4 * 2048];      // Wk1 zero-padded to N=128

// padded npj params (20 -> 128)
__device__ float g_bk1p[128];
__device__ float g_k1g [128];
__device__ float g_k1b [128];

// fragment-ordered fp16 ACTIVATION streams (hi only)
__device__ uint32_t g_Anode[(size_t)NBMAX * 4 * 2048];
__device__ uint32_t g_Actx [(size_t)NBMAX * 4 * 2048];
__device__ uint32_t g_Acat [(size_t)NBMAX * 8 * 2048];

__device__ __forceinline__ uint32_t pack_hi16(float a0, float a1) {
    __half2 hp = __floats2half2_rn(a0, a1);
    return *(uint32_t*)&hp;
}

#define MMA_F16(c, A, B) asm volatile( \
    "mma.sync.aligned.m16n8k16.row.col.f32.f16.f16.f32 " \
    "{%0,%1,%2,%3}, {%4,%5,%6,%7}, {%8,%9}, {%0,%1,%2,%3};\n" \
    : "+f"(c[0]), "+f"(c[1]), "+f"(c[2]), "+f"(c[3]) \
    : "r"(A.x), "r"(A.y), "r"(A.z), "r"(A.w), "r"(B.x), "r"(B.y))

// ---------------- fused zero: ctx, kf, asum ----------------
__global__ void zero_all(float4* ctx, float4* kf, float4* asum, int n4c, int n4s) {
    int i = blockIdx.x * blockDim.x + threadIdx.x;
    if (i < n4c) { ctx[i] = make_float4(0.f, 0.f, 0.f, 0.f); return; }
    i -= n4c;
    if (i < n4c) { kf[i] = make_float4(0.f, 0.f, 0.f, 0.f); return; }
    i -= n4c;
    if (i < n4s) asum[i] = make_float4(0.f, 0.f, 0.f, 0.f);
}

// ---------------- weight pack device fns ----------------
__device__ void dev_pack_w(const float* __restrict__ W, int K, int Ntot,
                           int transp, uint32_t* __restrict__ out, int b) {
    int idx = b * 256 + threadIdx.x;
    if (idx >= (K / 2) * Ntot) return;
    int kp = idx / Ntot, n = idx - kp * Ntot;
    int k0 = 2 * kp;
    float w0, w1;
    if (transp) { w0 = W[n * K + k0]; w1 = W[n * K + k0 + 1]; }
    else        { w0 = W[k0 * Ntot + n]; w1 = W[(k0 + 1) * Ntot + n]; }
    int c = kp >> 4, kpl = kp & 15;
    int ny = n >> 7, nl = n & 127;
    int bi = ((((nl >> 3) * 2 + (kpl >> 3)) * 32 + ((nl & 7) << 2) + (kpl & 3)) << 1)
             + ((kpl >> 2) & 1);
    size_t base = ((size_t)(ny * (K >> 5) + c)) << 11;
    out[base + bi] = pack_hi16(w0, w1);
}
__device__ void dev_pack_wk2(const float* __restrict__ W,
                             uint32_t* __restrict__ out, int b) {
    int idx = b * 256 + threadIdx.x;
    if (idx >= 200 * 128) return;
    int kp = idx >> 7, n = idx & 127;
    float w0 = W[(2 * kp) * 128 + n];
    float w1 = W[(2 * kp + 1) * 128 + n];
    int c = kp / 40, kpl = kp - c * 40;
    int bi = ((((n >> 3) * 5 + (kpl >> 3)) * 32 + ((n & 7) << 2) + (kpl & 3)) << 1)
             + ((kpl >> 2) & 1);
    out[c * 5120 + bi] = pack_hi16(w0, w1);
}
// Wk1 [128][20] -> padded N=128 stream (cols >= 20 zero)
__device__ void dev_pack_wk1(const float* __restrict__ W,
                             uint32_t* __restrict__ out, int b) {
    int idx = b * 256 + threadIdx.x;
    if (idx >= 64 * 128) return;
    int kp = idx >> 7, n = idx & 127;
    float w0 = (n < KP) ? W[(2 * kp) * KP + n] : 0.f;
    float w1 = (n < KP) ? W[(2 * kp + 1) * KP + n] : 0.f;
    int c = kp >> 4, kpl = kp & 15;
    int bi = ((((n >> 3) * 2 + (kpl >> 3)) * 32 + ((n & 7) << 2) + (kpl & 3)) << 1)
             + ((kpl >> 2) & 1);
    out[((size_t)c << 11) + bi] = pack_hi16(w0, w1);
}

// fused pack: Wpn[0,32) Wih[32,128) Whh[128,224) Wc[224,288) Wk2[288,388)
//             Wk1[388,420), pad-params block 420
__global__ void pack_w_all(const float* W_pn, const float* W_ih, const float* W_hh,
                           const float* Wc, const float* Wk2, const float* Wk1,
                           const float* bk1, const float* k1g, const float* k1b,
                           uint32_t* WpnS, uint32_t* WihS, uint32_t* WhhS,
                           uint32_t* WcS, uint32_t* Wk2S, uint32_t* Wk1S) {
    int b = blockIdx.x;
    if (b < 32)  { dev_pack_w(W_pn, 128, 128, 0, WpnS, b); return; }
    b -= 32;
    if (b < 96)  { dev_pack_w(W_ih, 128, 384, 1, WihS, b); return; }
    b -= 96;
    if (b < 96)  { dev_pack_w(W_hh, 128, 384, 1, WhhS, b); return; }
    b -= 96;
    if (b < 64)  { dev_pack_w(Wc, 256, 128, 0, WcS, b); return; }
    b -= 64;
    if (b < 100) { dev_pack_wk2(Wk2, Wk2S, b); return; }
    b -= 100;
    if (b < 32)  { dev_pack_wk1(Wk1, Wk1S, b); return; }
    // pad params
    int t = threadIdx.x;
    if (t < 128) {
        g_bk1p[t] = (t < KP) ? bk1[t] : 0.f;
        g_k1g[t]  = (t < KP) ? k1g[t] : 0.f;
        g_k1b[t]  = (t < KP) ? k1b[t] : 0.f;
    }
}

// activation pack (fp16 hi only)
__global__ void pack_act(const float* __restrict__ X0, int K0, int relu,
                         uint32_t* __restrict__ out, int V,
                         int coff, int KchTot) {
    int t = threadIdx.x;
    int mb = blockIdx.x;
    int Kch = K0 >> 5;
    for (int it = 0; it < Kch * 4; it++) {
        int c = it >> 2;
        int idx = ((it & 3) << 8) + t;
        int mt = idx >> 8;
        int ks = (idx >> 7) & 1;
        int ln = (idx >> 2) & 31;
        int ri = idx & 3;
        int row = mb * 64 + mt * 16 + (ri & 1) * 8 + (ln >> 2);
        if (row >= V) row = V - 1;
        int k = c * 32 + ks * 16 + ((ri >> 1) << 3) + ((ln & 3) << 1);
        float2 a = *(const float2*)&X0[(size_t)row * K0 + k];
        if (relu) { a.x = fmaxf(a.x, 0.f); a.y = fmaxf(a.y, 0.f); }
        size_t base = ((size_t)(mb * KchTot + coff + c)) << 11;
        out[base + idx] = pack_hi16(a.x, a.y);
    }
}

// ---- per-node edge-logit dots (npj moved to tensor path) ----
__global__ void edgedot_kernel(const float* __restrict__ x,
                               const float* __restrict__ We, int V) {
    int v = blockIdx.x * 8 + (threadIdx.x >> 5);
    if (v >= V) return;
    int lane = threadIdx.x & 31;
    float4 xv = *(const float4*)&x[(size_t)v * D + (lane << 2)];
    float4 w1 = *(const float4*)&We[lane << 2];
    float4 w2 = *(const float4*)&We[D + (lane << 2)];
    float u = xv.x * w1.x + xv.y * w1.y + xv.z * w1.z + xv.w * w1.w;
    float w = xv.x * w2.x + xv.y * w2.y + xv.z * w2.z + xv.w * w2.w;
    #pragma unroll
    for (int m = 16; m; m >>= 1) {
        u += __shfl_xor_sync(0xffffffffu, u, m);
        w += __shfl_xor_sync(0xffffffffu, w, m);
    }
    if (lane == 0) g_uw[v] = make_float2(u, w);
}

// ---- edge logits + exp + segment sum ----
__global__ void logits_kernel(const int* __restrict__ src,
                              const int* __restrict__ dst,
                              const float* __restrict__ be, int E) {
    int e = blockIdx.x * blockDim.x + threadIdx.x;
    if (e >= E) return;
    int sn = src[e], dn = dst[e];
    float2 ud = __ldg(&g_uw[dn]);
    float2 us = __ldg(&g_uw[sn]);
    float lg = fmaxf(ud.x + us.y + be[0], 0.f);
    float a = expf(lg);
    g_aexp[e] = a;
    atomicAdd(&g_asum[dn], a);
}

// ---------------- context scatter ----------------
__global__ void context_kernel(const int* __restrict__ src,
                               const int* __restrict__ dst, int E) {
    int e = blockIdx.x * 8 + (threadIdx.x >> 5);
    if (e >= E) return;
    int lane = threadIdx.x & 31;
    int sn = src[e], dn = dst[e];
    float coef = g_aexp[e] / g_asum[dn];
    uint2 hraw = *(const uint2*)&g_hvH[(size_t)sn * 64 + lane * 2];
    float2 h01 = __half22float2(*(__half2*)&hraw.x);
    float2 h23 = __half22float2(*(__half2*)&hraw.y);
    atomicAdd((float4*)&g_ctx[(size_t)dn * D + (lane << 2)],
              make_float4(h01.x * coef, h01.y * coef, h23.x * coef, h23.y * coef));
}

// =====================================================================
// Node GEMM, fp16 1-pass. mode: 0=f32 store, 1=half2 store,
// 2=npj epilogue (LN over 20 cols, relu, fp16 store to g_npjH).
// =====================================================================
__global__ __launch_bounds__(256)
void mma_gemm(const uint32_t* __restrict__ As, const uint32_t* __restrict__ Bs,
              int Kchunks, int Ntot, int mode,
              const float* __restrict__ bias,
              const float* __restrict__ lng, const float* __restrict__ lnb,
              float* __restrict__ out, int V) {
    __shared__ uint32_t sa[1024];
    __shared__ uint32_t sb[2048];
    __shared__ float red[2][64][2];

    int t = threadIdx.x;
    int lane = t & 31, w = t >> 5;
    int wm = w & 3, wn = w >> 2;
    int row0 = blockIdx.x * 64;
    int nb = blockIdx.y * 128;

    float acc[8][4];
    #pragma unroll
    for (int j = 0; j < 8; j++) { acc[j][0]=acc[j][1]=acc[j][2]=acc[j][3]=0.f; }

    const uint4* ag = (const uint4*)(As + (size_t)blockIdx.x * Kchunks * 2048);
    const uint4* bg = (const uint4*)(Bs + (size_t)blockIdx.y * Kchunks * 2048);

    uint4 pa0, pb0, pb1;
    pa0 = ag[t];
    pb0 = bg[t]; pb1 = bg[t + 256];
    for (int c = 0; c < Kchunks; c++) {
        __syncthreads();
        ((uint4*)sa)[t] = pa0;
        ((uint4*)sb)[t] = pb0; ((uint4*)sb)[t + 256] = pb1;
        __syncthreads();
        if (c + 1 < Kchunks) {
            const uint4* a4 = ag + (size_t)(c + 1) * 512;
            const uint4* b4 = bg + (size_t)(c + 1) * 512;
            pa0 = a4[t];
            pb0 = b4[t]; pb1 = b4[t + 256];
        }
        #pragma unroll
        for (int ks = 0; ks < 2; ks++) {
            uint4 ah = ((const uint4*)sa)[(wm * 2 + ks) * 32 + lane];
            #pragma unroll
            for (int j = 0; j < 8; j++) {
                int nt = wn * 8 + j;
                uint2 bh = ((const uint2*)sb)[(nt * 2 + ks) * 32 + lane];
                MMA_F16(acc[j], ah, bh);
            }
        }
    }

    int rl = row0 + wm * 16 + (lane >> 2);
    int rh = rl + 8;
    #pragma unroll
    for (int j = 0; j < 8; j++) {
        int gc = nb + wn * 64 + j * 8 + ((lane & 3) << 1);
        float b0 = bias[gc], b1 = bias[gc + 1];
        acc[j][0] += b0; acc[j][1] += b1; acc[j][2] += b0; acc[j][3] += b1;
    }
    if (mode == 2) {
        // npj: LN over cols 0..19 (only wn==0 holds them), relu, fp16 scatter
        if (wn == 0) {
            int c4 = lane & 3;
            float s_lo=0.f, q_lo=0.f, s_hi=0.f, q_hi=0.f;
            #pragma unroll
            for (int j = 0; j < 3; j++)
                #pragma unroll
                for (int c = 0; c < 2; c++) {
                    int col = j * 8 + c4 * 2 + c;
                    if (col < KP) {
                        float v = acc[j][c];      s_lo += v;  q_lo += v * v;
                        float vh = acc[j][2 + c]; s_hi += vh; q_hi += vh * vh;
                    }
                }
            #pragma unroll
            for (int m = 1; m <= 2; m <<= 1) {
                s_lo += __shfl_xor_sync(0xffffffffu, s_lo, m);
                q_lo += __shfl_xor_sync(0xffffffffu, q_lo, m);
                s_hi += __shfl_xor_sync(0xffffffffu, s_hi, m);
                q_hi += __shfl_xor_sync(0xffffffffu, q_hi, m);
            }
            float mu_lo = s_lo * (1.f / KP);
            float rs_lo = rsqrtf(q_lo * (1.f / KP) - mu_lo * mu_lo + EPS);
            float mu_hi = s_hi * (1.f / KP);
            float rs_hi = rsqrtf(q_hi * (1.f / KP) - mu_hi * mu_hi + EPS);
            #pragma unroll
            for (int j = 0; j < 3; j++)
                #pragma unroll
                for (int c = 0; c < 2; c++) {
                    int col = j * 8 + c4 * 2 + c;
                    if (col < KP) {
                        float gg = lng[col], bb = lnb[col];
                        if (rl < V)
                            g_npjH[rl * KP + col] = __float2half_rn(
                                fmaxf((acc[j][c] - mu_lo) * rs_lo * gg + bb, 0.f));
                        if (rh < V)
                            g_npjH[rh * KP + col] = __float2half_rn(
                                fmaxf((acc[j][2 + c] - mu_hi) * rs_hi * gg + bb, 0.f));
                    }
                }
        }
        return;
    }
    if (lng == nullptr) {
        if (mode == 1) {
            uint32_t* oh = (uint32_t*)out;
            int ld2 = Ntot >> 1;
            #pragma unroll
            for (int j = 0; j < 8; j++) {
                int gc = nb + wn * 64 + j * 8 + ((lane & 3) << 1);
                if (rl < V) oh[(size_t)rl * ld2 + (gc >> 1)] = pack_hi16(acc[j][0], acc[j][1]);
                if (rh < V) oh[(size_t)rh * ld2 + (gc >> 1)] = pack_hi16(acc[j][2], acc[j][3]);
            }
        } else {
            #pragma unroll
            for (int j = 0; j < 8; j++) {
                int gc = nb + wn * 64 + j * 8 + ((lane & 3) << 1);
                if (rl < V) *(float2*)&out[(size_t)rl * Ntot + gc] = make_float2(acc[j][0], acc[j][1]);
                if (rh < V) *(float2*)&out[(size_t)rh * Ntot + gc] = make_float2(acc[j][2], acc[j][3]);
            }
        }
    } else {
        float s_lo=0.f, q_lo=0.f, s_hi=0.f, q_hi=0.f;
        #pragma unroll
        for (int j = 0; j < 8; j++) {
            s_lo += acc[j][0] + acc[j][1];
            q_lo += acc[j][0]*acc[j][0] + acc[j][1]*acc[j][1];
            s_hi += acc[j][2] + acc[j][3];
            q_hi += acc[j][2]*acc[j][2] + acc[j][3]*acc[j][3];
        }
        #pragma unroll
        for (int m = 1; m <= 2; m <<= 1) {
            s_lo += __shfl_xor_sync(0xffffffffu, s_lo, m);
            q_lo += __shfl_xor_sync(0xffffffffu, q_lo, m);
            s_hi += __shfl_xor_sync(0xffffffffu, s_hi, m);
            q_hi += __shfl_xor_sync(0xffffffffu, q_hi, m);
        }
        int rloc = wm * 16 + (lane >> 2);
        if ((lane & 3) == 0) {
            red[wn][rloc][0] = s_lo;   red[wn][rloc][1] = q_lo;
            red[wn][rloc+8][0] = s_hi; red[wn][rloc+8][1] = q_hi;
        }
        __syncthreads();
        float ts_lo = s_lo + red[wn ^ 1][rloc][0];
        float tq_lo = q_lo + red[wn ^ 1][rloc][1];
        float ts_hi = s_hi + red[wn ^ 1][rloc + 8][0];
        float tq_hi = q_hi + red[wn ^ 1][rloc + 8][1];
        float mu_lo = ts_lo * (1.f/128.f);
        float mu_hi = ts_hi * (1.f/128.f);
        float rs_lo = rsqrtf(tq_lo * (1.f/128.f) - mu_lo*mu_lo + EPS);
        float rs_hi = rsqrtf(tq_hi * (1.f/128.f) - mu_hi*mu_hi + EPS);
        #pragma unroll
        for (int j = 0; j < 8; j++) {
            int gc = wn * 64 + j * 8 + ((lane & 3) << 1);
            float g0 = lng[gc], g1 = lng[gc+1];
            float bb0 = lnb[gc], bb1 = lnb[gc+1];
            if (rl < V) {
                float o0 = fmaxf((acc[j][0]-mu_lo)*rs_lo*g0 + bb0, 0.f);
                float o1 = fmaxf((acc[j][1]-mu_lo)*rs_lo*g1 + bb1, 0.f);
                *(float2*)&out[(size_t)rl * 128 + gc] = make_float2(o0, o1);
            }
            if (rh < V) {
                float o2 = fmaxf((acc[j][2]-mu_hi)*rs_hi*g0 + bb0, 0.f);
                float o3 = fmaxf((acc[j][3]-mu_hi)*rs_hi*g1 + bb1, 0.f);
                *(float2*)&out[(size_t)rh * 128 + gc] = make_float2(o2, o3);
            }
        }
    }
}

// =====================================================================
// Kron edge GEMM fp16 1-PASS, npj fp16, A-build via HMUL2.
// =====================================================================
__global__ __launch_bounds__(256, 2)
void kron_mma(const int* __restrict__ src, const int* __restrict__ dst,
              const uint32_t* __restrict__ Wk2S,
              const float* __restrict__ bk2,
              const float* __restrict__ lng, const float* __restrict__ lnb,
              int E) {
    extern __shared__ uint32_t dsm[];
    uint32_t* sa = dsm;               // 5120 u32
    uint32_t* sb = dsm + 5120;        // 5120 u32
    __half* Ss = (__half*)(dsm + 10240);
    __half* Ds = Ss + 2560;
    __shared__ int ssrc[128], sdst[128];
    __shared__ float red[2][128][2];

    int t = threadIdx.x;
    int lane = t & 31, w = t >> 5;
    int wm = w & 3, wn = w >> 2;
    int e0 = blockIdx.x * 128;

    if (t < 128) {
        int ee = e0 + t; if (ee >= E) ee = E - 1;
        ssrc[t] = src[ee];
        sdst[t] = dst[ee];
    }
    __syncthreads();
    const uint32_t* npjU = (const uint32_t*)g_npjH;
    for (int idx = t; idx < 1280; idx += 256) {
        int e = idx / 10, q = idx - e * 10;
        ((uint32_t*)Ss)[idx] = npjU[ssrc[e] * 10 + q];
        ((uint32_t*)Ds)[idx] = npjU[sdst[e] * 10 + q];
    }

    float acc[2][8][4];
    #pragma unroll
    for (int r = 0; r < 2; r++)
        #pragma unroll
        for (int j = 0; j < 8; j++) { acc[r][j][0]=acc[r][j][1]=acc[r][j][2]=acc[r][j][3]=0.f; }

    int be = t >> 1, ih = t & 1;
    int amt = be >> 4;
    int ribase = (be >> 3) & 1;
    int alnb = (be & 7) << 2;

    for (int c = 0; c < 5; c++) {
        __syncthreads();
        {
            const __half* ds = &Ds[be * 20];
            const __half* ss = &Ss[be * 20];
            #pragma unroll
            for (int iv = 0; iv < 2; iv++) {
                int il = ih * 2 + iv;
                __half2 sv2 = __half2half2(ss[c * 4 + il]);
                #pragma unroll
                for (int q = 0; q < 10; q++) {
                    __half2 d2 = *(const __half2*)&ds[2 * q];
                    __half2 p2 = __hmul2(sv2, d2);
                    int kp = il * 10 + q;
                    int ai = (((amt * 5 + (kp >> 3)) * 32 + alnb + (kp & 3)) << 2)
                             + ribase + (((kp >> 2) & 1) << 1);
                    sa[ai] = *(uint32_t*)&p2;
                }
            }
        }
        {
            const uint4* bsrc = (const uint4*)(Wk2S + c * 5120);
            #pragma unroll
            for (int i = 0; i < 5; i++)
                ((uint4*)sb)[t + (i << 8)] = bsrc[t + (i << 8)];
        }
        __syncthreads();
        #pragma unroll
        for (int ks = 0; ks < 5; ks++) {
            uint4 ah0 = ((const uint4*)sa)[((wm * 2 + 0) * 5 + ks) * 32 + lane];
            uint4 ah1 = ((const uint4*)sa)[((wm * 2 + 1) * 5 + ks) * 32 + lane];
            #pragma unroll
            for (int j = 0; j < 8; j++) {
                int nt = wn * 8 + j;
                uint2 bh = ((const uint2*)sb)[(nt * 5 + ks) * 32 + lane];
                MMA_F16(acc[0][j], ah0, bh);
                MMA_F16(acc[1][j], ah1, bh);
            }
        }
    }

    #pragma unroll
    for (int r = 0; r < 2; r++)
        #pragma unroll
        for (int j = 0; j < 8; j++) {
            int gc = wn * 64 + j * 8 + ((lane & 3) << 1);
            float b0 = bk2[gc], b1 = bk2[gc + 1];
            acc[r][j][0] += b0; acc[r][j][1] += b1;
            acc[r][j][2] += b0; acc[r][j][3] += b1;
        }
    float sum[2][2], sq[2][2];
    #pragma unroll
    for (int r = 0; r < 2; r++) {
        float s_lo=0.f, q_lo=0.f, s_hi=0.f, q_hi=0.f;
        #pragma unroll
        for (int j = 0; j < 8; j++) {
            s_lo += acc[r][j][0] + acc[r][j][1];
            q_lo += acc[r][j][0]*acc[r][j][0] + acc[r][j][1]*acc[r][j][1];
            s_hi += acc[r][j][2] + acc[r][j][3];
            q_hi += acc[r][j][2]*acc[r][j][2] + acc[r][j][3]*acc[r][j][3];
        }
        #pragma unroll
        for (int m = 1; m <= 2; m <<= 1) {
            s_lo += __shfl_xor_sync(0xffffffffu, s_lo, m);
            q_lo += __shfl_xor_sync(0xffffffffu, q_lo, m);
            s_hi += __shfl_xor_sync(0xffffffffu, s_hi, m);
            q_hi += __shfl_xor_sync(0xffffffffu, q_hi, m);
        }
        sum[r][0] = s_lo; sq[r][0] = q_lo;
        sum[r][1] = s_hi; sq[r][1] = q_hi;
        if ((lane & 3) == 0) {
            int rloc = wm * 32 + r * 16 + (lane >> 2);
            red[wn][rloc][0] = s_lo;     red[wn][rloc][1] = q_lo;
            red[wn][rloc + 8][0] = s_hi; red[wn][rloc + 8][1] = q_hi;
        }
    }
    __syncthreads();
    #pragma unroll
    for (int r = 0; r < 2; r++) {
        #pragma unroll
        for (int h = 0; h < 2; h++) {
            int rloc = wm * 32 + r * 16 + h * 8 + (lane >> 2);
            float ts = sum[r][h] + red[wn ^ 1][rloc][0];
            float tq = sq[r][h] + red[wn ^ 1][rloc][1];
            float mu = ts * (1.f / 128.f);
            float rs = rsqrtf(tq * (1.f / 128.f) - mu * mu + EPS);
            int ge = e0 + rloc;
            if (ge < E) {
                int dn = sdst[rloc];
                #pragma unroll
                for (int j = 0; j < 8; j++) {
                    int gc = wn * 64 + j * 8 + ((lane & 3) << 1);
                    float g0 = lng[gc], g1 = lng[gc + 1];
                    float bb0 = lnb[gc], bb1 = lnb[gc + 1];
                    float* p = &g_kf[(size_t)dn * 128 + gc];
                    atomicAdd(p,     fmaxf((acc[r][j][2*h  ]-mu)*rs*g0 + bb0, 0.f));
                    atomicAdd(p + 1, fmaxf((acc[r][j][2*h+1]-mu)*rs*g1 + bb1, 0.f));
                }
            }
        }
    }
}

// ---- GRU gates (fp16 gi/gh) + relu + LN -> Acat chunks 0-3; kf -> 4-7 ----
__global__ void gates_kernel(const float* __restrict__ x,
                             const float* __restrict__ lng,
                             const float* __restrict__ lnb,
                             uint32_t* __restrict__ Acat, int V) {
    int v = blockIdx.x * 8 + (threadIdx.x >> 5);
    if (v >= V) return;
    int lane = threadIdx.x & 31;
    const uint32_t* giH = &g_giH[(size_t)v * 192];
    const uint32_t* ghH = &g_ghH[(size_t)v * 192];
    float h[4];
    {
        uint2 uir = *(const uint2*)&giH[lane * 2];
        uint2 uiz = *(const uint2*)&giH[64 + lane * 2];
        uint2 uin = *(const uint2*)&giH[128 + lane * 2];
        uint2 uhr = *(const uint2*)&ghH[lane * 2];
        uint2 uhz = *(const uint2*)&ghH[64 + lane * 2];
        uint2 uhn = *(const uint2*)&ghH[128 + lane * 2];
        float4 xv = *(const float4*)&x[(size_t)v * D + (lane << 2)];
        #pragma unroll
        for (int hh = 0; hh < 2; hh++) {
            float2 ir = __half22float2(*(__half2*)((hh == 0) ? &uir.x : &uir.y));
            float2 iz = __half22float2(*(__half2*)((hh == 0) ? &uiz.x : &uiz.y));
            float2 in_ = __half22float2(*(__half2*)((hh == 0) ? &uin.x : &uin.y));
            float2 hr = __half22float2(*(__half2*)((hh == 0) ? &uhr.x : &uhr.y));
            float2 hz = __half22float2(*(__half2*)((hh == 0) ? &uhz.x : &uhz.y));
            float2 hn = __half22float2(*(__half2*)((hh == 0) ? &uhn.x : &uhn.y));
            #pragma unroll
            for (int q = 0; q < 2; q++) {
                int i = hh * 2 + q;
                float gir = (q == 0) ? ir.x : ir.y;
                float giz = (q == 0) ? iz.x : iz.y;
                float gin = (q == 0) ? in_.x : in_.y;
                float ghr = (q == 0) ? hr.x : hr.y;
                float ghz = (q == 0) ? hz.x : hz.y;
                float ghn = (q == 0) ? hn.x : hn.y;
                float r = 1.f / (1.f + expf(-(gir + ghr)));
                float z = 1.f / (1.f + expf(-(giz + ghz)));
                float n = tanhf(gin + r * ghn);
                h[i] = fmaxf((1.f - z) * n + z * (&xv.x)[i], 0.f);
            }
        }
    }
    float s = h[0] + h[1] + h[2] + h[3];
    #pragma unroll
    for (int m = 16; m; m >>= 1) s += __shfl_xor_sync(0xffffffffu, s, m);
    float mu = s * (1.f / 128.f), q = 0.f;
    #pragma unroll
    for (int i = 0; i < 4; i++) { float d0 = h[i] - mu; q = fmaf(d0, d0, q); }
    #pragma unroll
    for (int m = 16; m; m >>= 1) q += __shfl_xor_sync(0xffffffffu, q, m);
    float rstd = rsqrtf(q * (1.f / 128.f) + EPS);
    float4 gv = *(const float4*)&lng[lane << 2];
    float4 b2 = *(const float4*)&lnb[lane << 2];
    float o[4];
    o[0] = (h[0]-mu)*rstd*gv.x + b2.x;
    o[1] = (h[1]-mu)*rstd*gv.y + b2.y;
    o[2] = (h[2]-mu)*rstd*gv.z + b2.z;
    o[3] = (h[3]-mu)*rstd*gv.w + b2.w;
    float4 kv = *(const float4*)&g_kf[(size_t)v * D + (lane << 2)];
    int mb = v >> 6;
    int r = v & 63;
    int mt = r >> 4, rb = (r >> 3) & 1, lh = r & 7;
    #pragma unroll
    for (int pp = 0; pp < 2; pp++) {
        int kp = lane * 2 + pp;
        int ll = kp & 3;
        int ri = (((kp >> 2) & 1) << 1) | rb;
        int ks = (kp >> 3) & 1;
        int c  = kp >> 4;
        int idx = mt * 256 + ks * 128 + ((lh << 2) | ll) * 4 + ri;
        size_t base = ((size_t)(mb * 8 + c)) << 11;
        Acat[base + idx] = pack_hi16(o[2 * pp], o[2 * pp + 1]);
        base = ((size_t)(mb * 8 + 4 + c)) << 11;
        Acat[base + idx] = pack_hi16((&kv.x)[2 * pp], (&kv.x)[2 * pp + 1]);
    }
}

// ---------------- host ----------------
extern "C" void kernel_launch(void* const* d_in, const int* in_sizes, int n_in,
                              void* d_out, int out_size) {
    const float* node   = (const float*)d_in[0];
    const int*   src    = (const int*)  d_in[1];
    const int*   dst    = (const int*)  d_in[2];
    const float* W_edge = (const float*)d_in[3];
    const float* b_edge = (const float*)d_in[4];
    const float* W_pn   = (const float*)d_in[5];
    const float* b_pn   = (const float*)d_in[6];
    const float* W_ih   = (const float*)d_in[7];
    const float* b_ih   = (const float*)d_in[8];
    const float* W_hh   = (const float*)d_in[9];
    const float* b_hh   = (const float*)d_in[10];
    const float* ln_g   = (const float*)d_in[11];
    const float* ln_b   = (const float*)d_in[12];
    const float* Wk1    = (const float*)d_in[13];
    const float* bk1    = (const float*)d_in[14];
    const float* lnk1_g = (const float*)d_in[15];
    const float* lnk1_b = (const float*)d_in[16];
    const float* Wk2    = (const float*)d_in[17];
    const float* bk2    = (const float*)d_in[18];
    const float* lnk2_g = (const float*)d_in[19];
    const float* lnk2_b = (const float*)d_in[20];
    const float* Wc     = (const float*)d_in[21];
    const float* bc     = (const float*)d_in[22];
    const float* lnc_g  = (const float*)d_in[23];
    const float* lnc_b  = (const float*)d_in[24];
    int V = in_sizes[0] / D;
    int E = in_sizes[1];
    float* out = (float*)d_out;

    float *p_asum, *p_ctx, *p_kf, *p_bk1p, *p_k1g, *p_k1b;
    uint32_t *p_hvH, *p_giH, *p_ghH;
    uint32_t *p_WpnS, *p_WihS, *p_WhhS, *p_WcS, *p_Wk2S, *p_Wk1S;
    uint32_t *p_An, *p_Ac, *p_Aq;
    cudaGetSymbolAddress((void**)&p_asum, g_asum);
    cudaGetSymbolAddress((void**)&p_hvH,  g_hvH);
    cudaGetSymbolAddress((void**)&p_ctx,  g_ctx);
    cudaGetSymbolAddress((void**)&p_kf,   g_kf);
    cudaGetSymbolAddress((void**)&p_giH,  g_giH);
    cudaGetSymbolAddress((void**)&p_ghH,  g_ghH);
    cudaGetSymbolAddress((void**)&p_WpnS, g_WpnS);
    cudaGetSymbolAddress((void**)&p_WihS, g_WihS);
    cudaGetSymbolAddress((void**)&p_WhhS, g_WhhS);
    cudaGetSymbolAddress((void**)&p_WcS,  g_WcS);
    cudaGetSymbolAddress((void**)&p_Wk2S, g_Wk2S);
    cudaGetSymbolAddress((void**)&p_Wk1S, g_Wk1S);
    cudaGetSymbolAddress((void**)&p_bk1p, g_bk1p);
    cudaGetSymbolAddress((void**)&p_k1g,  g_k1g);
    cudaGetSymbolAddress((void**)&p_k1b,  g_k1b);
    cudaGetSymbolAddress((void**)&p_An,   g_Anode);
    cudaGetSymbolAddress((void**)&p_Ac,   g_Actx);
    cudaGetSymbolAddress((void**)&p_Aq,   g_Acat);

    static bool attr_set = false;
    if (!attr_set) {
        cudaFuncSetAttribute(kron_mma, cudaFuncAttributeMaxDynamicSharedMemorySize, 52000);
        attr_set = true;
    }

    int NBv = (V + 63) / 64;
    int n4c = V * 32;
    int n4s = V / 4;

    // fused zero: ctx + kf + asum
    zero_all<<<(2 * n4c + n4s + 255) / 256, 256>>>((float4*)p_ctx, (float4*)p_kf,
                                                   (float4*)p_asum, n4c, n4s);

    // fused weight packs (421 blocks incl. Wk1 + pads)
    pack_w_all<<<421, 256>>>(W_pn, W_ih, W_hh, Wc, Wk2, Wk1, bk1, lnk1_g, lnk1_b,
                             p_WpnS, p_WihS, p_WhhS, p_WcS, p_Wk2S, p_Wk1S);

    // pack node activations (hi only)
    pack_act<<<NBv, 256>>>(node, 128, 0, p_An, V, 0, 4);

    // edgedot + logits
    edgedot_kernel<<<(V + 7) / 8, 256>>>(node, W_edge, V);
    logits_kernel<<<(E + 255) / 256, 256>>>(src, dst, b_edge, E);

    // npj via tensor GEMM (mode 2)
    mma_gemm<<<dim3(NBv, 1), 256>>>(p_An, p_Wk1S, 4, 128, 2,
                                    p_bk1p, p_k1g, p_k1b, nullptr, V);

    // hv = node @ W_pn + b_pn (1-pass, fp16 out)
    mma_gemm<<<dim3(NBv, 1), 256>>>(p_An, p_WpnS, 4, 128, 1,
                                    b_pn, nullptr, nullptr, (float*)p_hvH, V);

    // edge kron GEMM + LN + relu + scatter to kf
    kron_mma<<<(E + 127) / 128, 256, 51200>>>(src, dst, p_Wk2S,
                                              bk2, lnk2_g, lnk2_b, E);

    // context scatter
    context_kernel<<<(E + 7) / 8, 256>>>(src, dst, E);

    // pack relu(ctx) (hi only)
    pack_act<<<NBv, 256>>>(p_ctx, 128, 1, p_Ac, V, 0, 4);

    // gi / gh (1-pass, fp16 output)
    mma_gemm<<<dim3(NBv, 3), 256>>>(p_Ac, p_WihS, 4, 384, 1,
                                    b_ih, nullptr, nullptr, (float*)p_giH, V);
    mma_gemm<<<dim3(NBv, 3), 256>>>(p_An, p_WhhS, 4, 384, 1,
                                    b_hh, nullptr, nullptr, (float*)p_ghH, V);

    // gates -> Acat chunks 0-3; kf -> chunks 4-7
    gates_kernel<<<(V + 7) / 8, 256>>>(node, ln_g, ln_b, p_Aq, V);

    // out = relu(LN(cat @ Wc + bc)) (1-pass)
    mma_gemm<<<dim3(NBv, 1), 256>>>(p_Aq, p_WcS, 8, 128, 0,
                                    bc, lnc_g, lnc_b, out, V);
}

// round 16
// speedup vs baseline: 1.9360x; 1.0168x over previous
#include <cuda_runtime.h>
#include <cuda_fp16.h>
#include <math.h>
#include <stdint.h>

#define D     128
#define KP    20
#define VMAX  100000
#define EMAX  400000
#define EPS   1e-5f
#define NBMAX 1563   // (VMAX+63)/64

// ---------------- scratch (device globals; no allocations) ----------------
__device__ __half g_npjH[VMAX * KP];
__device__ float g_aexp [EMAX];
__device__ float g_asum [VMAX];
__device__ float2 g_uw  [VMAX];
__device__ uint32_t g_hvH[(size_t)VMAX * 64];
__device__ float g_ctx  [VMAX * D];
__device__ float g_kf   [VMAX * D];
__device__ uint32_t g_giH[(size_t)VMAX * 192];
__device__ uint32_t g_ghH[(size_t)VMAX * 192];

// fragment-ordered fp16 WEIGHT streams (hi only)
__device__ uint32_t g_WpnS[1 * 4 * 2048];
__device__ uint32_t g_WihS[3 * 4 * 2048];
__device__ uint32_t g_WhhS[3 * 4 * 2048];
__device__ uint32_t g_WcS [1 * 8 * 2048];
__device__ uint32_t g_Wk2S[5 * 5120];
__device__ uint32_t g_Wk1S[4 * 2048];      // Wk1 zero-padded to N=128

// padded npj params (20 -> 128)
__device__ float g_bk1p[128];
__device__ float g_k1g [128];
__device__ float g_k1b [128];

// fragment-ordered fp16 ACTIVATION streams (hi only)
__device__ uint32_t g_Anode[(size_t)NBMAX * 4 * 2048];
__device__ uint32_t g_Actx [(size_t)NBMAX * 4 * 2048];
__device__ uint32_t g_Acat [(size_t)NBMAX * 8 * 2048];

__device__ __forceinline__ uint32_t pack_hi16(float a0, float a1) {
    __half2 hp = __floats2half2_rn(a0, a1);
    return *(uint32_t*)&hp;
}

#define MMA_F16(c, A, B) asm volatile( \
    "mma.sync.aligned.m16n8k16.row.col.f32.f16.f16.f32 " \
    "{%0,%1,%2,%3}, {%4,%5,%6,%7}, {%8,%9}, {%0,%1,%2,%3};\n" \
    : "+f"(c[0]), "+f"(c[1]), "+f"(c[2]), "+f"(c[3]) \
    : "r"(A.x), "r"(A.y), "r"(A.z), "r"(A.w), "r"(B.x), "r"(B.y))

// ---------------- fused zero: ctx, kf, asum ----------------
__global__ void zero_all(float4* ctx, float4* kf, float4* asum, int n4c, int n4s) {
    int i = blockIdx.x * blockDim.x + threadIdx.x;
    if (i < n4c) { ctx[i] = make_float4(0.f, 0.f, 0.f, 0.f); return; }
    i -= n4c;
    if (i < n4c) { kf[i] = make_float4(0.f, 0.f, 0.f, 0.f); return; }
    i -= n4c;
    if (i < n4s) asum[i] = make_float4(0.f, 0.f, 0.f, 0.f);
}

// ---------------- weight pack device fns ----------------
__device__ void dev_pack_w(const float* __restrict__ W, int K, int Ntot,
                           int transp, uint32_t* __restrict__ out, int b) {
    int idx = b * 256 + threadIdx.x;
    if (idx >= (K / 2) * Ntot) return;
    int kp = idx / Ntot, n = idx - kp * Ntot;
    int k0 = 2 * kp;
    float w0, w1;
    if (transp) { w0 = W[n * K + k0]; w1 = W[n * K + k0 + 1]; }
    else        { w0 = W[k0 * Ntot + n]; w1 = W[(k0 + 1) * Ntot + n]; }
    int c = kp >> 4, kpl = kp & 15;
    int ny = n >> 7, nl = n & 127;
    int bi = ((((nl >> 3) * 2 + (kpl >> 3)) * 32 + ((nl & 7) << 2) + (kpl & 3)) << 1)
             + ((kpl >> 2) & 1);
    size_t base = ((size_t)(ny * (K >> 5) + c)) << 11;
    out[base + bi] = pack_hi16(w0, w1);
}
__device__ void dev_pack_wk2(const float* __restrict__ W,
                             uint32_t* __restrict__ out, int b) {
    int idx = b * 256 + threadIdx.x;
    if (idx >= 200 * 128) return;
    int kp = idx >> 7, n = idx & 127;
    float w0 = W[(2 * kp) * 128 + n];
    float w1 = W[(2 * kp + 1) * 128 + n];
    int c = kp / 40, kpl = kp - c * 40;
    int bi = ((((n >> 3) * 5 + (kpl >> 3)) * 32 + ((n & 7) << 2) + (kpl & 3)) << 1)
             + ((kpl >> 2) & 1);
    out[c * 5120 + bi] = pack_hi16(w0, w1);
}
__device__ void dev_pack_wk1(const float* __restrict__ W,
                             uint32_t* __restrict__ out, int b) {
    int idx = b * 256 + threadIdx.x;
    if (idx >= 64 * 128) return;
    int kp = idx >> 7, n = idx & 127;
    float w0 = (n < KP) ? W[(2 * kp) * KP + n] : 0.f;
    float w1 = (n < KP) ? W[(2 * kp + 1) * KP + n] : 0.f;
    int c = kp >> 4, kpl = kp & 15;
    int bi = ((((n >> 3) * 2 + (kpl >> 3)) * 32 + ((n & 7) << 2) + (kpl & 3)) << 1)
             + ((kpl >> 2) & 1);
    out[((size_t)c << 11) + bi] = pack_hi16(w0, w1);
}

__global__ void pack_w_all(const float* W_pn, const float* W_ih, const float* W_hh,
                           const float* Wc, const float* Wk2, const float* Wk1,
                           const float* bk1, const float* k1g, const float* k1b,
                           uint32_t* WpnS, uint32_t* WihS, uint32_t* WhhS,
                           uint32_t* WcS, uint32_t* Wk2S, uint32_t* Wk1S) {
    int b = blockIdx.x;
    if (b < 32)  { dev_pack_w(W_pn, 128, 128, 0, WpnS, b); return; }
    b -= 32;
    if (b < 96)  { dev_pack_w(W_ih, 128, 384, 1, WihS, b); return; }
    b -= 96;
    if (b < 96)  { dev_pack_w(W_hh, 128, 384, 1, WhhS, b); return; }
    b -= 96;
    if (b < 64)  { dev_pack_w(Wc, 256, 128, 0, WcS, b); return; }
    b -= 64;
    if (b < 100) { dev_pack_wk2(Wk2, Wk2S, b); return; }
    b -= 100;
    if (b < 32)  { dev_pack_wk1(Wk1, Wk1S, b); return; }
    int t = threadIdx.x;
    if (t < 128) {
        g_bk1p[t] = (t < KP) ? bk1[t] : 0.f;
        g_k1g[t]  = (t < KP) ? k1g[t] : 0.f;
        g_k1b[t]  = (t < KP) ? k1b[t] : 0.f;
    }
}

// activation pack (fp16 hi only)
__global__ void pack_act(const float* __restrict__ X0, int K0, int relu,
                         uint32_t* __restrict__ out, int V,
                         int coff, int KchTot) {
    int t = threadIdx.x;
    int mb = blockIdx.x;
    int Kch = K0 >> 5;
    for (int it = 0; it < Kch * 4; it++) {
        int c = it >> 2;
        int idx = ((it & 3) << 8) + t;
        int mt = idx >> 8;
        int ks = (idx >> 7) & 1;
        int ln = (idx >> 2) & 31;
        int ri = idx & 3;
        int row = mb * 64 + mt * 16 + (ri & 1) * 8 + (ln >> 2);
        if (row >= V) row = V - 1;
        int k = c * 32 + ks * 16 + ((ri >> 1) << 3) + ((ln & 3) << 1);
        float2 a = *(const float2*)&X0[(size_t)row * K0 + k];
        if (relu) { a.x = fmaxf(a.x, 0.f); a.y = fmaxf(a.y, 0.f); }
        size_t base = ((size_t)(mb * KchTot + coff + c)) << 11;
        out[base + idx] = pack_hi16(a.x, a.y);
    }
}

// ---- per-node edge-logit dots ----
__global__ void edgedot_kernel(const float* __restrict__ x,
                               const float* __restrict__ We, int V) {
    int v = blockIdx.x * 8 + (threadIdx.x >> 5);
    if (v >= V) return;
    int lane = threadIdx.x & 31;
    float4 xv = *(const float4*)&x[(size_t)v * D + (lane << 2)];
    float4 w1 = *(const float4*)&We[lane << 2];
    float4 w2 = *(const float4*)&We[D + (lane << 2)];
    float u = xv.x * w1.x + xv.y * w1.y + xv.z * w1.z + xv.w * w1.w;
    float w = xv.x * w2.x + xv.y * w2.y + xv.z * w2.z + xv.w * w2.w;
    #pragma unroll
    for (int m = 16; m; m >>= 1) {
        u += __shfl_xor_sync(0xffffffffu, u, m);
        w += __shfl_xor_sync(0xffffffffu, w, m);
    }
    if (lane == 0) g_uw[v] = make_float2(u, w);
}

// ---- edge logits + exp + segment sum ----
__global__ void logits_kernel(const int* __restrict__ src,
                              const int* __restrict__ dst,
                              const float* __restrict__ be, int E) {
    int e = blockIdx.x * blockDim.x + threadIdx.x;
    if (e >= E) return;
    int sn = src[e], dn = dst[e];
    float2 ud = __ldg(&g_uw[dn]);
    float2 us = __ldg(&g_uw[sn]);
    float lg = fmaxf(ud.x + us.y + be[0], 0.f);
    float a = expf(lg);
    g_aexp[e] = a;
    atomicAdd(&g_asum[dn], a);
}

// ---------------- context scatter ----------------
__global__ void context_kernel(const int* __restrict__ src,
                               const int* __restrict__ dst, int E) {
    int e = blockIdx.x * 8 + (threadIdx.x >> 5);
    if (e >= E) return;
    int lane = threadIdx.x & 31;
    int sn = src[e], dn = dst[e];
    float coef = g_aexp[e] / g_asum[dn];
    uint2 hraw = *(const uint2*)&g_hvH[(size_t)sn * 64 + lane * 2];
    float2 h01 = __half22float2(*(__half2*)&hraw.x);
    float2 h23 = __half22float2(*(__half2*)&hraw.y);
    atomicAdd((float4*)&g_ctx[(size_t)dn * D + (lane << 2)],
              make_float4(h01.x * coef, h01.y * coef, h23.x * coef, h23.y * coef));
}

// =====================================================================
// Node GEMM, fp16 1-pass, dual parameter sets (ysplit dispatch).
// mode: 0=f32 store, 1=half2 store, 2=npj epilogue, 3=LN+relu f32 store.
// =====================================================================
__global__ __launch_bounds__(256)
void mma_gemm(const uint32_t* __restrict__ As, const uint32_t* __restrict__ Bs,
              int Kchunks, int Ntot, int mode,
              const float* __restrict__ bias,
              const float* __restrict__ lng, const float* __restrict__ lnb,
              float* __restrict__ out, int V,
              const uint32_t* __restrict__ As2, const uint32_t* __restrict__ Bs2,
              const float* __restrict__ bias2, float* __restrict__ out2,
              int mode2, int ysplit) {
    __shared__ uint32_t sa[1024];
    __shared__ uint32_t sb[2048];
    __shared__ float red[2][64][2];

    int t = threadIdx.x;
    int lane = t & 31, w = t >> 5;
    int wm = w & 3, wn = w >> 2;
    int row0 = blockIdx.x * 64;

    int ny = blockIdx.y;
    const uint32_t* A_ = As;
    const uint32_t* B_ = Bs;
    const float* bias_ = bias;
    float* out_ = out;
    int mode_ = mode;
    if (ny >= ysplit) {
        ny -= ysplit;
        A_ = As2; B_ = Bs2; bias_ = bias2; out_ = out2; mode_ = mode2;
    }
    int nb = ny * 128;

    float acc[8][4];
    #pragma unroll
    for (int j = 0; j < 8; j++) { acc[j][0]=acc[j][1]=acc[j][2]=acc[j][3]=0.f; }

    const uint4* ag = (const uint4*)(A_ + (size_t)blockIdx.x * Kchunks * 2048);
    const uint4* bg = (const uint4*)(B_ + (size_t)ny * Kchunks * 2048);

    uint4 pa0, pb0, pb1;
    pa0 = ag[t];
    pb0 = bg[t]; pb1 = bg[t + 256];
    for (int c = 0; c < Kchunks; c++) {
        __syncthreads();
        ((uint4*)sa)[t] = pa0;
        ((uint4*)sb)[t] = pb0; ((uint4*)sb)[t + 256] = pb1;
        __syncthreads();
        if (c + 1 < Kchunks) {
            const uint4* a4 = ag + (size_t)(c + 1) * 512;
            const uint4* b4 = bg + (size_t)(c + 1) * 512;
            pa0 = a4[t];
            pb0 = b4[t]; pb1 = b4[t + 256];
        }
        if (mode_ == 2) {
            // npj: only cols 0..23 (wn==0, j<3) contribute to stored outputs
            if (wn == 0) {
                #pragma unroll
                for (int ks = 0; ks < 2; ks++) {
                    uint4 ah = ((const uint4*)sa)[(wm * 2 + ks) * 32 + lane];
                    #pragma unroll
                    for (int j = 0; j < 3; j++) {
                        uint2 bh = ((const uint2*)sb)[(j * 2 + ks) * 32 + lane];
                        MMA_F16(acc[j], ah, bh);
                    }
                }
            }
        } else {
            #pragma unroll
            for (int ks = 0; ks < 2; ks++) {
                uint4 ah = ((const uint4*)sa)[(wm * 2 + ks) * 32 + lane];
                #pragma unroll
                for (int j = 0; j < 8; j++) {
                    int nt = wn * 8 + j;
                    uint2 bh = ((const uint2*)sb)[(nt * 2 + ks) * 32 + lane];
                    MMA_F16(acc[j], ah, bh);
                }
            }
        }
    }

    int rl = row0 + wm * 16 + (lane >> 2);
    int rh = rl + 8;
    if (mode_ == 2) {
        if (wn == 0) {
            int c4 = lane & 3;
            float s_lo=0.f, q_lo=0.f, s_hi=0.f, q_hi=0.f;
            #pragma unroll
            for (int j = 0; j < 3; j++)
                #pragma unroll
                for (int c = 0; c < 2; c++) {
                    int col = j * 8 + c4 * 2 + c;
                    if (col < KP) {
                        float v = acc[j][c] + bias_[col];
                        float vh = acc[j][2 + c] + bias_[col];
                        s_lo += v;  q_lo += v * v;
                        s_hi += vh; q_hi += vh * vh;
                        acc[j][c] = v; acc[j][2 + c] = vh;
                    }
                }
            #pragma unroll
            for (int m = 1; m <= 2; m <<= 1) {
                s_lo += __shfl_xor_sync(0xffffffffu, s_lo, m);
                q_lo += __shfl_xor_sync(0xffffffffu, q_lo, m);
                s_hi += __shfl_xor_sync(0xffffffffu, s_hi, m);
                q_hi += __shfl_xor_sync(0xffffffffu, q_hi, m);
            }
            float mu_lo = s_lo * (1.f / KP);
            float rs_lo = rsqrtf(q_lo * (1.f / KP) - mu_lo * mu_lo + EPS);
            float mu_hi = s_hi * (1.f / KP);
            float rs_hi = rsqrtf(q_hi * (1.f / KP) - mu_hi * mu_hi + EPS);
            #pragma unroll
            for (int j = 0; j < 3; j++)
                #pragma unroll
                for (int c = 0; c < 2; c++) {
                    int col = j * 8 + c4 * 2 + c;
                    if (col < KP) {
                        float gg = lng[col], bb = lnb[col];
                        if (rl < V)
                            g_npjH[rl * KP + col] = __float2half_rn(
                                fmaxf((acc[j][c] - mu_lo) * rs_lo * gg + bb, 0.f));
                        if (rh < V)
                            g_npjH[rh * KP + col] = __float2half_rn(
                                fmaxf((acc[j][2 + c] - mu_hi) * rs_hi * gg + bb, 0.f));
                    }
                }
        }
        return;
    }
    #pragma unroll
    for (int j = 0; j < 8; j++) {
        int gc = nb + wn * 64 + j * 8 + ((lane & 3) << 1);
        float b0 = bias_[gc], b1 = bias_[gc + 1];
        acc[j][0] += b0; acc[j][1] += b1; acc[j][2] += b0; acc[j][3] += b1;
    }
    if (mode_ == 1) {
        uint32_t* oh = (uint32_t*)out_;
        int ld2 = Ntot >> 1;
        #pragma unroll
        for (int j = 0; j < 8; j++) {
            int gc = nb + wn * 64 + j * 8 + ((lane & 3) << 1);
            if (rl < V) oh[(size_t)rl * ld2 + (gc >> 1)] = pack_hi16(acc[j][0], acc[j][1]);
            if (rh < V) oh[(size_t)rh * ld2 + (gc >> 1)] = pack_hi16(acc[j][2], acc[j][3]);
        }
    } else if (mode_ == 0) {
        #pragma unroll
        for (int j = 0; j < 8; j++) {
            int gc = nb + wn * 64 + j * 8 + ((lane & 3) << 1);
            if (rl < V) *(float2*)&out_[(size_t)rl * Ntot + gc] = make_float2(acc[j][0], acc[j][1]);
            if (rh < V) *(float2*)&out_[(size_t)rh * Ntot + gc] = make_float2(acc[j][2], acc[j][3]);
        }
    } else {  // mode 3: LN + relu (Ntot == 128)
        float s_lo=0.f, q_lo=0.f, s_hi=0.f, q_hi=0.f;
        #pragma unroll
        for (int j = 0; j < 8; j++) {
            s_lo += acc[j][0] + acc[j][1];
            q_lo += acc[j][0]*acc[j][0] + acc[j][1]*acc[j][1];
            s_hi += acc[j][2] + acc[j][3];
            q_hi += acc[j][2]*acc[j][2] + acc[j][3]*acc[j][3];
        }
        #pragma unroll
        for (int m = 1; m <= 2; m <<= 1) {
            s_lo += __shfl_xor_sync(0xffffffffu, s_lo, m);
            q_lo += __shfl_xor_sync(0xffffffffu, q_lo, m);
            s_hi += __shfl_xor_sync(0xffffffffu, s_hi, m);
            q_hi += __shfl_xor_sync(0xffffffffu, q_hi, m);
        }
        int rloc = wm * 16 + (lane >> 2);
        if ((lane & 3) == 0) {
            red[wn][rloc][0] = s_lo;   red[wn][rloc][1] = q_lo;
            red[wn][rloc+8][0] = s_hi; red[wn][rloc+8][1] = q_hi;
        }
        __syncthreads();
        float ts_lo = s_lo + red[wn ^ 1][rloc][0];
        float tq_lo = q_lo + red[wn ^ 1][rloc][1];
        float ts_hi = s_hi + red[wn ^ 1][rloc + 8][0];
        float tq_hi = q_hi + red[wn ^ 1][rloc + 8][1];
        float mu_lo = ts_lo * (1.f/128.f);
        float mu_hi = ts_hi * (1.f/128.f);
        float rs_lo = rsqrtf(tq_lo * (1.f/128.f) - mu_lo*mu_lo + EPS);
        float rs_hi = rsqrtf(tq_hi * (1.f/128.f) - mu_hi*mu_hi + EPS);
        #pragma unroll
        for (int j = 0; j < 8; j++) {
            int gc = wn * 64 + j * 8 + ((lane & 3) << 1);
            float g0 = lng[gc], g1 = lng[gc+1];
            float bb0 = lnb[gc], bb1 = lnb[gc+1];
            if (rl < V) {
                float o0 = fmaxf((acc[j][0]-mu_lo)*rs_lo*g0 + bb0, 0.f);
                float o1 = fmaxf((acc[j][1]-mu_lo)*rs_lo*g1 + bb1, 0.f);
                *(float2*)&out_[(size_t)rl * 128 + gc] = make_float2(o0, o1);
            }
            if (rh < V) {
                float o2 = fmaxf((acc[j][2]-mu_hi)*rs_hi*g0 + bb0, 0.f);
                float o3 = fmaxf((acc[j][3]-mu_hi)*rs_hi*g1 + bb1, 0.f);
                *(float2*)&out_[(size_t)rh * 128 + gc] = make_float2(o2, o3);
            }
        }
    }
}

// =====================================================================
// Kron edge GEMM fp16 1-PASS (R15 body, unchanged)
// =====================================================================
__global__ __launch_bounds__(256, 2)
void kron_mma(const int* __restrict__ src, const int* __restrict__ dst,
              const uint32_t* __restrict__ Wk2S,
              const float* __restrict__ bk2,
              const float* __restrict__ lng, const float* __restrict__ lnb,
              int E) {
    extern __shared__ uint32_t dsm[];
    uint32_t* sa = dsm;
    uint32_t* sb = dsm + 5120;
    __half* Ss = (__half*)(dsm + 10240);
    __half* Ds = Ss + 2560;
    __shared__ int ssrc[128], sdst[128];
    __shared__ float red[2][128][2];

    int t = threadIdx.x;
    int lane = t & 31, w = t >> 5;
    int wm = w & 3, wn = w >> 2;
    int e0 = blockIdx.x * 128;

    if (t < 128) {
        int ee = e0 + t; if (ee >= E) ee = E - 1;
        ssrc[t] = src[ee];
        sdst[t] = dst[ee];
    }
    __syncthreads();
    const uint32_t* npjU = (const uint32_t*)g_npjH;
    for (int idx = t; idx < 1280; idx += 256) {
        int e = idx / 10, q = idx - e * 10;
        ((uint32_t*)Ss)[idx] = npjU[ssrc[e] * 10 + q];
        ((uint32_t*)Ds)[idx] = npjU[sdst[e] * 10 + q];
    }

    float acc[2][8][4];
    #pragma unroll
    for (int r = 0; r < 2; r++)
        #pragma unroll
        for (int j = 0; j < 8; j++) { acc[r][j][0]=acc[r][j][1]=acc[r][j][2]=acc[r][j][3]=0.f; }

    int be = t >> 1, ih = t & 1;
    int amt = be >> 4;
    int ribase = (be >> 3) & 1;
    int alnb = (be & 7) << 2;

    for (int c = 0; c < 5; c++) {
        __syncthreads();
        {
            const __half* ds = &Ds[be * 20];
            const __half* ss = &Ss[be * 20];
            #pragma unroll
            for (int iv = 0; iv < 2; iv++) {
                int il = ih * 2 + iv;
                __half2 sv2 = __half2half2(ss[c * 4 + il]);
                #pragma unroll
                for (int q = 0; q < 10; q++) {
                    __half2 d2 = *(const __half2*)&ds[2 * q];
                    __half2 p2 = __hmul2(sv2, d2);
                    int kp = il * 10 + q;
                    int ai = (((amt * 5 + (kp >> 3)) * 32 + alnb + (kp & 3)) << 2)
                             + ribase + (((kp >> 2) & 1) << 1);
                    sa[ai] = *(uint32_t*)&p2;
                }
            }
        }
        {
            const uint4* bsrc = (const uint4*)(Wk2S + c * 5120);
            #pragma unroll
            for (int i = 0; i < 5; i++)
                ((uint4*)sb)[t + (i << 8)] = bsrc[t + (i << 8)];
        }
        __syncthreads();
        #pragma unroll
        for (int ks = 0; ks < 5; ks++) {
            uint4 ah0 = ((const uint4*)sa)[((wm * 2 + 0) * 5 + ks) * 32 + lane];
            uint4 ah1 = ((const uint4*)sa)[((wm * 2 + 1) * 5 + ks) * 32 + lane];
            #pragma unroll
            for (int j = 0; j < 8; j++) {
                int nt = wn * 8 + j;
                uint2 bh = ((const uint2*)sb)[(nt * 5 + ks) * 32 + lane];
                MMA_F16(acc[0][j], ah0, bh);
                MMA_F16(acc[1][j], ah1, bh);
            }
        }
    }

    #pragma unroll
    for (int r = 0; r < 2; r++)
        #pragma unroll
        for (int j = 0; j < 8; j++) {
            int gc = wn * 64 + j * 8 + ((lane & 3) << 1);
            float b0 = bk2[gc], b1 = bk2[gc + 1];
            acc[r][j][0] += b0; acc[r][j][1] += b1;
            acc[r][j][2] += b0; acc[r][j][3] += b1;
        }
    float sum[2][2], sq[2][2];
    #pragma unroll
    for (int r = 0; r < 2; r++) {
        float s_lo=0.f, q_lo=0.f, s_hi=0.f, q_hi=0.f;
        #pragma unroll
        for (int j = 0; j < 8; j++) {
            s_lo += acc[r][j][0] + acc[r][j][1];
            q_lo += acc[r][j][0]*acc[r][j][0] + acc[r][j][1]*acc[r][j][1];
            s_hi += acc[r][j][2] + acc[r][j][3];
            q_hi += acc[r][j][2]*acc[r][j][2] + acc[r][j][3]*acc[r][j][3];
        }
        #pragma unroll
        for (int m = 1; m <= 2; m <<= 1) {
            s_lo += __shfl_xor_sync(0xffffffffu, s_lo, m);
            q_lo += __shfl_xor_sync(0xffffffffu, q_lo, m);
            s_hi += __shfl_xor_sync(0xffffffffu, s_hi, m);
            q_hi += __shfl_xor_sync(0xffffffffu, q_hi, m);
        }
        sum[r][0] = s_lo; sq[r][0] = q_lo;
        sum[r][1] = s_hi; sq[r][1] = q_hi;
        if ((lane & 3) == 0) {
            int rloc = wm * 32 + r * 16 + (lane >> 2);
            red[wn][rloc][0] = s_lo;     red[wn][rloc][1] = q_lo;
            red[wn][rloc + 8][0] = s_hi; red[wn][rloc + 8][1] = q_hi;
        }
    }
    __syncthreads();
    #pragma unroll
    for (int r = 0; r < 2; r++) {
        #pragma unroll
        for (int h = 0; h < 2; h++) {
            int rloc = wm * 32 + r * 16 + h * 8 + (lane >> 2);
            float ts = sum[r][h] + red[wn ^ 1][rloc][0];
            float tq = sq[r][h] + red[wn ^ 1][rloc][1];
            float mu = ts * (1.f / 128.f);
            float rs = rsqrtf(tq * (1.f / 128.f) - mu * mu + EPS);
            int ge = e0 + rloc;
            if (ge < E) {
                int dn = sdst[rloc];
                #pragma unroll
                for (int j = 0; j < 8; j++) {
                    int gc = wn * 64 + j * 8 + ((lane & 3) << 1);
                    float g0 = lng[gc], g1 = lng[gc + 1];
                    float bb0 = lnb[gc], bb1 = lnb[gc + 1];
                    float* p = &g_kf[(size_t)dn * 128 + gc];
                    atomicAdd(p,     fmaxf((acc[r][j][2*h  ]-mu)*rs*g0 + bb0, 0.f));
                    atomicAdd(p + 1, fmaxf((acc[r][j][2*h+1]-mu)*rs*g1 + bb1, 0.f));
                }
            }
        }
    }
}

// ---- GRU gates (fp16 gi/gh) + relu + LN -> Acat chunks 0-3; kf -> 4-7 ----
__global__ void gates_kernel(const float* __restrict__ x,
                             const float* __restrict__ lng,
                             const float* __restrict__ lnb,
                             uint32_t* __restrict__ Acat, int V) {
    int v = blockIdx.x * 8 + (threadIdx.x >> 5);
    if (v >= V) return;
    int lane = threadIdx.x & 31;
    const uint32_t* giH = &g_giH[(size_t)v * 192];
    const uint32_t* ghH = &g_ghH[(size_t)v * 192];
    float h[4];
    {
        uint2 uir = *(const uint2*)&giH[lane * 2];
        uint2 uiz = *(const uint2*)&giH[64 + lane * 2];
        uint2 uin = *(const uint2*)&giH[128 + lane * 2];
        uint2 uhr = *(const uint2*)&ghH[lane * 2];
        uint2 uhz = *(const uint2*)&ghH[64 + lane * 2];
        uint2 uhn = *(const uint2*)&ghH[128 + lane * 2];
        float4 xv = *(const float4*)&x[(size_t)v * D + (lane << 2)];
        #pragma unroll
        for (int hh = 0; hh < 2; hh++) {
            float2 ir = __half22float2(*(__half2*)((hh == 0) ? &uir.x : &uir.y));
            float2 iz = __half22float2(*(__half2*)((hh == 0) ? &uiz.x : &uiz.y));
            float2 in_ = __half22float2(*(__half2*)((hh == 0) ? &uin.x : &uin.y));
            float2 hr = __half22float2(*(__half2*)((hh == 0) ? &uhr.x : &uhr.y));
            float2 hz = __half22float2(*(__half2*)((hh == 0) ? &uhz.x : &uhz.y));
            float2 hn = __half22float2(*(__half2*)((hh == 0) ? &uhn.x : &uhn.y));
            #pragma unroll
            for (int q = 0; q < 2; q++) {
                int i = hh * 2 + q;
                float gir = (q == 0) ? ir.x : ir.y;
                float giz = (q == 0) ? iz.x : iz.y;
                float gin = (q == 0) ? in_.x : in_.y;
                float ghr = (q == 0) ? hr.x : hr.y;
                float ghz = (q == 0) ? hz.x : hz.y;
                float ghn = (q == 0) ? hn.x : hn.y;
                float r = 1.f / (1.f + expf(-(gir + ghr)));
                float z = 1.f / (1.f + expf(-(giz + ghz)));
                float n = tanhf(gin + r * ghn);
                h[i] = fmaxf((1.f - z) * n + z * (&xv.x)[i], 0.f);
            }
        }
    }
    float s = h[0] + h[1] + h[2] + h[3];
    #pragma unroll
    for (int m = 16; m; m >>= 1) s += __shfl_xor_sync(0xffffffffu, s, m);
    float mu = s * (1.f / 128.f), q = 0.f;
    #pragma unroll
    for (int i = 0; i < 4; i++) { float d0 = h[i] - mu; q = fmaf(d0, d0, q); }
    #pragma unroll
    for (int m = 16; m; m >>= 1) q += __shfl_xor_sync(0xffffffffu, q, m);
    float rstd = rsqrtf(q * (1.f / 128.f) + EPS);
    float4 gv = *(const float4*)&lng[lane << 2];
    float4 b2 = *(const float4*)&lnb[lane << 2];
    float o[4];
    o[0] = (h[0]-mu)*rstd*gv.x + b2.x;
    o[1] = (h[1]-mu)*rstd*gv.y + b2.y;
    o[2] = (h[2]-mu)*rstd*gv.z + b2.z;
    o[3] = (h[3]-mu)*rstd*gv.w + b2.w;
    float4 kv = *(const float4*)&g_kf[(size_t)v * D + (lane << 2)];
    int mb = v >> 6;
    int r = v & 63;
    int mt = r >> 4, rb = (r >> 3) & 1, lh = r & 7;
    #pragma unroll
    for (int pp = 0; pp < 2; pp++) {
        int kp = lane * 2 + pp;
        int ll = kp & 3;
        int ri = (((kp >> 2) & 1) << 1) | rb;
        int ks = (kp >> 3) & 1;
        int c  = kp >> 4;
        int idx = mt * 256 + ks * 128 + ((lh << 2) | ll) * 4 + ri;
        size_t base = ((size_t)(mb * 8 + c)) << 11;
        Acat[base + idx] = pack_hi16(o[2 * pp], o[2 * pp + 1]);
        base = ((size_t)(mb * 8 + 4 + c)) << 11;
        Acat[base + idx] = pack_hi16((&kv.x)[2 * pp], (&kv.x)[2 * pp + 1]);
    }
}

// ---------------- host ----------------
extern "C" void kernel_launch(void* const* d_in, const int* in_sizes, int n_in,
                              void* d_out, int out_size) {
    const float* node   = (const float*)d_in[0];
    const int*   src    = (const int*)  d_in[1];
    const int*   dst    = (const int*)  d_in[2];
    const float* W_edge = (const float*)d_in[3];
    const float* b_edge = (const float*)d_in[4];
    const float* W_pn   = (const float*)d_in[5];
    const float* b_pn   = (const float*)d_in[6];
    const float* W_ih   = (const float*)d_in[7];
    const float* b_ih   = (const float*)d_in[8];
    const float* W_hh   = (const float*)d_in[9];
    const float* b_hh   = (const float*)d_in[10];
    const float* ln_g   = (const float*)d_in[11];
    const float* ln_b   = (const float*)d_in[12];
    const float* Wk1    = (const float*)d_in[13];
    const float* bk1    = (const float*)d_in[14];
    const float* lnk1_g = (const float*)d_in[15];
    const float* lnk1_b = (const float*)d_in[16];
    const float* Wk2    = (const float*)d_in[17];
    const float* bk2    = (const float*)d_in[18];
    const float* lnk2_g = (const float*)d_in[19];
    const float* lnk2_b = (const float*)d_in[20];
    const float* Wc     = (const float*)d_in[21];
    const float* bc     = (const float*)d_in[22];
    const float* lnc_g  = (const float*)d_in[23];
    const float* lnc_b  = (const float*)d_in[24];
    int V = in_sizes[0] / D;
    int E = in_sizes[1];
    float* out = (float*)d_out;

    float *p_asum, *p_ctx, *p_kf, *p_bk1p, *p_k1g, *p_k1b;
    uint32_t *p_hvH, *p_giH, *p_ghH;
    uint32_t *p_WpnS, *p_WihS, *p_WhhS, *p_WcS, *p_Wk2S, *p_Wk1S;
    uint32_t *p_An, *p_Ac, *p_Aq;
    cudaGetSymbolAddress((void**)&p_asum, g_asum);
    cudaGetSymbolAddress((void**)&p_hvH,  g_hvH);
    cudaGetSymbolAddress((void**)&p_ctx,  g_ctx);
    cudaGetSymbolAddress((void**)&p_kf,   g_kf);
    cudaGetSymbolAddress((void**)&p_giH,  g_giH);
    cudaGetSymbolAddress((void**)&p_ghH,  g_ghH);
    cudaGetSymbolAddress((void**)&p_WpnS, g_WpnS);
    cudaGetSymbolAddress((void**)&p_WihS, g_WihS);
    cudaGetSymbolAddress((void**)&p_WhhS, g_WhhS);
    cudaGetSymbolAddress((void**)&p_WcS,  g_WcS);
    cudaGetSymbolAddress((void**)&p_Wk2S, g_Wk2S);
    cudaGetSymbolAddress((void**)&p_Wk1S, g_Wk1S);
    cudaGetSymbolAddress((void**)&p_bk1p, g_bk1p);
    cudaGetSymbolAddress((void**)&p_k1g,  g_k1g);
    cudaGetSymbolAddress((void**)&p_k1b,  g_k1b);
    cudaGetSymbolAddress((void**)&p_An,   g_Anode);
    cudaGetSymbolAddress((void**)&p_Ac,   g_Actx);
    cudaGetSymbolAddress((void**)&p_Aq,   g_Acat);

    static bool attr_set = false;
    if (!attr_set) {
        cudaFuncSetAttribute(kron_mma, cudaFuncAttributeMaxDynamicSharedMemorySize, 52000);
        attr_set = true;
    }

    int NBv = (V + 63) / 64;
    int n4c = V * 32;
    int n4s = V / 4;

    // fused zero
    zero_all<<<(2 * n4c + n4s + 255) / 256, 256>>>((float4*)p_ctx, (float4*)p_kf,
                                                   (float4*)p_asum, n4c, n4s);
    // fused weight packs
    pack_w_all<<<421, 256>>>(W_pn, W_ih, W_hh, Wc, Wk2, Wk1, bk1, lnk1_g, lnk1_b,
                             p_WpnS, p_WihS, p_WhhS, p_WcS, p_Wk2S, p_Wk1S);
    // pack node activations
    pack_act<<<NBv, 256>>>(node, 128, 0, p_An, V, 0, 4);
    // edgedot + logits
    edgedot_kernel<<<(V + 7) / 8, 256>>>(node, W_edge, V);
    logits_kernel<<<(E + 255) / 256, 256>>>(src, dst, b_edge, E);

    // FUSED: hv (mode 1) + npj (mode 2) — same A, grid.y = 2, ysplit = 1
    mma_gemm<<<dim3(NBv, 2), 256>>>(p_An, p_WpnS, 4, 128, 1,
                                    b_pn, p_k1g, p_k1b, (float*)p_hvH, V,
                                    p_An, p_Wk1S, p_bk1p, nullptr, 2, 1);

    // kron GEMM + LN + relu + scatter to kf
    kron_mma<<<(E + 127) / 128, 256, 51200>>>(src, dst, p_Wk2S,
                                              bk2, lnk2_g, lnk2_b, E);
    // context scatter
    context_kernel<<<(E + 7) / 8, 256>>>(src, dst, E);
    // pack relu(ctx)
    pack_act<<<NBv, 256>>>(p_ctx, 128, 1, p_Ac, V, 0, 4);

    // FUSED: gi (y<3) + gh (y>=3) — grid.y = 6, ysplit = 3
    mma_gemm<<<dim3(NBv, 6), 256>>>(p_Ac, p_WihS, 4, 384, 1,
                                    b_ih, nullptr, nullptr, (float*)p_giH, V,
                                    p_An, p_WhhS, b_hh, (float*)p_ghH, 1, 3);

    // gates -> Acat
    gates_kernel<<<(V + 7) / 8, 256>>>(node, ln_g, ln_b, p_Aq, V);

    // out = relu(LN(cat @ Wc + bc)) — mode 3
    mma_gemm<<<dim3(NBv, 1), 256>>>(p_Aq, p_WcS, 8, 128, 3,
                                    bc, lnc_g, lnc_b, out, V,
                                    nullptr, nullptr, nullptr, nullptr, 0, 999);
}

// round 17
// speedup vs baseline: 1.9444x; 1.0044x over previous
#include <cuda_runtime.h>
#include <cuda_fp16.h>
#include <math.h>
#include <stdint.h>

#define D     128
#define KP    20
#define VMAX  100000
#define EMAX  400000
#define EPS   1e-5f
#define NBMAX 1563   // (VMAX+63)/64

// ---------------- scratch (device globals; no allocations) ----------------
__device__ __half g_npjH[VMAX * KP];
__device__ float g_aexp [EMAX];
__device__ float g_asum [VMAX];
__device__ float2 g_uw  [VMAX];
__device__ uint32_t g_hvH[(size_t)VMAX * 64];
__device__ float g_ctx  [VMAX * D];
__device__ float g_kf   [VMAX * D];
__device__ uint32_t g_giH[(size_t)VMAX * 192];
__device__ uint32_t g_ghH[(size_t)VMAX * 192];

// fragment-ordered fp16 WEIGHT streams (hi only)
__device__ uint32_t g_WpnS[1 * 4 * 2048];
__device__ uint32_t g_WihS[3 * 4 * 2048];
__device__ uint32_t g_WhhS[3 * 4 * 2048];
__device__ uint32_t g_WcS [1 * 8 * 2048];
__device__ uint32_t g_Wk2S[5 * 5120];
__device__ uint32_t g_Wk1S[4 * 2048];      // Wk1 zero-padded to N=128

// padded npj params (20 -> 128)
__device__ float g_bk1p[128];
__device__ float g_k1g [128];
__device__ float g_k1b [128];

// fragment-ordered fp16 ACTIVATION streams (hi only)
__device__ uint32_t g_Anode[(size_t)NBMAX * 4 * 2048];
__device__ uint32_t g_Actx [(size_t)NBMAX * 4 * 2048];
__device__ uint32_t g_Acat [(size_t)NBMAX * 8 * 2048];

__device__ __forceinline__ uint32_t pack_hi16(float a0, float a1) {
    __half2 hp = __floats2half2_rn(a0, a1);
    return *(uint32_t*)&hp;
}

#define MMA_F16(c, A, B) asm volatile( \
    "mma.sync.aligned.m16n8k16.row.col.f32.f16.f16.f32 " \
    "{%0,%1,%2,%3}, {%4,%5,%6,%7}, {%8,%9}, {%0,%1,%2,%3};\n" \
    : "+f"(c[0]), "+f"(c[1]), "+f"(c[2]), "+f"(c[3]) \
    : "r"(A.x), "r"(A.y), "r"(A.z), "r"(A.w), "r"(B.x), "r"(B.y))

// ---------------- prologue device fns ----------------
__device__ void dev_pack_w(const float* __restrict__ W, int K, int Ntot,
                           int transp, uint32_t* __restrict__ out, int b) {
    int idx = b * 256 + threadIdx.x;
    if (idx >= (K / 2) * Ntot) return;
    int kp = idx / Ntot, n = idx - kp * Ntot;
    int k0 = 2 * kp;
    float w0, w1;
    if (transp) { w0 = W[n * K + k0]; w1 = W[n * K + k0 + 1]; }
    else        { w0 = W[k0 * Ntot + n]; w1 = W[(k0 + 1) * Ntot + n]; }
    int c = kp >> 4, kpl = kp & 15;
    int ny = n >> 7, nl = n & 127;
    int bi = ((((nl >> 3) * 2 + (kpl >> 3)) * 32 + ((nl & 7) << 2) + (kpl & 3)) << 1)
             + ((kpl >> 2) & 1);
    size_t base = ((size_t)(ny * (K >> 5) + c)) << 11;
    out[base + bi] = pack_hi16(w0, w1);
}
__device__ void dev_pack_wk2(const float* __restrict__ W,
                             uint32_t* __restrict__ out, int b) {
    int idx = b * 256 + threadIdx.x;
    if (idx >= 200 * 128) return;
    int kp = idx >> 7, n = idx & 127;
    float w0 = W[(2 * kp) * 128 + n];
    float w1 = W[(2 * kp + 1) * 128 + n];
    int c = kp / 40, kpl = kp - c * 40;
    int bi = ((((n >> 3) * 5 + (kpl >> 3)) * 32 + ((n & 7) << 2) + (kpl & 3)) << 1)
             + ((kpl >> 2) & 1);
    out[c * 5120 + bi] = pack_hi16(w0, w1);
}
__device__ void dev_pack_wk1(const float* __restrict__ W,
                             uint32_t* __restrict__ out, int b) {
    int idx = b * 256 + threadIdx.x;
    if (idx >= 64 * 128) return;
    int kp = idx >> 7, n = idx & 127;
    float w0 = (n < KP) ? W[(2 * kp) * KP + n] : 0.f;
    float w1 = (n < KP) ? W[(2 * kp + 1) * KP + n] : 0.f;
    int c = kp >> 4, kpl = kp & 15;
    int bi = ((((n >> 3) * 2 + (kpl >> 3)) * 32 + ((n & 7) << 2) + (kpl & 3)) << 1)
             + ((kpl >> 2) & 1);
    out[((size_t)c << 11) + bi] = pack_hi16(w0, w1);
}
__device__ void dev_pack_act(const float* __restrict__ X0, int K0, int relu,
                             uint32_t* __restrict__ out, int V,
                             int coff, int KchTot, int mb) {
    int t = threadIdx.x;
    int Kch = K0 >> 5;
    for (int it = 0; it < Kch * 4; it++) {
        int c = it >> 2;
        int idx = ((it & 3) << 8) + t;
        int mt = idx >> 8;
        int ks = (idx >> 7) & 1;
        int ln = (idx >> 2) & 31;
        int ri = idx & 3;
        int row = mb * 64 + mt * 16 + (ri & 1) * 8 + (ln >> 2);
        if (row >= V) row = V - 1;
        int k = c * 32 + ks * 16 + ((ri >> 1) << 3) + ((ln & 3) << 1);
        float2 a = *(const float2*)&X0[(size_t)row * K0 + k];
        if (relu) { a.x = fmaxf(a.x, 0.f); a.y = fmaxf(a.y, 0.f); }
        size_t base = ((size_t)(mb * KchTot + coff + c)) << 11;
        out[base + idx] = pack_hi16(a.x, a.y);
    }
}
__device__ void dev_edgedot(const float* __restrict__ x,
                            const float* __restrict__ We, int V, int b) {
    int v = b * 8 + (threadIdx.x >> 5);
    if (v >= V) return;
    int lane = threadIdx.x & 31;
    float4 xv = *(const float4*)&x[(size_t)v * D + (lane << 2)];
    float4 w1 = *(const float4*)&We[lane << 2];
    float4 w2 = *(const float4*)&We[D + (lane << 2)];
    float u = xv.x * w1.x + xv.y * w1.y + xv.z * w1.z + xv.w * w1.w;
    float w = xv.x * w2.x + xv.y * w2.y + xv.z * w2.z + xv.w * w2.w;
    #pragma unroll
    for (int m = 16; m; m >>= 1) {
        u += __shfl_xor_sync(0xffffffffu, u, m);
        w += __shfl_xor_sync(0xffffffffu, w, m);
    }
    if (lane == 0) g_uw[v] = make_float2(u, w);
}

// ================= fused prologue =================
// ranges: [0,nz) zero(ctx,kf,asum) | [.. +421) weight packs |
//         [.. +NBv) pack_act(node) | [.. +ned) edgedot
__global__ void prologue_kernel(const float* node, const float* We,
                                const float* W_pn, const float* W_ih,
                                const float* W_hh, const float* Wc,
                                const float* Wk2, const float* Wk1,
                                const float* bk1, const float* k1g, const float* k1b,
                                uint32_t* WpnS, uint32_t* WihS, uint32_t* WhhS,
                                uint32_t* WcS, uint32_t* Wk2S, uint32_t* Wk1S,
                                float4* ctx, float4* kf, float4* asum, uint32_t* An,
                                int V, int n4c, int n4s, int nz, int NBv, int ned) {
    int b = blockIdx.x;
    if (b < nz) {
        int i = b * 256 + threadIdx.x;
        if (i < n4c) { ctx[i] = make_float4(0.f, 0.f, 0.f, 0.f); return; }
        i -= n4c;
        if (i < n4c) { kf[i] = make_float4(0.f, 0.f, 0.f, 0.f); return; }
        i -= n4c;
        if (i < n4s) asum[i] = make_float4(0.f, 0.f, 0.f, 0.f);
        return;
    }
    b -= nz;
    if (b < 32)  { dev_pack_w(W_pn, 128, 128, 0, WpnS, b); return; }
    b -= 32;
    if (b < 96)  { dev_pack_w(W_ih, 128, 384, 1, WihS, b); return; }
    b -= 96;
    if (b < 96)  { dev_pack_w(W_hh, 128, 384, 1, WhhS, b); return; }
    b -= 96;
    if (b < 64)  { dev_pack_w(Wc, 256, 128, 0, WcS, b); return; }
    b -= 64;
    if (b < 100) { dev_pack_wk2(Wk2, Wk2S, b); return; }
    b -= 100;
    if (b < 32)  { dev_pack_wk1(Wk1, Wk1S, b); return; }
    b -= 32;
    if (b < 1) {
        int t = threadIdx.x;
        if (t < 128) {
            g_bk1p[t] = (t < KP) ? bk1[t] : 0.f;
            g_k1g[t]  = (t < KP) ? k1g[t] : 0.f;
            g_k1b[t]  = (t < KP) ? k1b[t] : 0.f;
        }
        return;
    }
    b -= 1;
    if (b < NBv) { dev_pack_act(node, 128, 0, An, V, 0, 4, b); return; }
    b -= NBv;
    if (b < ned) dev_edgedot(node, We, V, b);
}

// activation pack standalone (for ctx)
__global__ void pack_act(const float* __restrict__ X0, int K0, int relu,
                         uint32_t* __restrict__ out, int V,
                         int coff, int KchTot) {
    dev_pack_act(X0, K0, relu, out, V, coff, KchTot, blockIdx.x);
}

// ---- edge logits + exp + segment sum ----
__global__ void logits_kernel(const int* __restrict__ src,
                              const int* __restrict__ dst,
                              const float* __restrict__ be, int E) {
    int e = blockIdx.x * blockDim.x + threadIdx.x;
    if (e >= E) return;
    int sn = src[e], dn = dst[e];
    float2 ud = __ldg(&g_uw[dn]);
    float2 us = __ldg(&g_uw[sn]);
    float lg = fmaxf(ud.x + us.y + be[0], 0.f);
    float a = expf(lg);
    g_aexp[e] = a;
    atomicAdd(&g_asum[dn], a);
}

// ---------------- context scatter ----------------
__global__ void context_kernel(const int* __restrict__ src,
                               const int* __restrict__ dst, int E) {
    int e = blockIdx.x * 8 + (threadIdx.x >> 5);
    if (e >= E) return;
    int lane = threadIdx.x & 31;
    int sn = src[e], dn = dst[e];
    float coef = g_aexp[e] / g_asum[dn];
    uint2 hraw = *(const uint2*)&g_hvH[(size_t)sn * 64 + lane * 2];
    float2 h01 = __half22float2(*(__half2*)&hraw.x);
    float2 h23 = __half22float2(*(__half2*)&hraw.y);
    atomicAdd((float4*)&g_ctx[(size_t)dn * D + (lane << 2)],
              make_float4(h01.x * coef, h01.y * coef, h23.x * coef, h23.y * coef));
}

// =====================================================================
// Node GEMM, fp16 1-pass, dual parameter sets (ysplit dispatch).
// mode: 0=f32 store, 1=half2 store, 2=npj epilogue, 3=LN+relu f32 store.
// =====================================================================
__global__ __launch_bounds__(256)
void mma_gemm(const uint32_t* __restrict__ As, const uint32_t* __restrict__ Bs,
              int Kchunks, int Ntot, int mode,
              const float* __restrict__ bias,
              const float* __restrict__ lng, const float* __restrict__ lnb,
              float* __restrict__ out, int V,
              const uint32_t* __restrict__ As2, const uint32_t* __restrict__ Bs2,
              const float* __restrict__ bias2, float* __restrict__ out2,
              int mode2, int ysplit) {
    __shared__ uint32_t sa[1024];
    __shared__ uint32_t sb[2048];
    __shared__ float red[2][64][2];

    int t = threadIdx.x;
    int lane = t & 31, w = t >> 5;
    int wm = w & 3, wn = w >> 2;
    int row0 = blockIdx.x * 64;

    int ny = blockIdx.y;
    const uint32_t* A_ = As;
    const uint32_t* B_ = Bs;
    const float* bias_ = bias;
    float* out_ = out;
    int mode_ = mode;
    if (ny >= ysplit) {
        ny -= ysplit;
        A_ = As2; B_ = Bs2; bias_ = bias2; out_ = out2; mode_ = mode2;
    }
    int nb = ny * 128;

    float acc[8][4];
    #pragma unroll
    for (int j = 0; j < 8; j++) { acc[j][0]=acc[j][1]=acc[j][2]=acc[j][3]=0.f; }

    const uint4* ag = (const uint4*)(A_ + (size_t)blockIdx.x * Kchunks * 2048);
    const uint4* bg = (const uint4*)(B_ + (size_t)ny * Kchunks * 2048);

    uint4 pa0, pb0, pb1;
    pa0 = ag[t];
    pb0 = bg[t]; pb1 = bg[t + 256];
    for (int c = 0; c < Kchunks; c++) {
        __syncthreads();
        ((uint4*)sa)[t] = pa0;
        ((uint4*)sb)[t] = pb0; ((uint4*)sb)[t + 256] = pb1;
        __syncthreads();
        if (c + 1 < Kchunks) {
            const uint4* a4 = ag + (size_t)(c + 1) * 512;
            const uint4* b4 = bg + (size_t)(c + 1) * 512;
            pa0 = a4[t];
            pb0 = b4[t]; pb1 = b4[t + 256];
        }
        if (mode_ == 2) {
            if (wn == 0) {
                #pragma unroll
                for (int ks = 0; ks < 2; ks++) {
                    uint4 ah = ((const uint4*)sa)[(wm * 2 + ks) * 32 + lane];
                    #pragma unroll
                    for (int j = 0; j < 3; j++) {
                        uint2 bh = ((const uint2*)sb)[(j * 2 + ks) * 32 + lane];
                        MMA_F16(acc[j], ah, bh);
                    }
                }
            }
        } else {
            #pragma unroll
            for (int ks = 0; ks < 2; ks++) {
                uint4 ah = ((const uint4*)sa)[(wm * 2 + ks) * 32 + lane];
                #pragma unroll
                for (int j = 0; j < 8; j++) {
                    int nt = wn * 8 + j;
                    uint2 bh = ((const uint2*)sb)[(nt * 2 + ks) * 32 + lane];
                    MMA_F16(acc[j], ah, bh);
                }
            }
        }
    }

    int rl = row0 + wm * 16 + (lane >> 2);
    int rh = rl + 8;
    if (mode_ == 2) {
        if (wn == 0) {
            int c4 = lane & 3;
            float s_lo=0.f, q_lo=0.f, s_hi=0.f, q_hi=0.f;
            #pragma unroll
            for (int j = 0; j < 3; j++)
                #pragma unroll
                for (int c = 0; c < 2; c++) {
                    int col = j * 8 + c4 * 2 + c;
                    if (col < KP) {
                        float v = acc[j][c] + bias_[col];
                        float vh = acc[j][2 + c] + bias_[col];
                        s_lo += v;  q_lo += v * v;
                        s_hi += vh; q_hi += vh * vh;
                        acc[j][c] = v; acc[j][2 + c] = vh;
                    }
                }
            #pragma unroll
            for (int m = 1; m <= 2; m <<= 1) {
                s_lo += __shfl_xor_sync(0xffffffffu, s_lo, m);
                q_lo += __shfl_xor_sync(0xffffffffu, q_lo, m);
                s_hi += __shfl_xor_sync(0xffffffffu, s_hi, m);
                q_hi += __shfl_xor_sync(0xffffffffu, q_hi, m);
            }
            float mu_lo = s_lo * (1.f / KP);
            float rs_lo = rsqrtf(q_lo * (1.f / KP) - mu_lo * mu_lo + EPS);
            float mu_hi = s_hi * (1.f / KP);
            float rs_hi = rsqrtf(q_hi * (1.f / KP) - mu_hi * mu_hi + EPS);
            #pragma unroll
            for (int j = 0; j < 3; j++)
                #pragma unroll
                for (int c = 0; c < 2; c++) {
                    int col = j * 8 + c4 * 2 + c;
                    if (col < KP) {
                        float gg = lng[col], bb = lnb[col];
                        if (rl < V)
                            g_npjH[rl * KP + col] = __float2half_rn(
                                fmaxf((acc[j][c] - mu_lo) * rs_lo * gg + bb, 0.f));
                        if (rh < V)
                            g_npjH[rh * KP + col] = __float2half_rn(
                                fmaxf((acc[j][2 + c] - mu_hi) * rs_hi * gg + bb, 0.f));
                    }
                }
        }
        return;
    }
    #pragma unroll
    for (int j = 0; j < 8; j++) {
        int gc = nb + wn * 64 + j * 8 + ((lane & 3) << 1);
        float b0 = bias_[gc], b1 = bias_[gc + 1];
        acc[j][0] += b0; acc[j][1] += b1; acc[j][2] += b0; acc[j][3] += b1;
    }
    if (mode_ == 1) {
        uint32_t* oh = (uint32_t*)out_;
        int ld2 = Ntot >> 1;
        #pragma unroll
        for (int j = 0; j < 8; j++) {
            int gc = nb + wn * 64 + j * 8 + ((lane & 3) << 1);
            if (rl < V) oh[(size_t)rl * ld2 + (gc >> 1)] = pack_hi16(acc[j][0], acc[j][1]);
            if (rh < V) oh[(size_t)rh * ld2 + (gc >> 1)] = pack_hi16(acc[j][2], acc[j][3]);
        }
    } else if (mode_ == 0) {
        #pragma unroll
        for (int j = 0; j < 8; j++) {
            int gc = nb + wn * 64 + j * 8 + ((lane & 3) << 1);
            if (rl < V) *(float2*)&out_[(size_t)rl * Ntot + gc] = make_float2(acc[j][0], acc[j][1]);
            if (rh < V) *(float2*)&out_[(size_t)rh * Ntot + gc] = make_float2(acc[j][2], acc[j][3]);
        }
    } else {  // mode 3: LN + relu (Ntot == 128)
        float s_lo=0.f, q_lo=0.f, s_hi=0.f, q_hi=0.f;
        #pragma unroll
        for (int j = 0; j < 8; j++) {
            s_lo += acc[j][0] + acc[j][1];
            q_lo += acc[j][0]*acc[j][0] + acc[j][1]*acc[j][1];
            s_hi += acc[j][2] + acc[j][3];
            q_hi += acc[j][2]*acc[j][2] + acc[j][3]*acc[j][3];
        }
        #pragma unroll
        for (int m = 1; m <= 2; m <<= 1) {
            s_lo += __shfl_xor_sync(0xffffffffu, s_lo, m);
            q_lo += __shfl_xor_sync(0xffffffffu, q_lo, m);
            s_hi += __shfl_xor_sync(0xffffffffu, s_hi, m);
            q_hi += __shfl_xor_sync(0xffffffffu, q_hi, m);
        }
        int rloc = wm * 16 + (lane >> 2);
        if ((lane & 3) == 0) {
            red[wn][rloc][0] = s_lo;   red[wn][rloc][1] = q_lo;
            red[wn][rloc+8][0] = s_hi; red[wn][rloc+8][1] = q_hi;
        }
        __syncthreads();
        float ts_lo = s_lo + red[wn ^ 1][rloc][0];
        float tq_lo = q_lo + red[wn ^ 1][rloc][1];
        float ts_hi = s_hi + red[wn ^ 1][rloc + 8][0];
        float tq_hi = q_hi + red[wn ^ 1][rloc + 8][1];
        float mu_lo = ts_lo * (1.f/128.f);
        float mu_hi = ts_hi * (1.f/128.f);
        float rs_lo = rsqrtf(tq_lo * (1.f/128.f) - mu_lo*mu_lo + EPS);
        float rs_hi = rsqrtf(tq_hi * (1.f/128.f) - mu_hi*mu_hi + EPS);
        #pragma unroll
        for (int j = 0; j < 8; j++) {
            int gc = wn * 64 + j * 8 + ((lane & 3) << 1);
            float g0 = lng[gc], g1 = lng[gc+1];
            float bb0 = lnb[gc], bb1 = lnb[gc+1];
            if (rl < V) {
                float o0 = fmaxf((acc[j][0]-mu_lo)*rs_lo*g0 + bb0, 0.f);
                float o1 = fmaxf((acc[j][1]-mu_lo)*rs_lo*g1 + bb1, 0.f);
                *(float2*)&out_[(size_t)rl * 128 + gc] = make_float2(o0, o1);
            }
            if (rh < V) {
                float o2 = fmaxf((acc[j][2]-mu_hi)*rs_hi*g0 + bb0, 0.f);
                float o3 = fmaxf((acc[j][3]-mu_hi)*rs_hi*g1 + bb1, 0.f);
                *(float2*)&out_[(size_t)rh * 128 + gc] = make_float2(o2, o3);
            }
        }
    }
}

// =====================================================================
// Kron edge GEMM fp16 1-PASS (unchanged)
// =====================================================================
__global__ __launch_bounds__(256, 2)
void kron_mma(const int* __restrict__ src, const int* __restrict__ dst,
              const uint32_t* __restrict__ Wk2S,
              const float* __restrict__ bk2,
              const float* __restrict__ lng, const float* __restrict__ lnb,
              int E) {
    extern __shared__ uint32_t dsm[];
    uint32_t* sa = dsm;
    uint32_t* sb = dsm + 5120;
    __half* Ss = (__half*)(dsm + 10240);
    __half* Ds = Ss + 2560;
    __shared__ int ssrc[128], sdst[128];
    __shared__ float red[2][128][2];

    int t = threadIdx.x;
    int lane = t & 31, w = t >> 5;
    int wm = w & 3, wn = w >> 2;
    int e0 = blockIdx.x * 128;

    if (t < 128) {
        int ee = e0 + t; if (ee >= E) ee = E - 1;
        ssrc[t] = src[ee];
        sdst[t] = dst[ee];
    }
    __syncthreads();
    const uint32_t* npjU = (const uint32_t*)g_npjH;
    for (int idx = t; idx < 1280; idx += 256) {
        int e = idx / 10, q = idx - e * 10;
        ((uint32_t*)Ss)[idx] = npjU[ssrc[e] * 10 + q];
        ((uint32_t*)Ds)[idx] = npjU[sdst[e] * 10 + q];
    }

    float acc[2][8][4];
    #pragma unroll
    for (int r = 0; r < 2; r++)
        #pragma unroll
        for (int j = 0; j < 8; j++) { acc[r][j][0]=acc[r][j][1]=acc[r][j][2]=acc[r][j][3]=0.f; }

    int be = t >> 1, ih = t & 1;
    int amt = be >> 4;
    int ribase = (be >> 3) & 1;
    int alnb = (be & 7) << 2;

    for (int c = 0; c < 5; c++) {
        __syncthreads();
        {
            const __half* ds = &Ds[be * 20];
            const __half* ss = &Ss[be * 20];
            #pragma unroll
            for (int iv = 0; iv < 2; iv++) {
                int il = ih * 2 + iv;
                __half2 sv2 = __half2half2(ss[c * 4 + il]);
                #pragma unroll
                for (int q = 0; q < 10; q++) {
                    __half2 d2 = *(const __half2*)&ds[2 * q];
                    __half2 p2 = __hmul2(sv2, d2);
                    int kp = il * 10 + q;
                    int ai = (((amt * 5 + (kp >> 3)) * 32 + alnb + (kp & 3)) << 2)
                             + ribase + (((kp >> 2) & 1) << 1);
                    sa[ai] = *(uint32_t*)&p2;
                }
            }
        }
        {
            const uint4* bsrc = (const uint4*)(Wk2S + c * 5120);
            #pragma unroll
            for (int i = 0; i < 5; i++)
                ((uint4*)sb)[t + (i << 8)] = bsrc[t + (i << 8)];
        }
        __syncthreads();
        #pragma unroll
        for (int ks = 0; ks < 5; ks++) {
            uint4 ah0 = ((const uint4*)sa)[((wm * 2 + 0) * 5 + ks) * 32 + lane];
            uint4 ah1 = ((const uint4*)sa)[((wm * 2 + 1) * 5 + ks) * 32 + lane];
            #pragma unroll
            for (int j = 0; j < 8; j++) {
                int nt = wn * 8 + j;
                uint2 bh = ((const uint2*)sb)[(nt * 5 + ks) * 32 + lane];
                MMA_F16(acc[0][j], ah0, bh);
                MMA_F16(acc[1][j], ah1, bh);
            }
        }
    }

    #pragma unroll
    for (int r = 0; r < 2; r++)
        #pragma unroll
        for (int j = 0; j < 8; j++) {
            int gc = wn * 64 + j * 8 + ((lane & 3) << 1);
            float b0 = bk2[gc], b1 = bk2[gc + 1];
            acc[r][j][0] += b0; acc[r][j][1] += b1;
            acc[r][j][2] += b0; acc[r][j][3] += b1;
        }
    float sum[2][2], sq[2][2];
    #pragma unroll
    for (int r = 0; r < 2; r++) {
        float s_lo=0.f, q_lo=0.f, s_hi=0.f, q_hi=0.f;
        #pragma unroll
        for (int j = 0; j < 8; j++) {
            s_lo += acc[r][j][0] + acc[r][j][1];
            q_lo += acc[r][j][0]*acc[r][j][0] + acc[r][j][1]*acc[r][j][1];
            s_hi += acc[r][j][2] + acc[r][j][3];
            q_hi += acc[r][j][2]*acc[r][j][2] + acc[r][j][3]*acc[r][j][3];
        }
        #pragma unroll
        for (int m = 1; m <= 2; m <<= 1) {
            s_lo += __shfl_xor_sync(0xffffffffu, s_lo, m);
            q_lo += __shfl_xor_sync(0xffffffffu, q_lo, m);
            s_hi += __shfl_xor_sync(0xffffffffu, s_hi, m);
            q_hi += __shfl_xor_sync(0xffffffffu, q_hi, m);
        }
        sum[r][0] = s_lo; sq[r][0] = q_lo;
        sum[r][1] = s_hi; sq[r][1] = q_hi;
        if ((lane & 3) == 0) {
            int rloc = wm * 32 + r * 16 + (lane >> 2);
            red[wn][rloc][0] = s_lo;     red[wn][rloc][1] = q_lo;
            red[wn][rloc + 8][0] = s_hi; red[wn][rloc + 8][1] = q_hi;
        }
    }
    __syncthreads();
    #pragma unroll
    for (int r = 0; r < 2; r++) {
        #pragma unroll
        for (int h = 0; h < 2; h++) {
            int rloc = wm * 32 + r * 16 + h * 8 + (lane >> 2);
            float ts = sum[r][h] + red[wn ^ 1][rloc][0];
            float tq = sq[r][h] + red[wn ^ 1][rloc][1];
            float mu = ts * (1.f / 128.f);
            float rs = rsqrtf(tq * (1.f / 128.f) - mu * mu + EPS);
            int ge = e0 + rloc;
            if (ge < E) {
                int dn = sdst[rloc];
                #pragma unroll
                for (int j = 0; j < 8; j++) {
                    int gc = wn * 64 + j * 8 + ((lane & 3) << 1);
                    float g0 = lng[gc], g1 = lng[gc + 1];
                    float bb0 = lnb[gc], bb1 = lnb[gc + 1];
                    float* p = &g_kf[(size_t)dn * 128 + gc];
                    atomicAdd(p,     fmaxf((acc[r][j][2*h  ]-mu)*rs*g0 + bb0, 0.f));
                    atomicAdd(p + 1, fmaxf((acc[r][j][2*h+1]-mu)*rs*g1 + bb1, 0.f));
                }
            }
        }
    }
}

// ---- GRU gates (fp16 gi/gh) + relu + LN -> Acat chunks 0-3; kf -> 4-7 ----
__global__ void gates_kernel(const float* __restrict__ x,
                             const float* __restrict__ lng,
                             const float* __restrict__ lnb,
                             uint32_t* __restrict__ Acat, int V) {
    int v = blockIdx.x * 8 + (threadIdx.x >> 5);
    if (v >= V) return;
    int lane = threadIdx.x & 31;
    const uint32_t* giH = &g_giH[(size_t)v * 192];
    const uint32_t* ghH = &g_ghH[(size_t)v * 192];
    float h[4];
    {
        uint2 uir = *(const uint2*)&giH[lane * 2];
        uint2 uiz = *(const uint2*)&giH[64 + lane * 2];
        uint2 uin = *(const uint2*)&giH[128 + lane * 2];
        uint2 uhr = *(const uint2*)&ghH[lane * 2];
        uint2 uhz = *(const uint2*)&ghH[64 + lane * 2];
        uint2 uhn = *(const uint2*)&ghH[128 + lane * 2];
        float4 xv = *(const float4*)&x[(size_t)v * D + (lane << 2)];
        #pragma unroll
        for (int hh = 0; hh < 2; hh++) {
            float2 ir = __half22float2(*(__half2*)((hh == 0) ? &uir.x : &uir.y));
            float2 iz = __half22float2(*(__half2*)((hh == 0) ? &uiz.x : &uiz.y));
            float2 in_ = __half22float2(*(__half2*)((hh == 0) ? &uin.x : &uin.y));
            float2 hr = __half22float2(*(__half2*)((hh == 0) ? &uhr.x : &uhr.y));
            float2 hz = __half22float2(*(__half2*)((hh == 0) ? &uhz.x : &uhz.y));
            float2 hn = __half22float2(*(__half2*)((hh == 0) ? &uhn.x : &uhn.y));
            #pragma unroll
            for (int q = 0; q < 2; q++) {
                int i = hh * 2 + q;
                float gir = (q == 0) ? ir.x : ir.y;
                float giz = (q == 0) ? iz.x : iz.y;
                float gin = (q == 0) ? in_.x : in_.y;
                float ghr = (q == 0) ? hr.x : hr.y;
                float ghz = (q == 0) ? hz.x : hz.y;
                float ghn = (q == 0) ? hn.x : hn.y;
                float r = 1.f / (1.f + expf(-(gir + ghr)));
                float z = 1.f / (1.f + expf(-(giz + ghz)));
                float n = tanhf(gin + r * ghn);
                h[i] = fmaxf((1.f - z) * n + z * (&xv.x)[i], 0.f);
            }
        }
    }
    float s = h[0] + h[1] + h[2] + h[3];
    #pragma unroll
    for (int m = 16; m; m >>= 1) s += __shfl_xor_sync(0xffffffffu, s, m);
    float mu = s * (1.f / 128.f), q = 0.f;
    #pragma unroll
    for (int i = 0; i < 4; i++) { float d0 = h[i] - mu; q = fmaf(d0, d0, q); }
    #pragma unroll
    for (int m = 16; m; m >>= 1) q += __shfl_xor_sync(0xffffffffu, q, m);
    float rstd = rsqrtf(q * (1.f / 128.f) + EPS);
    float4 gv = *(const float4*)&lng[lane << 2];
    float4 b2 = *(const float4*)&lnb[lane << 2];
    float o[4];
    o[0] = (h[0]-mu)*rstd*gv.x + b2.x;
    o[1] = (h[1]-mu)*rstd*gv.y + b2.y;
    o[2] = (h[2]-mu)*rstd*gv.z + b2.z;
    o[3] = (h[3]-mu)*rstd*gv.w + b2.w;
    float4 kv = *(const float4*)&g_kf[(size_t)v * D + (lane << 2)];
    int mb = v >> 6;
    int r = v & 63;
    int mt = r >> 4, rb = (r >> 3) & 1, lh = r & 7;
    #pragma unroll
    for (int pp = 0; pp < 2; pp++) {
        int kp = lane * 2 + pp;
        int ll = kp & 3;
        int ri = (((kp >> 2) & 1) << 1) | rb;
        int ks = (kp >> 3) & 1;
        int c  = kp >> 4;
        int idx = mt * 256 + ks * 128 + ((lh << 2) | ll) * 4 + ri;
        size_t base = ((size_t)(mb * 8 + c)) << 11;
        Acat[base + idx] = pack_hi16(o[2 * pp], o[2 * pp + 1]);
        base = ((size_t)(mb * 8 + 4 + c)) << 11;
        Acat[base + idx] = pack_hi16((&kv.x)[2 * pp], (&kv.x)[2 * pp + 1]);
    }
}

// ---------------- host ----------------
extern "C" void kernel_launch(void* const* d_in, const int* in_sizes, int n_in,
                              void* d_out, int out_size) {
    const float* node   = (const float*)d_in[0];
    const int*   src    = (const int*)  d_in[1];
    const int*   dst    = (const int*)  d_in[2];
    const float* W_edge = (const float*)d_in[3];
    const float* b_edge = (const float*)d_in[4];
    const float* W_pn   = (const float*)d_in[5];
    const float* b_pn   = (const float*)d_in[6];
    const float* W_ih   = (const float*)d_in[7];
    const float* b_ih   = (const float*)d_in[8];
    const float* W_hh   = (const float*)d_in[9];
    const float* b_hh   = (const float*)d_in[10];
    const float* ln_g   = (const float*)d_in[11];
    const float* ln_b   = (const float*)d_in[12];
    const float* Wk1    = (const float*)d_in[13];
    const float* bk1    = (const float*)d_in[14];
    const float* lnk1_g = (const float*)d_in[15];
    const float* lnk1_b = (const float*)d_in[16];
    const float* Wk2    = (const float*)d_in[17];
    const float* bk2    = (const float*)d_in[18];
    const float* lnk2_g = (const float*)d_in[19];
    const float* lnk2_b = (const float*)d_in[20];
    const float* Wc     = (const float*)d_in[21];
    const float* bc     = (const float*)d_in[22];
    const float* lnc_g  = (const float*)d_in[23];
    const float* lnc_b  = (const float*)d_in[24];
    int V = in_sizes[0] / D;
    int E = in_sizes[1];
    float* out = (float*)d_out;

    float *p_asum, *p_ctx, *p_kf, *p_bk1p, *p_k1g, *p_k1b;
    uint32_t *p_hvH, *p_giH, *p_ghH;
    uint32_t *p_WpnS, *p_WihS, *p_WhhS, *p_WcS, *p_Wk2S, *p_Wk1S;
    uint32_t *p_An, *p_Ac, *p_Aq;
    cudaGetSymbolAddress((void**)&p_asum, g_asum);
    cudaGetSymbolAddress((void**)&p_hvH,  g_hvH);
    cudaGetSymbolAddress((void**)&p_ctx,  g_ctx);
    cudaGetSymbolAddress((void**)&p_kf,   g_kf);
    cudaGetSymbolAddress((void**)&p_giH,  g_giH);
    cudaGetSymbolAddress((void**)&p_ghH,  g_ghH);
    cudaGetSymbolAddress((void**)&p_WpnS, g_WpnS);
    cudaGetSymbolAddress((void**)&p_WihS, g_WihS);
    cudaGetSymbolAddress((void**)&p_WhhS, g_WhhS);
    cudaGetSymbolAddress((void**)&p_WcS,  g_WcS);
    cudaGetSymbolAddress((void**)&p_Wk2S, g_Wk2S);
    cudaGetSymbolAddress((void**)&p_Wk1S, g_Wk1S);
    cudaGetSymbolAddress((void**)&p_bk1p, g_bk1p);
    cudaGetSymbolAddress((void**)&p_k1g,  g_k1g);
    cudaGetSymbolAddress((void**)&p_k1b,  g_k1b);
    cudaGetSymbolAddress((void**)&p_An,   g_Anode);
    cudaGetSymbolAddress((void**)&p_Ac,   g_Actx);
    cudaGetSymbolAddress((void**)&p_Aq,   g_Acat);

    static bool attr_set = false;
    if (!attr_set) {
        cudaFuncSetAttribute(kron_mma, cudaFuncAttributeMaxDynamicSharedMemorySize, 52000);
        attr_set = true;
    }

    int NBv = (V + 63) / 64;
    int n4c = V * 32;
    int n4s = V / 4;
    int nz  = (2 * n4c + n4s + 255) / 256;
    int ned = (V + 7) / 8;

    // FUSED prologue: zeros + weight packs + pack_act(node) + edgedot
    int g0 = nz + 421 + NBv + ned;
    prologue_kernel<<<g0, 256>>>(node, W_edge, W_pn, W_ih, W_hh, Wc, Wk2, Wk1,
                                 bk1, lnk1_g, lnk1_b,
                                 p_WpnS, p_WihS, p_WhhS, p_WcS, p_Wk2S, p_Wk1S,
                                 (float4*)p_ctx, (float4*)p_kf, (float4*)p_asum,
                                 p_An, V, n4c, n4s, nz, NBv, ned);

    logits_kernel<<<(E + 255) / 256, 256>>>(src, dst, b_edge, E);

    // FUSED: hv (mode 1) + npj (mode 2)
    mma_gemm<<<dim3(NBv, 2), 256>>>(p_An, p_WpnS, 4, 128, 1,
                                    b_pn, p_k1g, p_k1b, (float*)p_hvH, V,
                                    p_An, p_Wk1S, p_bk1p, nullptr, 2, 1);

    // kron GEMM + LN + relu + scatter to kf
    kron_mma<<<(E + 127) / 128, 256, 51200>>>(src, dst, p_Wk2S,
                                              bk2, lnk2_g, lnk2_b, E);
    // context scatter
    context_kernel<<<(E + 7) / 8, 256>>>(src, dst, E);
    // pack relu(ctx)
    pack_act<<<NBv, 256>>>(p_ctx, 128, 1, p_Ac, V, 0, 4);

    // FUSED: gi + gh
    mma_gemm<<<dim3(NBv, 6), 256>>>(p_Ac, p_WihS, 4, 384, 1,
                                    b_ih, nullptr, nullptr, (float*)p_giH, V,
                                    p_An, p_WhhS, b_hh, (float*)p_ghH, 1, 3);

    // gates -> Acat
    gates_kernel<<<(V + 7) / 8, 256>>>(node, ln_g, ln_b, p_Aq, V);

    // out = relu(LN(cat @ Wc + bc)) — mode 3
    mma_gemm<<<dim3(NBv, 1), 256>>>(p_Aq, p_WcS, 8, 128, 3,
                                    bc, lnc_g, lnc_b, out, V,
                                    nullptr, nullptr, nullptr, nullptr, 0, 999);
}